// round 4
// baseline (speedup 1.0000x reference)
#include <cuda_runtime.h>
#include <math.h>
#include <mma.h>

using namespace nvcuda;

#define Nn 50000
#define Ee 400000
#define Hh 128
#define Gg 512
#define COUT 10

static constexpr float EPSBN = 1e-5f;
static constexpr float BNB   = 1e-4f;

// ---------------- scratch (static device allocations) ----------------
__device__ float g_h[Nn*Hh];
__device__ float g_t[Nn*Hh];
__device__ float g_s[Nn*Hh];
__device__ float g_stats[512];
__device__ float g_mean[256];
__device__ float g_rstd[256];
__device__ float g_disU[Nn];
__device__ float g_dis0[Nn];
__device__ float g_dis1[Nn];
__device__ float g_epro[Nn*4];
__device__ float g_t2[Nn*2];
__device__ float g_natt[Nn*2];
__device__ float g_eatt[Ee*2];
__device__ int   g_gstart[Gg+1];
__device__ float g_cat[Gg*256];
__device__ float g_hd[Gg*128];
__device__ float g_logits[Gg*COUT];
// CSR by destination
__device__ int g_cnt[Nn];
__device__ int g_incl[Nn];
__device__ int g_bsum[64];
__device__ int g_rowptr[Nn+1];
__device__ int g_cursor[Nn];
__device__ int g_eid[Ee];

// ---------------- small utility kernels ----------------
__global__ void fill3_f32(float* a, float* b, float* c, float v, int n) {
    int i = blockIdx.x*blockDim.x + threadIdx.x;
    if (i < n) { a[i] = v; b[i] = v; c[i] = v; }
}

__global__ void count_deg(const int* __restrict__ src, float* deg, int E) {
    int i = blockIdx.x*blockDim.x + threadIdx.x;
    if (i < E) atomicAdd(&deg[src[i]], 1.0f);
}

__global__ void rsqrt_inplace(float* p, int n) {
    int i = blockIdx.x*blockDim.x + threadIdx.x;
    if (i < n) p[i] = rsqrtf(p[i]);
}

__global__ void gstart_kernel(const int* __restrict__ batch, int* gstart, int n, int G) {
    int i = blockIdx.x*blockDim.x + threadIdx.x;
    if (i >= n) return;
    int b  = batch[i];
    int pb = (i == 0) ? -1 : batch[i-1];
    for (int g = pb+1; g <= b; g++) gstart[g] = i;
    if (i == n-1) {
        for (int g = b+1; g <= G; g++) gstart[g] = n;
    }
}

// ---------------- CSR build (sort edges by dst) ----------------
__global__ void hist_dst(const int* __restrict__ dst, int* cnt, int E) {
    int e = blockIdx.x*blockDim.x + threadIdx.x;
    if (e < E) atomicAdd(&cnt[dst[e]], 1);
}

__global__ void scan_block(const int* __restrict__ cnt, int* incl, int* bsum, int n) {
    __shared__ int sm[1024];
    int i = blockIdx.x*1024 + threadIdx.x;
    sm[threadIdx.x] = (i < n) ? cnt[i] : 0;
    __syncthreads();
    for (int off = 1; off < 1024; off <<= 1) {
        int t = (threadIdx.x >= off) ? sm[threadIdx.x - off] : 0;
        __syncthreads();
        sm[threadIdx.x] += t;
        __syncthreads();
    }
    if (i < n) incl[i] = sm[threadIdx.x];
    if (threadIdx.x == 1023) bsum[blockIdx.x] = sm[1023];
}

__global__ void scan_tops(int* bsum, int nb) {
    if (threadIdx.x == 0 && blockIdx.x == 0) {
        int s = 0;
        for (int i = 0; i < nb; i++) { s += bsum[i]; bsum[i] = s; }
    }
}

__global__ void make_rowptr(const int* __restrict__ cnt, const int* __restrict__ incl,
                            const int* __restrict__ bsum,
                            int* rowptr, int* cursor, int n, int E) {
    int i = blockIdx.x*blockDim.x + threadIdx.x;
    if (i < n) {
        int b = i >> 10;
        int ex = incl[i] - cnt[i] + ((b > 0) ? bsum[b-1] : 0);
        rowptr[i] = ex;
        cursor[i] = ex;
    }
    if (i == 0) rowptr[n] = E;
}

__global__ void fill_csr(const int* __restrict__ dst, int* cursor, int* eid, int E) {
    int e = blockIdx.x*blockDim.x + threadIdx.x;
    if (e < E) {
        int p = atomicAdd(&cursor[dst[e]], 1);
        eid[p] = e;
    }
}

// ---------------- BatchNorm stats ----------------
template<int C>
__global__ void colstats(const float* __restrict__ A, int lda, int aoff,
                         int n, float* sums) {
    long total  = (long)n * C;
    long stride = (long)gridDim.x * blockDim.x;
    long i0     = (long)blockIdx.x*blockDim.x + threadIdx.x;
    if (i0 >= total) return;
    int c = (int)(i0 % C);
    float s0 = 0.f, s1 = 0.f;
    for (long i = i0; i < total; i += stride) {
        int r = (int)(i / C);
        float v = A[(long)r*lda + aoff + c];
        s0 += v; s1 += v*v;
    }
    atomicAdd(&sums[c], s0);
    atomicAdd(&sums[C+c], s1);
}

// both natt-scaled channels in one pass
__global__ void colstats2(const float* __restrict__ A, const float* __restrict__ natt,
                          int n, float* sums) {
    long total  = (long)n * 128;
    long stride = (long)gridDim.x * blockDim.x;
    long i0     = (long)blockIdx.x*blockDim.x + threadIdx.x;
    if (i0 >= total) return;
    int c = (int)(i0 % 128);
    float s00=0.f, s01=0.f, s10=0.f, s11=0.f;
    for (long i = i0; i < total; i += stride) {
        int r = (int)(i / 128);
        float v = A[(long)r*128 + c];
        float v0 = v * natt[r*2+0];
        float v1 = v * natt[r*2+1];
        s00 += v0; s01 += v0*v0;
        s10 += v1; s11 += v1*v1;
    }
    atomicAdd(&sums[c], s00);
    atomicAdd(&sums[128+c], s01);
    atomicAdd(&sums[256+c], s10);
    atomicAdd(&sums[384+c], s11);
}

__global__ void finalize_stats(const float* __restrict__ sums, int C, float inv_n,
                               float* mean, float* rstd) {
    int c = threadIdx.x + blockIdx.x*blockDim.x;
    if (c < C) {
        float m = sums[c]*inv_n;
        float var = sums[C+c]*inv_n - m*m;
        mean[c] = m;
        rstd[c] = rsqrtf(var + EPSBN);
    }
}

// ---------------- big GEMM on tensor cores (TF32 hi/lo split) ----------------
// out[n,128] = act( BN(rs*A)[n,128] @ W[128,128] )
// 128x128 tile per CTA, K chunked by 32. 8 warps, each warp owns 16 rows.
static constexpr int LDA_S = 36;   // Ah/Al smem leading dim
static constexpr int LDW_S = 132;  // Wh/Wl smem leading dim
static constexpr int GEMM_SMEM = (2*128*LDA_S + 2*32*LDW_S) * 4;  // 70656 B

__global__ __launch_bounds__(256) void gemm128_tc(
    const float* __restrict__ A,
    const float* __restrict__ rs, int rss, int rso,
    const float* __restrict__ mean, const float* __restrict__ rstd,
    const float* __restrict__ W,
    float* __restrict__ out,
    int n, int act)
{
    extern __shared__ float sm[];
    float* Ah = sm;                    // 128 x 36
    float* Al = Ah + 128*LDA_S;
    float* Wh = Al + 128*LDA_S;        // 32 x 132
    float* Wl = Wh + 32*LDW_S;
    float* stage = sm;                 // reused after mainloop (128x128)

    int tid  = threadIdx.x;
    int warp = tid >> 5;
    int row0 = blockIdx.x * 128;

    wmma::fragment<wmma::accumulator, 16, 16, 8, float> acc[8];
    #pragma unroll
    for (int nt = 0; nt < 8; nt++) wmma::fill_fragment(acc[nt], 0.f);

    for (int k0 = 0; k0 < 128; k0 += 32) {
        __syncthreads();
        // A chunk: 128 rows x 32 cols (BN + row-scale fused), hi/lo split
        #pragma unroll
        for (int ii = 0; ii < 4; ii++) {
            int i = tid + ii*256;           // 0..1023
            int r = i >> 3, q = i & 7;
            int gr = row0 + r;
            float4 v = make_float4(0.f,0.f,0.f,0.f);
            if (gr < n) {
                v = ((const float4*)A)[gr*32 + (k0>>2) + q];
                float sc = rs ? rs[gr*rss + rso] : 1.f;
                int c = k0 + q*4;
                v.x = (v.x*sc - mean[c+0])*rstd[c+0] + BNB;
                v.y = (v.y*sc - mean[c+1])*rstd[c+1] + BNB;
                v.z = (v.z*sc - mean[c+2])*rstd[c+2] + BNB;
                v.w = (v.w*sc - mean[c+3])*rstd[c+3] + BNB;
            }
            float4 h, l;
            h.x = wmma::__float_to_tf32(v.x); l.x = wmma::__float_to_tf32(v.x - h.x);
            h.y = wmma::__float_to_tf32(v.y); l.y = wmma::__float_to_tf32(v.y - h.y);
            h.z = wmma::__float_to_tf32(v.z); l.z = wmma::__float_to_tf32(v.z - h.z);
            h.w = wmma::__float_to_tf32(v.w); l.w = wmma::__float_to_tf32(v.w - h.w);
            int base = r*LDA_S + q*4;
            *(float4*)&Ah[base] = h;
            *(float4*)&Al[base] = l;
        }
        // W chunk: 32 rows x 128 cols, hi/lo split
        #pragma unroll
        for (int ii = 0; ii < 4; ii++) {
            int i = tid + ii*256;
            int r = i >> 5, q = i & 31;
            float4 v = ((const float4*)W)[(k0 + r)*32 + q];
            float4 h, l;
            h.x = wmma::__float_to_tf32(v.x); l.x = wmma::__float_to_tf32(v.x - h.x);
            h.y = wmma::__float_to_tf32(v.y); l.y = wmma::__float_to_tf32(v.y - h.y);
            h.z = wmma::__float_to_tf32(v.z); l.z = wmma::__float_to_tf32(v.z - h.z);
            h.w = wmma::__float_to_tf32(v.w); l.w = wmma::__float_to_tf32(v.w - h.w);
            int base = r*LDW_S + q*4;
            *(float4*)&Wh[base] = h;
            *(float4*)&Wl[base] = l;
        }
        __syncthreads();

        #pragma unroll
        for (int k8 = 0; k8 < 4; k8++) {
            wmma::fragment<wmma::matrix_a, 16, 16, 8, wmma::precision::tf32, wmma::row_major> ah, al;
            wmma::load_matrix_sync(ah, &Ah[(warp*16)*LDA_S + k8*8], LDA_S);
            wmma::load_matrix_sync(al, &Al[(warp*16)*LDA_S + k8*8], LDA_S);
            #pragma unroll
            for (int nt = 0; nt < 8; nt++) {
                wmma::fragment<wmma::matrix_b, 16, 16, 8, wmma::precision::tf32, wmma::row_major> bh, bl;
                wmma::load_matrix_sync(bh, &Wh[(k8*8)*LDW_S + nt*16], LDW_S);
                wmma::load_matrix_sync(bl, &Wl[(k8*8)*LDW_S + nt*16], LDW_S);
                wmma::mma_sync(acc[nt], ah, bh, acc[nt]);
                wmma::mma_sync(acc[nt], ah, bl, acc[nt]);
                wmma::mma_sync(acc[nt], al, bh, acc[nt]);
            }
        }
    }

    __syncthreads();
    #pragma unroll
    for (int nt = 0; nt < 8; nt++)
        wmma::store_matrix_sync(&stage[(warp*16)*128 + nt*16], acc[nt], 128, wmma::mem_row_major);
    __syncthreads();

    #pragma unroll
    for (int ii = 0; ii < 16; ii++) {
        int i = tid + ii*256;          // 0..4095 : 128 rows x 32 float4
        int r = i >> 5, q = i & 31;
        int gr = row0 + r;
        if (gr < n) {
            float4 o = ((float4*)stage)[i];
            if (act == 1) {
                o.x = fmaxf(o.x, 0.f); o.y = fmaxf(o.y, 0.f);
                o.z = fmaxf(o.z, 0.f); o.w = fmaxf(o.w, 0.f);
            }
            ((float4*)out)[gr*32 + q] = o;
        }
    }
}

// ---------------- CSR gather conv: one warp per dst node ----------------
__global__ __launch_bounds__(256) void gather128(
    const float* __restrict__ t,
    const int* __restrict__ rowptr, const int* __restrict__ eid,
    const int* __restrict__ esrc, const float* __restrict__ dis,
    const float* __restrict__ eatt, int ewo,
    const float* __restrict__ bias,
    float* __restrict__ out, int n, int act)
{
    int gt = blockIdx.x*blockDim.x + threadIdx.x;
    int v = gt >> 5, lane = gt & 31;
    if (v >= n) return;
    float dv = dis[v];
    float4 acc = ((const float4*)t)[v*32 + lane];
    float d2 = dv*dv;
    acc.x *= d2; acc.y *= d2; acc.z *= d2; acc.w *= d2;
    int st = rowptr[v], en = rowptr[v+1];
    for (int p = st; p < en; p++) {
        int e = __ldg(&eid[p]);
        int s = __ldg(&esrc[e]);
        float w = __ldg(&dis[s]) * dv;
        if (eatt) w *= __ldg(&eatt[e*2 + ewo]);
        float4 x = ((const float4*)t)[s*32 + lane];
        acc.x += w*x.x; acc.y += w*x.y; acc.z += w*x.z; acc.w += w*x.w;
    }
    if (bias) {
        float4 b = ((const float4*)bias)[lane];
        acc.x += b.x; acc.y += b.y; acc.z += b.z; acc.w += b.w;
    }
    if (act == 1) {
        acc.x = fmaxf(acc.x, 0.f); acc.y = fmaxf(acc.y, 0.f);
        acc.z = fmaxf(acc.z, 0.f); acc.w = fmaxf(acc.w, 0.f);
    }
    ((float4*)out)[v*32 + lane] = acc;
}

// ---------------- attention ----------------
__global__ void proj_kernel(const float* __restrict__ h, const float* __restrict__ eW,
                            const float* __restrict__ naW, float* __restrict__ epro,
                            float* __restrict__ t2, int n) {
    __shared__ float sEW[512];
    __shared__ float sNA[256];
    int tid = threadIdx.x;
    for (int i = tid; i < 512; i += blockDim.x) sEW[i] = eW[i];
    for (int i = tid; i < 256; i += blockDim.x) sNA[i] = naW[i];
    __syncthreads();
    int lane = tid & 31;
    int w0 = (blockIdx.x*blockDim.x + tid) >> 5;
    int nw = (gridDim.x*blockDim.x) >> 5;
    for (int v = w0; v < n; v += nw) {
        float4 hv = ((const float4*)h)[v*32 + lane];
        float hx[4] = {hv.x, hv.y, hv.z, hv.w};
        float p0=0,p1=0,q0=0,q1=0,u0=0,u1=0;
        #pragma unroll
        for (int i = 0; i < 4; i++) {
            int k = lane*4 + i; float x = hx[i];
            p0 += x*sEW[k*2+0];        p1 += x*sEW[k*2+1];
            q0 += x*sEW[(128+k)*2+0];  q1 += x*sEW[(128+k)*2+1];
            u0 += x*sNA[k*2+0];        u1 += x*sNA[k*2+1];
        }
        #pragma unroll
        for (int o = 16; o; o >>= 1) {
            p0 += __shfl_xor_sync(0xffffffffu, p0, o);
            p1 += __shfl_xor_sync(0xffffffffu, p1, o);
            q0 += __shfl_xor_sync(0xffffffffu, q0, o);
            q1 += __shfl_xor_sync(0xffffffffu, q1, o);
            u0 += __shfl_xor_sync(0xffffffffu, u0, o);
            u1 += __shfl_xor_sync(0xffffffffu, u1, o);
        }
        if (lane == 0) {
            epro[v*4+0]=p0; epro[v*4+1]=p1; epro[v*4+2]=q0; epro[v*4+3]=q1;
            t2[v*2+0]=u0; t2[v*2+1]=u1;
        }
    }
}

__global__ void edge_att_kernel(const int* __restrict__ src, const int* __restrict__ dst,
                                const float* __restrict__ epro, const float* __restrict__ eb,
                                float* __restrict__ eatt, float* deg0, float* deg1, int E) {
    int e = blockIdx.x*blockDim.x + threadIdx.x;
    if (e >= E) return;
    int s = src[e], d = dst[e];
    float l0 = epro[s*4+0] + epro[d*4+2] + eb[0];
    float l1 = epro[s*4+1] + epro[d*4+3] + eb[1];
    float m = fmaxf(l0, l1);
    float e0 = expf(l0 - m), e1 = expf(l1 - m);
    float inv = 1.f/(e0+e1);
    float a0 = e0*inv, a1 = e1*inv;
    eatt[e*2+0] = a0; eatt[e*2+1] = a1;
    atomicAdd(&deg0[s], a0);
    atomicAdd(&deg1[s], a1);
}

// fused node-attention gather + softmax (CSR)
__global__ void natt_gather(const float* __restrict__ t2,
                            const int* __restrict__ rowptr, const int* __restrict__ eid,
                            const int* __restrict__ esrc, const float* __restrict__ disU,
                            const float* __restrict__ nab,
                            float* __restrict__ natt, int n) {
    int v = blockIdx.x*blockDim.x + threadIdx.x;
    if (v >= n) return;
    float dv = disU[v];
    float d2 = dv*dv;
    float a0 = t2[v*2+0]*d2, a1 = t2[v*2+1]*d2;
    int st = rowptr[v], en = rowptr[v+1];
    for (int p = st; p < en; p++) {
        int e = eid[p];
        int s = esrc[e];
        float w = disU[s]*dv;
        a0 += w*t2[s*2+0];
        a1 += w*t2[s*2+1];
    }
    a0 += nab[0]; a1 += nab[1];
    float m = fmaxf(a0, a1);
    float e0 = expf(a0 - m), e1 = expf(a1 - m);
    float inv = 1.f/(e0+e1);
    natt[v*2+0] = e0*inv; natt[v*2+1] = e1*inv;
}

// pool with fused bias + elu
__global__ void pool_elu(const float* __restrict__ s, const float* __restrict__ b,
                         const int* __restrict__ gstart, float* __restrict__ cat, int off) {
    int g = blockIdx.x, c = threadIdx.x;
    int st = gstart[g], en = gstart[g+1];
    float bc = b[c], acc = 0.f;
    for (int v = st; v < en; v++) {
        float z = s[v*128 + c] + bc;
        acc += (z > 0.f) ? z : expm1f(z);
    }
    cat[g*256 + off + c] = acc;
}

// ---------------- head GEMM: one block per row ----------------
__global__ void head_gemm(const float* __restrict__ A, int lda, int aoff,
                          const float* __restrict__ mean, const float* __restrict__ rstd,
                          const float* __restrict__ W, const float* __restrict__ b,
                          float* __restrict__ out, int K, int cols, int act) {
    __shared__ float a[256];
    int r = blockIdx.x;
    for (int k = threadIdx.x; k < K; k += blockDim.x)
        a[k] = (A[r*lda + aoff + k] - mean[k]) * rstd[k] + BNB;
    __syncthreads();
    for (int c = threadIdx.x; c < cols; c += blockDim.x) {
        float acc = b[c];
        for (int k = 0; k < K; k++) acc += a[k] * W[k*cols + c];
        if (act == 1) acc = fmaxf(acc, 0.f);
        else if (act == 2) {
            acc = (acc > 0.f) ? acc : expm1f(acc);
            acc = (acc > 0.f) ? acc : expm1f(acc);
        }
        out[r*cols + c] = acc;
    }
}

__global__ void log_softmax10(const float* __restrict__ in, float* __restrict__ out, int G) {
    int r = blockIdx.x*blockDim.x + threadIdx.x;
    if (r >= G) return;
    float v[COUT]; float m = -1e30f;
    #pragma unroll
    for (int i = 0; i < COUT; i++) { v[i] = in[r*COUT + i]; m = fmaxf(m, v[i]); }
    float s = 0.f;
    #pragma unroll
    for (int i = 0; i < COUT; i++) s += expf(v[i] - m);
    float lse = m + logf(s);
    #pragma unroll
    for (int i = 0; i < COUT; i++) out[r*COUT + i] = v[i] - lse;
}

// ---------------- host orchestration ----------------
extern "C" void kernel_launch(void* const* d_in, const int* in_sizes, int n_in,
                              void* d_out, int out_size) {
    const float* x      = (const float*)d_in[0];
    const float* W_feat = (const float*)d_in[1];
    const float* conv_Ws= (const float*)d_in[2];
    const float* conv_bs= (const float*)d_in[3];
    const float* eW     = (const float*)d_in[4];
    const float* eb     = (const float*)d_in[5];
    const float* naW    = (const float*)d_in[6];
    const float* nab    = (const float*)d_in[7];
    const float* xcW    = (const float*)d_in[8];
    const float* xcb    = (const float*)d_in[9];
    const float* xoW    = (const float*)d_in[10];
    const float* xob    = (const float*)d_in[11];
    const float* cW1    = (const float*)d_in[12];
    const float* cb1    = (const float*)d_in[13];
    const float* cW2    = (const float*)d_in[14];
    const float* cb2    = (const float*)d_in[15];
    const float* oW1    = (const float*)d_in[16];
    const float* ob1    = (const float*)d_in[17];
    const float* oW2    = (const float*)d_in[18];
    const float* ob2    = (const float*)d_in[19];
    const float* coW1   = (const float*)d_in[20];
    const float* cob1   = (const float*)d_in[21];
    const float* coW2   = (const float*)d_in[22];
    const float* cob2   = (const float*)d_in[23];
    const int* esrc     = (const int*)d_in[24];
    const int* edst     = (const int*)d_in[25];
    const int* batch    = (const int*)d_in[26];
    float* out = (float*)d_out;

    float *p_h,*p_t,*p_s,*p_stats,*p_mean,*p_rstd,*p_disU,*p_dis0,*p_dis1;
    float *p_epro,*p_t2,*p_natt,*p_eatt,*p_cat,*p_hd,*p_logits;
    int *p_gstart,*p_cnt,*p_incl,*p_bsum,*p_rowptr,*p_cursor,*p_eid;
    cudaGetSymbolAddress((void**)&p_h, g_h);
    cudaGetSymbolAddress((void**)&p_t, g_t);
    cudaGetSymbolAddress((void**)&p_s, g_s);
    cudaGetSymbolAddress((void**)&p_stats, g_stats);
    cudaGetSymbolAddress((void**)&p_mean, g_mean);
    cudaGetSymbolAddress((void**)&p_rstd, g_rstd);
    cudaGetSymbolAddress((void**)&p_disU, g_disU);
    cudaGetSymbolAddress((void**)&p_dis0, g_dis0);
    cudaGetSymbolAddress((void**)&p_dis1, g_dis1);
    cudaGetSymbolAddress((void**)&p_epro, g_epro);
    cudaGetSymbolAddress((void**)&p_t2, g_t2);
    cudaGetSymbolAddress((void**)&p_natt, g_natt);
    cudaGetSymbolAddress((void**)&p_eatt, g_eatt);
    cudaGetSymbolAddress((void**)&p_cat, g_cat);
    cudaGetSymbolAddress((void**)&p_hd, g_hd);
    cudaGetSymbolAddress((void**)&p_logits, g_logits);
    cudaGetSymbolAddress((void**)&p_gstart, g_gstart);
    cudaGetSymbolAddress((void**)&p_cnt, g_cnt);
    cudaGetSymbolAddress((void**)&p_incl, g_incl);
    cudaGetSymbolAddress((void**)&p_bsum, g_bsum);
    cudaGetSymbolAddress((void**)&p_rowptr, g_rowptr);
    cudaGetSymbolAddress((void**)&p_cursor, g_cursor);
    cudaGetSymbolAddress((void**)&p_eid, g_eid);

    cudaFuncSetAttribute(gemm128_tc, cudaFuncAttributeMaxDynamicSharedMemorySize, GEMM_SMEM);

    const int N = Nn, E = Ee, G = Gg;
    const int NB = (N + 127) / 128;
    const int NT = (N + 255) / 256;
    const int ET = (E + 255) / 256;
    const int GW = (N*32 + 255) / 256;
    const int NSCAN = (N + 1023) / 1024;

    // ---- CSR build + degrees + group starts ----
    cudaMemsetAsync(p_cnt, 0, Nn*sizeof(int));
    hist_dst<<<ET,256>>>(edst, p_cnt, E);
    scan_block<<<NSCAN,1024>>>(p_cnt, p_incl, p_bsum, N);
    scan_tops<<<1,32>>>(p_bsum, NSCAN);
    make_rowptr<<<NT,256>>>(p_cnt, p_incl, p_bsum, p_rowptr, p_cursor, N, E);
    fill_csr<<<ET,256>>>(edst, p_cursor, p_eid, E);

    fill3_f32<<<NT,256>>>(p_disU, p_dis0, p_dis1, 1.f, N);
    count_deg<<<ET,256>>>(esrc, p_disU, E);
    rsqrt_inplace<<<NT,256>>>(p_disU, N);
    gstart_kernel<<<NT,256>>>(batch, p_gstart, N, G);

    // ---- h = relu(BN(x) @ W_feat) ----
    cudaMemsetAsync(p_stats, 0, 2048);
    colstats<128><<<512,256>>>(x, 128, 0, N, p_stats);
    finalize_stats<<<1,256>>>(p_stats, 128, 1.f/N, p_mean, p_rstd);
    gemm128_tc<<<NB,256,GEMM_SMEM>>>(x, nullptr,0,0, p_mean, p_rstd, W_feat, p_h, N, 1);

    // ---- 3 GCN layers ----
    for (int l = 0; l < 3; l++) {
        cudaMemsetAsync(p_stats, 0, 2048);
        colstats<128><<<512,256>>>(p_h, 128, 0, N, p_stats);
        finalize_stats<<<1,256>>>(p_stats, 128, 1.f/N, p_mean, p_rstd);
        gemm128_tc<<<NB,256,GEMM_SMEM>>>(p_h, nullptr,0,0, p_mean, p_rstd,
                                         conv_Ws + l*128*128, p_t, N, 0);
        gather128<<<GW,256>>>(p_t, p_rowptr, p_eid, esrc, p_disU, nullptr, 0,
                              conv_bs + l*128, p_h, N, 1);
    }

    // ---- attention ----
    proj_kernel<<<512,256>>>(p_h, eW, naW, p_epro, p_t2, N);
    edge_att_kernel<<<ET,256>>>(esrc, edst, p_epro, eb, p_eatt, p_dis0, p_dis1, E);
    rsqrt_inplace<<<NT,256>>>(p_dis0, N);
    rsqrt_inplace<<<NT,256>>>(p_dis1, N);
    natt_gather<<<NT,256>>>(p_t2, p_rowptr, p_eid, esrc, p_disU, nab, p_natt, N);

    // ---- XC / XO stats (one fused pass) ----
    cudaMemsetAsync(p_stats, 0, 2048);
    colstats2<<<512,256>>>(p_h, p_natt, N, p_stats);
    finalize_stats<<<1,256>>>(p_stats,       128, 1.f/N, p_mean,       p_rstd);
    finalize_stats<<<1,256>>>(p_stats + 256, 128, 1.f/N, p_mean + 128, p_rstd + 128);

    // ---- XC branch ----
    gemm128_tc<<<NB,256,GEMM_SMEM>>>(p_h, p_natt, 2, 0, p_mean, p_rstd, xcW, p_t, N, 0);
    gather128<<<GW,256>>>(p_t, p_rowptr, p_eid, esrc, p_dis0, p_eatt, 0,
                          nullptr, p_s, N, 0);
    pool_elu<<<G,128>>>(p_s, xcb, p_gstart, p_cat, 0);

    // ---- XO branch ----
    gemm128_tc<<<NB,256,GEMM_SMEM>>>(p_h, p_natt, 2, 1, p_mean + 128, p_rstd + 128,
                                     xoW, p_t, N, 0);
    gather128<<<GW,256>>>(p_t, p_rowptr, p_eid, esrc, p_dis1, p_eatt, 1,
                          nullptr, p_s, N, 0);
    pool_elu<<<G,128>>>(p_s, xob, p_gstart, p_cat, 128);

    // ---- C head ----
    cudaMemsetAsync(p_stats, 0, 2048);
    colstats<128><<<64,256>>>(p_cat, 256, 0, G, p_stats);
    finalize_stats<<<1,256>>>(p_stats, 128, 1.f/G, p_mean, p_rstd);
    head_gemm<<<G,128>>>(p_cat, 256, 0, p_mean, p_rstd, cW1, cb1, p_hd, 128, 128, 1);
    cudaMemsetAsync(p_stats, 0, 2048);
    colstats<128><<<64,256>>>(p_hd, 128, 0, G, p_stats);
    finalize_stats<<<1,256>>>(p_stats, 128, 1.f/G, p_mean, p_rstd);
    head_gemm<<<G,128>>>(p_hd, 128, 0, p_mean, p_rstd, cW2, cb2, p_logits, 128, COUT, 0);
    log_softmax10<<<(G+127)/128,128>>>(p_logits, out, G);

    // ---- O head ----
    cudaMemsetAsync(p_stats, 0, 2048);
    colstats<128><<<64,256>>>(p_cat, 256, 128, G, p_stats);
    finalize_stats<<<1,256>>>(p_stats, 128, 1.f/G, p_mean, p_rstd);
    head_gemm<<<G,128>>>(p_cat, 256, 128, p_mean, p_rstd, oW1, ob1, p_hd, 128, 128, 1);
    cudaMemsetAsync(p_stats, 0, 2048);
    colstats<128><<<64,256>>>(p_hd, 128, 0, G, p_stats);
    finalize_stats<<<1,256>>>(p_stats, 128, 1.f/G, p_mean, p_rstd);
    head_gemm<<<G,128>>>(p_hd, 128, 0, p_mean, p_rstd, oW2, ob2, p_logits, 128, COUT, 0);
    log_softmax10<<<(G+127)/128,128>>>(p_logits, out + G*COUT, G);

    // ---- CO head ----
    cudaMemsetAsync(p_stats, 0, 2048);
    colstats<256><<<64,256>>>(p_cat, 256, 0, G, p_stats);
    finalize_stats<<<1,256>>>(p_stats, 256, 1.f/G, p_mean, p_rstd);
    head_gemm<<<G,128>>>(p_cat, 256, 0, p_mean, p_rstd, coW1, cob1, p_hd, 256, 128, 2);
    cudaMemsetAsync(p_stats, 0, 2048);
    colstats<128><<<64,256>>>(p_hd, 128, 0, G, p_stats);
    finalize_stats<<<1,256>>>(p_stats, 128, 1.f/G, p_mean, p_rstd);
    head_gemm<<<G,128>>>(p_hd, 128, 0, p_mean, p_rstd, coW2, cob2, p_logits, 128, COUT, 0);
    log_softmax10<<<(G+127)/128,128>>>(p_logits, out + 2*G*COUT, G);
}

// round 5
// speedup vs baseline: 1.2989x; 1.2989x over previous
#include <cuda_runtime.h>
#include <math.h>

#define Nn 50000
#define Ee 400000
#define Hh 128
#define Gg 512
#define COUT 10

typedef unsigned long long u64;

static constexpr float EPSBN = 1e-5f;
static constexpr float BNB   = 1e-4f;

// ---------------- scratch (static device allocations) ----------------
__device__ float g_h[Nn*Hh];
__device__ float g_t[Nn*Hh];
__device__ float g_s[Nn*Hh];
__device__ float g_stats[512];
__device__ float g_mean[256];
__device__ float g_rstd[256];
__device__ float g_disU[Nn];
__device__ float g_dis0[Nn];
__device__ float g_dis1[Nn];
__device__ float g_epro[Nn*4];
__device__ float g_t2[Nn*2];
__device__ float g_natt[Nn*2];
__device__ float g_eatt[Ee*2];
__device__ int   g_gstart[Gg+1];
__device__ float g_cat[Gg*256];
__device__ float g_hd[Gg*128];
__device__ float g_logits[Gg*COUT];
// CSR by destination
__device__ int g_cnt[Nn];
__device__ int g_incl[Nn];
__device__ int g_bsum[64];
__device__ int g_rowptr[Nn+1];
__device__ int g_cursor[Nn];
__device__ int g_eid[Ee];

// ---------------- small utility kernels ----------------
__global__ void fill3_f32(float* a, float* b, float* c, float v, int n) {
    int i = blockIdx.x*blockDim.x + threadIdx.x;
    if (i < n) { a[i] = v; b[i] = v; c[i] = v; }
}

// fused: unit out-degree (src) as float + dst histogram for CSR
__global__ void deg_hist(const int* __restrict__ src, const int* __restrict__ dst,
                         float* degU, int* cnt, int E) {
    int i = blockIdx.x*blockDim.x + threadIdx.x;
    if (i < E) {
        atomicAdd(&degU[src[i]], 1.0f);
        atomicAdd(&cnt[dst[i]], 1);
    }
}

__global__ void rsqrt_one(float* p, int n) {
    int i = blockIdx.x*blockDim.x + threadIdx.x;
    if (i < n) p[i] = rsqrtf(p[i]);
}

__global__ void rsqrt_two(float* p, float* q, int n) {
    int i = blockIdx.x*blockDim.x + threadIdx.x;
    if (i < n) { p[i] = rsqrtf(p[i]); q[i] = rsqrtf(q[i]); }
}

__global__ void gstart_kernel(const int* __restrict__ batch, int* gstart, int n, int G) {
    int i = blockIdx.x*blockDim.x + threadIdx.x;
    if (i >= n) return;
    int b  = batch[i];
    int pb = (i == 0) ? -1 : batch[i-1];
    for (int g = pb+1; g <= b; g++) gstart[g] = i;
    if (i == n-1) {
        for (int g = b+1; g <= G; g++) gstart[g] = n;
    }
}

// ---------------- CSR build (sort edges by dst) ----------------
__global__ void scan_block(const int* __restrict__ cnt, int* incl, int* bsum, int n) {
    __shared__ int sm[1024];
    int i = blockIdx.x*1024 + threadIdx.x;
    sm[threadIdx.x] = (i < n) ? cnt[i] : 0;
    __syncthreads();
    for (int off = 1; off < 1024; off <<= 1) {
        int t = (threadIdx.x >= off) ? sm[threadIdx.x - off] : 0;
        __syncthreads();
        sm[threadIdx.x] += t;
        __syncthreads();
    }
    if (i < n) incl[i] = sm[threadIdx.x];
    if (threadIdx.x == 1023) bsum[blockIdx.x] = sm[1023];
}

__global__ void scan_tops(int* bsum, int nb) {
    if (threadIdx.x == 0 && blockIdx.x == 0) {
        int s = 0;
        for (int i = 0; i < nb; i++) { s += bsum[i]; bsum[i] = s; }
    }
}

__global__ void make_rowptr(const int* __restrict__ cnt, const int* __restrict__ incl,
                            const int* __restrict__ bsum,
                            int* rowptr, int* cursor, int n, int E) {
    int i = blockIdx.x*blockDim.x + threadIdx.x;
    if (i < n) {
        int b = i >> 10;
        int ex = incl[i] - cnt[i] + ((b > 0) ? bsum[b-1] : 0);
        rowptr[i] = ex;
        cursor[i] = ex;
    }
    if (i == 0) rowptr[n] = E;
}

__global__ void fill_csr(const int* __restrict__ dst, int* cursor, int* eid, int E) {
    int e = blockIdx.x*blockDim.x + threadIdx.x;
    if (e < E) {
        int p = atomicAdd(&cursor[dst[e]], 1);
        eid[p] = e;
    }
}

// ---------------- BatchNorm stats (big N) ----------------
template<int C>
__global__ void colstats(const float* __restrict__ A, int lda, int aoff,
                         int n, float* sums) {
    long total  = (long)n * C;
    long stride = (long)gridDim.x * blockDim.x;
    long i0     = (long)blockIdx.x*blockDim.x + threadIdx.x;
    if (i0 >= total) return;
    int c = (int)(i0 % C);
    float s0 = 0.f, s1 = 0.f;
    for (long i = i0; i < total; i += stride) {
        int r = (int)(i / C);
        float v = A[(long)r*lda + aoff + c];
        s0 += v; s1 += v*v;
    }
    atomicAdd(&sums[c], s0);
    atomicAdd(&sums[C+c], s1);
}

// both natt-scaled channels in one pass
__global__ void colstats2(const float* __restrict__ A, const float* __restrict__ natt,
                          int n, float* sums) {
    long total  = (long)n * 128;
    long stride = (long)gridDim.x * blockDim.x;
    long i0     = (long)blockIdx.x*blockDim.x + threadIdx.x;
    if (i0 >= total) return;
    int c = (int)(i0 % 128);
    float s00=0.f, s01=0.f, s10=0.f, s11=0.f;
    for (long i = i0; i < total; i += stride) {
        int r = (int)(i / 128);
        float v = A[(long)r*128 + c];
        float v0 = v * natt[r*2+0];
        float v1 = v * natt[r*2+1];
        s00 += v0; s01 += v0*v0;
        s10 += v1; s11 += v1*v1;
    }
    atomicAdd(&sums[c], s00);
    atomicAdd(&sums[128+c], s01);
    atomicAdd(&sums[256+c], s10);
    atomicAdd(&sums[384+c], s11);
}

__global__ void finalize_stats(const float* __restrict__ sums, int C, float inv_n,
                               float* mean, float* rstd) {
    int c = threadIdx.x + blockIdx.x*blockDim.x;
    if (c < C) {
        float m = sums[c]*inv_n;
        float var = sums[C+c]*inv_n - m*m;
        mean[c] = m;
        rstd[c] = rsqrtf(var + EPSBN);
    }
}

// single-kernel BN stats for small n (heads): one block per column
__global__ void head_stats(const float* __restrict__ A, int lda, int aoff,
                           int n, float* mean, float* rstd) {
    __shared__ float s0s[4], s1s[4];
    int c = blockIdx.x;
    int lane = threadIdx.x & 31, warp = threadIdx.x >> 5;
    float s0 = 0.f, s1 = 0.f;
    for (int r = threadIdx.x; r < n; r += blockDim.x) {
        float v = A[r*lda + aoff + c];
        s0 += v; s1 += v*v;
    }
    #pragma unroll
    for (int o = 16; o; o >>= 1) {
        s0 += __shfl_xor_sync(0xffffffffu, s0, o);
        s1 += __shfl_xor_sync(0xffffffffu, s1, o);
    }
    if (lane == 0) { s0s[warp] = s0; s1s[warp] = s1; }
    __syncthreads();
    if (threadIdx.x == 0) {
        float t0 = 0.f, t1 = 0.f;
        for (int w = 0; w < 4; w++) { t0 += s0s[w]; t1 += s1s[w]; }
        float m = t0 / n;
        float var = t1 / n - m*m;
        mean[c] = m;
        rstd[c] = rsqrtf(var + EPSBN);
    }
}

// ---------------- big GEMM (packed f32x2 FMA) ----------------
// out[n,128] = act( BN(rs*A)[n,128] @ W[128,128] )
// 128 rows per block, whole K=128 resident, 256 threads, 8x8 per thread
// accumulated as 8x4 packed f32x2 pairs.
static constexpr int GEMM_SMEM = 2 * 128 * 128 * 4;

__global__ __launch_bounds__(256) void gemm128(
    const float* __restrict__ A,
    const float* __restrict__ rs, int rss, int rso,
    const float* __restrict__ mean, const float* __restrict__ rstd,
    const float* __restrict__ W,
    float* __restrict__ out,
    int n, int act)
{
    extern __shared__ float sm[];
    float* As = sm;               // [128][128]
    float* Ws = sm + 128*128;     // [128][128]
    int tid  = threadIdx.x;
    int row0 = blockIdx.x * 128;

    const float4* Wg = (const float4*)W;
    float4* Ws4 = (float4*)Ws;
    #pragma unroll 4
    for (int i = tid; i < 128*32; i += 256) Ws4[i] = Wg[i];

    for (int i = tid; i < 128*32; i += 256) {
        int r = i >> 5, cq = i & 31;
        int gr = row0 + r;
        float4 v = make_float4(0.f,0.f,0.f,0.f);
        if (gr < n) {
            v = ((const float4*)A)[gr*32 + cq];
            float sc = rs ? rs[gr*rss + rso] : 1.f;
            int c = cq*4;
            v.x = (v.x*sc - mean[c+0])*rstd[c+0] + BNB;
            v.y = (v.y*sc - mean[c+1])*rstd[c+1] + BNB;
            v.z = (v.z*sc - mean[c+2])*rstd[c+2] + BNB;
            v.w = (v.w*sc - mean[c+3])*rstd[c+3] + BNB;
        }
        ((float4*)As)[i] = v;
    }
    __syncthreads();

    int tc = tid & 15, tr = tid >> 4;
    int r0 = tr*4, r1 = 64 + tr*4;
    int c0 = tc*4, c1 = 64 + tc*4;

    u64 accp[8][4];
    #pragma unroll
    for (int i = 0; i < 8; i++)
        #pragma unroll
        for (int j = 0; j < 4; j++) accp[i][j] = 0ull;

    for (int k = 0; k < 128; k += 4) {
        float4 a4[8];
        #pragma unroll
        for (int i = 0; i < 4; i++) {
            a4[i]   = *(const float4*)&As[(r0+i)*128 + k];
            a4[4+i] = *(const float4*)&As[(r1+i)*128 + k];
        }
        #pragma unroll
        for (int kk = 0; kk < 4; kk++) {
            ulonglong2 w01 = *(const ulonglong2*)&Ws[(k+kk)*128 + c0];
            ulonglong2 w23 = *(const ulonglong2*)&Ws[(k+kk)*128 + c1];
            u64 wp0 = w01.x, wp1 = w01.y, wp2 = w23.x, wp3 = w23.y;
            #pragma unroll
            for (int i = 0; i < 8; i++) {
                float a = ((const float*)&a4[i])[kk];
                unsigned int ai = __float_as_uint(a);
                u64 ap;
                asm("mov.b64 %0, {%1, %1};" : "=l"(ap) : "r"(ai));
                asm("fma.rn.f32x2 %0, %1, %2, %0;" : "+l"(accp[i][0]) : "l"(ap), "l"(wp0));
                asm("fma.rn.f32x2 %0, %1, %2, %0;" : "+l"(accp[i][1]) : "l"(ap), "l"(wp1));
                asm("fma.rn.f32x2 %0, %1, %2, %0;" : "+l"(accp[i][2]) : "l"(ap), "l"(wp2));
                asm("fma.rn.f32x2 %0, %1, %2, %0;" : "+l"(accp[i][3]) : "l"(ap), "l"(wp3));
            }
        }
    }

    float4* O4 = (float4*)out;
    #pragma unroll
    for (int i = 0; i < 8; i++) {
        int gr = row0 + ((i < 4) ? (r0 + i) : (r1 + i - 4));
        if (gr < n) {
            float o[8];
            #pragma unroll
            for (int j = 0; j < 4; j++) {
                unsigned int lo, hi;
                asm("mov.b64 {%0, %1}, %2;" : "=r"(lo), "=r"(hi) : "l"(accp[i][j]));
                o[2*j]   = __uint_as_float(lo);
                o[2*j+1] = __uint_as_float(hi);
            }
            float4 o0 = make_float4(o[0], o[1], o[2], o[3]);
            float4 o1 = make_float4(o[4], o[5], o[6], o[7]);
            if (act == 1) {
                o0.x=fmaxf(o0.x,0.f); o0.y=fmaxf(o0.y,0.f);
                o0.z=fmaxf(o0.z,0.f); o0.w=fmaxf(o0.w,0.f);
                o1.x=fmaxf(o1.x,0.f); o1.y=fmaxf(o1.y,0.f);
                o1.z=fmaxf(o1.z,0.f); o1.w=fmaxf(o1.w,0.f);
            }
            O4[gr*32 + tc]      = o0;
            O4[gr*32 + 16 + tc] = o1;
        }
    }
}

// ---------------- CSR gather conv: one warp per dst node ----------------
__global__ __launch_bounds__(256) void gather128(
    const float* __restrict__ t,
    const int* __restrict__ rowptr, const int* __restrict__ eid,
    const int* __restrict__ esrc, const float* __restrict__ dis,
    const float* __restrict__ eatt, int ewo,
    const float* __restrict__ bias,
    float* __restrict__ out, int n, int act)
{
    int gt = blockIdx.x*blockDim.x + threadIdx.x;
    int v = gt >> 5, lane = gt & 31;
    if (v >= n) return;
    float dv = dis[v];
    float4 acc = ((const float4*)t)[v*32 + lane];
    float d2 = dv*dv;
    acc.x *= d2; acc.y *= d2; acc.z *= d2; acc.w *= d2;
    int st = rowptr[v], en = rowptr[v+1];
    for (int p = st; p < en; p++) {
        int e = __ldg(&eid[p]);
        int s = __ldg(&esrc[e]);
        float w = __ldg(&dis[s]) * dv;
        if (eatt) w *= __ldg(&eatt[e*2 + ewo]);
        float4 x = ((const float4*)t)[s*32 + lane];
        acc.x += w*x.x; acc.y += w*x.y; acc.z += w*x.z; acc.w += w*x.w;
    }
    if (bias) {
        float4 b = ((const float4*)bias)[lane];
        acc.x += b.x; acc.y += b.y; acc.z += b.z; acc.w += b.w;
    }
    if (act == 1) {
        acc.x = fmaxf(acc.x, 0.f); acc.y = fmaxf(acc.y, 0.f);
        acc.z = fmaxf(acc.z, 0.f); acc.w = fmaxf(acc.w, 0.f);
    }
    ((float4*)out)[v*32 + lane] = acc;
}

// ---------------- attention ----------------
__global__ void proj_kernel(const float* __restrict__ h, const float* __restrict__ eW,
                            const float* __restrict__ naW, float* __restrict__ epro,
                            float* __restrict__ t2, int n) {
    __shared__ float sEW[512];
    __shared__ float sNA[256];
    int tid = threadIdx.x;
    for (int i = tid; i < 512; i += blockDim.x) sEW[i] = eW[i];
    for (int i = tid; i < 256; i += blockDim.x) sNA[i] = naW[i];
    __syncthreads();
    int lane = tid & 31;
    int w0 = (blockIdx.x*blockDim.x + tid) >> 5;
    int nw = (gridDim.x*blockDim.x) >> 5;
    for (int v = w0; v < n; v += nw) {
        float4 hv = ((const float4*)h)[v*32 + lane];
        float hx[4] = {hv.x, hv.y, hv.z, hv.w};
        float p0=0,p1=0,q0=0,q1=0,u0=0,u1=0;
        #pragma unroll
        for (int i = 0; i < 4; i++) {
            int k = lane*4 + i; float x = hx[i];
            p0 += x*sEW[k*2+0];        p1 += x*sEW[k*2+1];
            q0 += x*sEW[(128+k)*2+0];  q1 += x*sEW[(128+k)*2+1];
            u0 += x*sNA[k*2+0];        u1 += x*sNA[k*2+1];
        }
        #pragma unroll
        for (int o = 16; o; o >>= 1) {
            p0 += __shfl_xor_sync(0xffffffffu, p0, o);
            p1 += __shfl_xor_sync(0xffffffffu, p1, o);
            q0 += __shfl_xor_sync(0xffffffffu, q0, o);
            q1 += __shfl_xor_sync(0xffffffffu, q1, o);
            u0 += __shfl_xor_sync(0xffffffffu, u0, o);
            u1 += __shfl_xor_sync(0xffffffffu, u1, o);
        }
        if (lane == 0) {
            epro[v*4+0]=p0; epro[v*4+1]=p1; epro[v*4+2]=q0; epro[v*4+3]=q1;
            t2[v*2+0]=u0; t2[v*2+1]=u1;
        }
    }
}

__global__ void edge_att_kernel(const int* __restrict__ src, const int* __restrict__ dst,
                                const float* __restrict__ epro, const float* __restrict__ eb,
                                float* __restrict__ eatt, float* deg0, float* deg1, int E) {
    int e = blockIdx.x*blockDim.x + threadIdx.x;
    if (e >= E) return;
    int s = src[e], d = dst[e];
    float l0 = epro[s*4+0] + epro[d*4+2] + eb[0];
    float l1 = epro[s*4+1] + epro[d*4+3] + eb[1];
    float m = fmaxf(l0, l1);
    float e0 = expf(l0 - m), e1 = expf(l1 - m);
    float inv = 1.f/(e0+e1);
    float a0 = e0*inv, a1 = e1*inv;
    eatt[e*2+0] = a0; eatt[e*2+1] = a1;
    atomicAdd(&deg0[s], a0);
    atomicAdd(&deg1[s], a1);
}

// fused node-attention gather + softmax (CSR)
__global__ void natt_gather(const float* __restrict__ t2,
                            const int* __restrict__ rowptr, const int* __restrict__ eid,
                            const int* __restrict__ esrc, const float* __restrict__ disU,
                            const float* __restrict__ nab,
                            float* __restrict__ natt, int n) {
    int v = blockIdx.x*blockDim.x + threadIdx.x;
    if (v >= n) return;
    float dv = disU[v];
    float d2 = dv*dv;
    float a0 = t2[v*2+0]*d2, a1 = t2[v*2+1]*d2;
    int st = rowptr[v], en = rowptr[v+1];
    for (int p = st; p < en; p++) {
        int e = eid[p];
        int s = esrc[e];
        float w = disU[s]*dv;
        a0 += w*t2[s*2+0];
        a1 += w*t2[s*2+1];
    }
    a0 += nab[0]; a1 += nab[1];
    float m = fmaxf(a0, a1);
    float e0 = expf(a0 - m), e1 = expf(a1 - m);
    float inv = 1.f/(e0+e1);
    natt[v*2+0] = e0*inv; natt[v*2+1] = e1*inv;
}

// pool with fused bias + elu
__global__ void pool_elu(const float* __restrict__ s, const float* __restrict__ b,
                         const int* __restrict__ gstart, float* __restrict__ cat, int off) {
    int g = blockIdx.x, c = threadIdx.x;
    int st = gstart[g], en = gstart[g+1];
    float bc = b[c], acc = 0.f;
    for (int v = st; v < en; v++) {
        float z = s[v*128 + c] + bc;
        acc += (z > 0.f) ? z : expm1f(z);
    }
    cat[g*256 + off + c] = acc;
}

// ---------------- head GEMM: one block per row ----------------
__global__ void head_gemm(const float* __restrict__ A, int lda, int aoff,
                          const float* __restrict__ mean, const float* __restrict__ rstd,
                          const float* __restrict__ W, const float* __restrict__ b,
                          float* __restrict__ out, int K, int cols, int act) {
    __shared__ float a[256];
    int r = blockIdx.x;
    for (int k = threadIdx.x; k < K; k += blockDim.x)
        a[k] = (A[r*lda + aoff + k] - mean[k]) * rstd[k] + BNB;
    __syncthreads();
    for (int c = threadIdx.x; c < cols; c += blockDim.x) {
        float acc = b[c];
        for (int k = 0; k < K; k++) acc += a[k] * W[k*cols + c];
        if (act == 1) acc = fmaxf(acc, 0.f);
        else if (act == 2) {
            acc = (acc > 0.f) ? acc : expm1f(acc);
            acc = (acc > 0.f) ? acc : expm1f(acc);
        }
        out[r*cols + c] = acc;
    }
}

__global__ void log_softmax10(const float* __restrict__ in, float* __restrict__ out, int G) {
    int r = blockIdx.x*blockDim.x + threadIdx.x;
    if (r >= G) return;
    float v[COUT]; float m = -1e30f;
    #pragma unroll
    for (int i = 0; i < COUT; i++) { v[i] = in[r*COUT + i]; m = fmaxf(m, v[i]); }
    float s = 0.f;
    #pragma unroll
    for (int i = 0; i < COUT; i++) s += expf(v[i] - m);
    float lse = m + logf(s);
    #pragma unroll
    for (int i = 0; i < COUT; i++) out[r*COUT + i] = v[i] - lse;
}

// ---------------- host orchestration ----------------
extern "C" void kernel_launch(void* const* d_in, const int* in_sizes, int n_in,
                              void* d_out, int out_size) {
    const float* x      = (const float*)d_in[0];
    const float* W_feat = (const float*)d_in[1];
    const float* conv_Ws= (const float*)d_in[2];
    const float* conv_bs= (const float*)d_in[3];
    const float* eW     = (const float*)d_in[4];
    const float* eb     = (const float*)d_in[5];
    const float* naW    = (const float*)d_in[6];
    const float* nab    = (const float*)d_in[7];
    const float* xcW    = (const float*)d_in[8];
    const float* xcb    = (const float*)d_in[9];
    const float* xoW    = (const float*)d_in[10];
    const float* xob    = (const float*)d_in[11];
    const float* cW1    = (const float*)d_in[12];
    const float* cb1    = (const float*)d_in[13];
    const float* cW2    = (const float*)d_in[14];
    const float* cb2    = (const float*)d_in[15];
    const float* oW1    = (const float*)d_in[16];
    const float* ob1    = (const float*)d_in[17];
    const float* oW2    = (const float*)d_in[18];
    const float* ob2    = (const float*)d_in[19];
    const float* coW1   = (const float*)d_in[20];
    const float* cob1   = (const float*)d_in[21];
    const float* coW2   = (const float*)d_in[22];
    const float* cob2   = (const float*)d_in[23];
    const int* esrc     = (const int*)d_in[24];
    const int* edst     = (const int*)d_in[25];
    const int* batch    = (const int*)d_in[26];
    float* out = (float*)d_out;

    float *p_h,*p_t,*p_s,*p_stats,*p_mean,*p_rstd,*p_disU,*p_dis0,*p_dis1;
    float *p_epro,*p_t2,*p_natt,*p_eatt,*p_cat,*p_hd,*p_logits;
    int *p_gstart,*p_cnt,*p_incl,*p_bsum,*p_rowptr,*p_cursor,*p_eid;
    cudaGetSymbolAddress((void**)&p_h, g_h);
    cudaGetSymbolAddress((void**)&p_t, g_t);
    cudaGetSymbolAddress((void**)&p_s, g_s);
    cudaGetSymbolAddress((void**)&p_stats, g_stats);
    cudaGetSymbolAddress((void**)&p_mean, g_mean);
    cudaGetSymbolAddress((void**)&p_rstd, g_rstd);
    cudaGetSymbolAddress((void**)&p_disU, g_disU);
    cudaGetSymbolAddress((void**)&p_dis0, g_dis0);
    cudaGetSymbolAddress((void**)&p_dis1, g_dis1);
    cudaGetSymbolAddress((void**)&p_epro, g_epro);
    cudaGetSymbolAddress((void**)&p_t2, g_t2);
    cudaGetSymbolAddress((void**)&p_natt, g_natt);
    cudaGetSymbolAddress((void**)&p_eatt, g_eatt);
    cudaGetSymbolAddress((void**)&p_cat, g_cat);
    cudaGetSymbolAddress((void**)&p_hd, g_hd);
    cudaGetSymbolAddress((void**)&p_logits, g_logits);
    cudaGetSymbolAddress((void**)&p_gstart, g_gstart);
    cudaGetSymbolAddress((void**)&p_cnt, g_cnt);
    cudaGetSymbolAddress((void**)&p_incl, g_incl);
    cudaGetSymbolAddress((void**)&p_bsum, g_bsum);
    cudaGetSymbolAddress((void**)&p_rowptr, g_rowptr);
    cudaGetSymbolAddress((void**)&p_cursor, g_cursor);
    cudaGetSymbolAddress((void**)&p_eid, g_eid);

    cudaFuncSetAttribute(gemm128, cudaFuncAttributeMaxDynamicSharedMemorySize, GEMM_SMEM);

    const int N = Nn, E = Ee, G = Gg;
    const int NB = (N + 127) / 128;
    const int NT = (N + 255) / 256;
    const int ET = (E + 255) / 256;
    const int GW = (N*32 + 255) / 256;
    const int NSCAN = (N + 1023) / 1024;

    // ---- CSR build + degrees + group starts ----
    cudaMemsetAsync(p_cnt, 0, Nn*sizeof(int));
    fill3_f32<<<NT,256>>>(p_disU, p_dis0, p_dis1, 1.f, N);
    deg_hist<<<ET,256>>>(esrc, edst, p_disU, p_cnt, E);
    scan_block<<<NSCAN,1024>>>(p_cnt, p_incl, p_bsum, N);
    scan_tops<<<1,32>>>(p_bsum, NSCAN);
    make_rowptr<<<NT,256>>>(p_cnt, p_incl, p_bsum, p_rowptr, p_cursor, N, E);
    fill_csr<<<ET,256>>>(edst, p_cursor, p_eid, E);
    rsqrt_one<<<NT,256>>>(p_disU, N);
    gstart_kernel<<<NT,256>>>(batch, p_gstart, N, G);

    // ---- h = relu(BN(x) @ W_feat) ----
    cudaMemsetAsync(p_stats, 0, 2048);
    colstats<128><<<512,256>>>(x, 128, 0, N, p_stats);
    finalize_stats<<<1,256>>>(p_stats, 128, 1.f/N, p_mean, p_rstd);
    gemm128<<<NB,256,GEMM_SMEM>>>(x, nullptr,0,0, p_mean, p_rstd, W_feat, p_h, N, 1);

    // ---- 3 GCN layers ----
    for (int l = 0; l < 3; l++) {
        cudaMemsetAsync(p_stats, 0, 2048);
        colstats<128><<<512,256>>>(p_h, 128, 0, N, p_stats);
        finalize_stats<<<1,256>>>(p_stats, 128, 1.f/N, p_mean, p_rstd);
        gemm128<<<NB,256,GEMM_SMEM>>>(p_h, nullptr,0,0, p_mean, p_rstd,
                                      conv_Ws + l*128*128, p_t, N, 0);
        gather128<<<GW,256>>>(p_t, p_rowptr, p_eid, esrc, p_disU, nullptr, 0,
                              conv_bs + l*128, p_h, N, 1);
    }

    // ---- attention ----
    proj_kernel<<<512,256>>>(p_h, eW, naW, p_epro, p_t2, N);
    edge_att_kernel<<<ET,256>>>(esrc, edst, p_epro, eb, p_eatt, p_dis0, p_dis1, E);
    rsqrt_two<<<NT,256>>>(p_dis0, p_dis1, N);
    natt_gather<<<NT,256>>>(p_t2, p_rowptr, p_eid, esrc, p_disU, nab, p_natt, N);

    // ---- XC / XO stats (one fused pass) ----
    cudaMemsetAsync(p_stats, 0, 2048);
    colstats2<<<512,256>>>(p_h, p_natt, N, p_stats);
    finalize_stats<<<1,256>>>(p_stats,       128, 1.f/N, p_mean,       p_rstd);
    finalize_stats<<<1,256>>>(p_stats + 256, 128, 1.f/N, p_mean + 128, p_rstd + 128);

    // ---- XC branch ----
    gemm128<<<NB,256,GEMM_SMEM>>>(p_h, p_natt, 2, 0, p_mean, p_rstd, xcW, p_t, N, 0);
    gather128<<<GW,256>>>(p_t, p_rowptr, p_eid, esrc, p_dis0, p_eatt, 0,
                          nullptr, p_s, N, 0);
    pool_elu<<<G,128>>>(p_s, xcb, p_gstart, p_cat, 0);

    // ---- XO branch ----
    gemm128<<<NB,256,GEMM_SMEM>>>(p_h, p_natt, 2, 1, p_mean + 128, p_rstd + 128,
                                  xoW, p_t, N, 0);
    gather128<<<GW,256>>>(p_t, p_rowptr, p_eid, esrc, p_dis1, p_eatt, 1,
                          nullptr, p_s, N, 0);
    pool_elu<<<G,128>>>(p_s, xob, p_gstart, p_cat, 128);

    // ---- C head ----
    head_stats<<<128,128>>>(p_cat, 256, 0, G, p_mean, p_rstd);
    head_gemm<<<G,128>>>(p_cat, 256, 0, p_mean, p_rstd, cW1, cb1, p_hd, 128, 128, 1);
    head_stats<<<128,128>>>(p_hd, 128, 0, G, p_mean, p_rstd);
    head_gemm<<<G,128>>>(p_hd, 128, 0, p_mean, p_rstd, cW2, cb2, p_logits, 128, COUT, 0);
    log_softmax10<<<(G+127)/128,128>>>(p_logits, out, G);

    // ---- O head ----
    head_stats<<<128,128>>>(p_cat, 256, 128, G, p_mean, p_rstd);
    head_gemm<<<G,128>>>(p_cat, 256, 128, p_mean, p_rstd, oW1, ob1, p_hd, 128, 128, 1);
    head_stats<<<128,128>>>(p_hd, 128, 0, G, p_mean, p_rstd);
    head_gemm<<<G,128>>>(p_hd, 128, 0, p_mean, p_rstd, oW2, ob2, p_logits, 128, COUT, 0);
    log_softmax10<<<(G+127)/128,128>>>(p_logits, out + G*COUT, G);

    // ---- CO head ----
    head_stats<<<256,128>>>(p_cat, 256, 0, G, p_mean, p_rstd);
    head_gemm<<<G,128>>>(p_cat, 256, 0, p_mean, p_rstd, coW1, cob1, p_hd, 256, 128, 2);
    head_stats<<<128,128>>>(p_hd, 128, 0, G, p_mean, p_rstd);
    head_gemm<<<G,128>>>(p_hd, 128, 0, p_mean, p_rstd, coW2, cob2, p_logits, 128, COUT, 0);
    log_softmax10<<<(G+127)/128,128>>>(p_logits, out + 2*G*COUT, G);
}

// round 6
// speedup vs baseline: 1.4910x; 1.1479x over previous
#include <cuda_runtime.h>
#include <math.h>

#define Nn 50000
#define Ee 400000
#define Hh 128
#define Gg 512
#define COUT 10

typedef unsigned long long u64;

static constexpr float EPSBN = 1e-5f;
static constexpr float BNB   = 1e-4f;

// ---------------- scratch (static device allocations) ----------------
__device__ float g_h[Nn*Hh];
__device__ float g_t[Nn*Hh];
__device__ float g_t2b[Nn*Hh];     // second GEMM output (XO branch)
__device__ float g_s[Nn*Hh];
__device__ float g_s2[Nn*Hh];
__device__ float g_stats[512];
__device__ float g_mean[512];
__device__ float g_rstd[512];
__device__ float g_disU[Nn];
__device__ float g_dis0[Nn];
__device__ float g_dis1[Nn];
__device__ float g_epro[Nn*4];
__device__ float g_t2[Nn*2];
__device__ float g_natt[Nn*2];
__device__ float g_eatt[Ee*2];
__device__ int   g_gstart[Gg+1];
__device__ float g_cat[Gg*256];
__device__ float g_hd[3*Gg*128];
// CSR by destination
__device__ int g_cnt[Nn];
__device__ int g_incl[Nn];
__device__ int g_bsum[64];
__device__ int g_rowptr[Nn+1];
__device__ int g_cursor[Nn];
__device__ int g_eid[Ee];

// ---------------- small utility kernels ----------------
__global__ void fill3_f32(float* a, float* b, float* c, float v, int n) {
    int i = blockIdx.x*blockDim.x + threadIdx.x;
    if (i < n) { a[i] = v; b[i] = v; c[i] = v; }
}

__global__ void deg_hist(const int* __restrict__ src, const int* __restrict__ dst,
                         float* degU, int* cnt, int E) {
    int i = blockIdx.x*blockDim.x + threadIdx.x;
    if (i < E) {
        atomicAdd(&degU[src[i]], 1.0f);
        atomicAdd(&cnt[dst[i]], 1);
    }
}

__global__ void rsqrt_one(float* p, int n) {
    int i = blockIdx.x*blockDim.x + threadIdx.x;
    if (i < n) p[i] = rsqrtf(p[i]);
}

__global__ void rsqrt_two(float* p, float* q, int n) {
    int i = blockIdx.x*blockDim.x + threadIdx.x;
    if (i < n) { p[i] = rsqrtf(p[i]); q[i] = rsqrtf(q[i]); }
}

__global__ void gstart_kernel(const int* __restrict__ batch, int* gstart, int n, int G) {
    int i = blockIdx.x*blockDim.x + threadIdx.x;
    if (i >= n) return;
    int b  = batch[i];
    int pb = (i == 0) ? -1 : batch[i-1];
    for (int g = pb+1; g <= b; g++) gstart[g] = i;
    if (i == n-1) {
        for (int g = b+1; g <= G; g++) gstart[g] = n;
    }
}

// ---------------- CSR build ----------------
__global__ void scan_block(const int* __restrict__ cnt, int* incl, int* bsum, int n) {
    __shared__ int sm[1024];
    int i = blockIdx.x*1024 + threadIdx.x;
    sm[threadIdx.x] = (i < n) ? cnt[i] : 0;
    __syncthreads();
    for (int off = 1; off < 1024; off <<= 1) {
        int t = (threadIdx.x >= off) ? sm[threadIdx.x - off] : 0;
        __syncthreads();
        sm[threadIdx.x] += t;
        __syncthreads();
    }
    if (i < n) incl[i] = sm[threadIdx.x];
    if (threadIdx.x == 1023) bsum[blockIdx.x] = sm[1023];
}

__global__ void scan_tops(int* bsum, int nb) {
    if (threadIdx.x == 0 && blockIdx.x == 0) {
        int s = 0;
        for (int i = 0; i < nb; i++) { s += bsum[i]; bsum[i] = s; }
    }
}

__global__ void make_rowptr(const int* __restrict__ cnt, const int* __restrict__ incl,
                            const int* __restrict__ bsum,
                            int* rowptr, int* cursor, int n, int E) {
    int i = blockIdx.x*blockDim.x + threadIdx.x;
    if (i < n) {
        int b = i >> 10;
        int ex = incl[i] - cnt[i] + ((b > 0) ? bsum[b-1] : 0);
        rowptr[i] = ex;
        cursor[i] = ex;
    }
    if (i == 0) rowptr[n] = E;
}

__global__ void fill_csr(const int* __restrict__ dst, int* cursor, int* eid, int E) {
    int e = blockIdx.x*blockDim.x + threadIdx.x;
    if (e < E) {
        int p = atomicAdd(&cursor[dst[e]], 1);
        eid[p] = e;
    }
}

// ---------------- BatchNorm stats ----------------
__global__ void colstats(const float* __restrict__ A, int n, float* sums) {
    long total  = (long)n * 128;
    long stride = (long)gridDim.x * blockDim.x;
    long i0     = (long)blockIdx.x*blockDim.x + threadIdx.x;
    if (i0 >= total) return;
    int c = (int)(i0 % 128);
    float s0 = 0.f, s1 = 0.f;
    for (long i = i0; i < total; i += stride) {
        int r = (int)(i / 128);
        float v = A[(long)r*128 + c];
        s0 += v; s1 += v*v;
    }
    atomicAdd(&sums[c], s0);
    atomicAdd(&sums[128+c], s1);
}

__global__ void colstats2(const float* __restrict__ A, const float* __restrict__ natt,
                          int n, float* sums) {
    long total  = (long)n * 128;
    long stride = (long)gridDim.x * blockDim.x;
    long i0     = (long)blockIdx.x*blockDim.x + threadIdx.x;
    if (i0 >= total) return;
    int c = (int)(i0 % 128);
    float s00=0.f, s01=0.f, s10=0.f, s11=0.f;
    for (long i = i0; i < total; i += stride) {
        int r = (int)(i / 128);
        float v = A[(long)r*128 + c];
        float v0 = v * natt[r*2+0];
        float v1 = v * natt[r*2+1];
        s00 += v0; s01 += v0*v0;
        s10 += v1; s11 += v1*v1;
    }
    atomicAdd(&sums[c], s00);
    atomicAdd(&sums[128+c], s01);
    atomicAdd(&sums[256+c], s10);
    atomicAdd(&sums[384+c], s11);
}

__global__ void finalize_stats(const float* __restrict__ sums, int C, float inv_n,
                               float* mean, float* rstd) {
    int c = threadIdx.x + blockIdx.x*blockDim.x;
    if (c < C) {
        float m = sums[c]*inv_n;
        float var = sums[C+c]*inv_n - m*m;
        mean[c] = m;
        rstd[c] = rsqrtf(var + EPSBN);
    }
}

// head stats: one block per column over an [n, lda] matrix
__global__ void head_stats(const float* __restrict__ A, int lda, int n,
                           float* mean, float* rstd) {
    __shared__ float s0s[4], s1s[4];
    int c = blockIdx.x;
    int lane = threadIdx.x & 31, warp = threadIdx.x >> 5;
    float s0 = 0.f, s1 = 0.f;
    for (int r = threadIdx.x; r < n; r += blockDim.x) {
        float v = A[r*lda + c];
        s0 += v; s1 += v*v;
    }
    #pragma unroll
    for (int o = 16; o; o >>= 1) {
        s0 += __shfl_xor_sync(0xffffffffu, s0, o);
        s1 += __shfl_xor_sync(0xffffffffu, s1, o);
    }
    if (lane == 0) { s0s[warp] = s0; s1s[warp] = s1; }
    __syncthreads();
    if (threadIdx.x == 0) {
        float t0 = 0.f, t1 = 0.f;
        for (int w = 0; w < 4; w++) { t0 += s0s[w]; t1 += s1s[w]; }
        float m = t0 / n;
        float var = t1 / n - m*m;
        mean[c] = m;
        rstd[c] = rsqrtf(var + EPSBN);
    }
}

// stats over 3 concatenated [n,128] buffers (head layer-2)
__global__ void head_stats3(const float* __restrict__ hd, int n,
                            float* mean, float* rstd) {
    __shared__ float s0s[4], s1s[4];
    int cg = blockIdx.x;             // 0..383
    int head = cg >> 7, c = cg & 127;
    const float* A = hd + head*Gg*128;
    int lane = threadIdx.x & 31, warp = threadIdx.x >> 5;
    float s0 = 0.f, s1 = 0.f;
    for (int r = threadIdx.x; r < n; r += blockDim.x) {
        float v = A[r*128 + c];
        s0 += v; s1 += v*v;
    }
    #pragma unroll
    for (int o = 16; o; o >>= 1) {
        s0 += __shfl_xor_sync(0xffffffffu, s0, o);
        s1 += __shfl_xor_sync(0xffffffffu, s1, o);
    }
    if (lane == 0) { s0s[warp] = s0; s1s[warp] = s1; }
    __syncthreads();
    if (threadIdx.x == 0) {
        float t0 = 0.f, t1 = 0.f;
        for (int w = 0; w < 4; w++) { t0 += s0s[w]; t1 += s1s[w]; }
        float m = t0 / n;
        float var = t1 / n - m*m;
        mean[cg] = m;
        rstd[cg] = rsqrtf(var + EPSBN);
    }
}

// ---------------- big GEMM (packed f32x2 FMA, BM=64) ----------------
// out[n,128] = act( BN(rs*A)[n,128] @ W[128,128] ), optional column stats out
static constexpr int GEMM_SMEM = (64*128 + 128*128) * 4;   // 96 KB

__global__ __launch_bounds__(256) void gemm128(
    const float* __restrict__ A,
    const float* __restrict__ rs, int rss, int rso,
    const float* __restrict__ mean, const float* __restrict__ rstd,
    const float* __restrict__ W,
    float* __restrict__ out,
    float* __restrict__ sums,
    int n, int act)
{
    extern __shared__ float sm[];
    float* As = sm;               // [64][128]
    float* Ws = sm + 64*128;      // [128][128]
    int tid  = threadIdx.x;
    int row0 = blockIdx.x * 64;

    const float4* Wg = (const float4*)W;
    float4* Ws4 = (float4*)Ws;
    #pragma unroll 4
    for (int i = tid; i < 128*32; i += 256) Ws4[i] = Wg[i];

    #pragma unroll 2
    for (int i = tid; i < 64*32; i += 256) {
        int r = i >> 5, cq = i & 31;
        int gr = row0 + r;
        float4 v = make_float4(0.f,0.f,0.f,0.f);
        if (gr < n) {
            v = ((const float4*)A)[gr*32 + cq];
            float sc = rs ? rs[gr*rss + rso] : 1.f;
            int c = cq*4;
            v.x = (v.x*sc - mean[c+0])*rstd[c+0] + BNB;
            v.y = (v.y*sc - mean[c+1])*rstd[c+1] + BNB;
            v.z = (v.z*sc - mean[c+2])*rstd[c+2] + BNB;
            v.w = (v.w*sc - mean[c+3])*rstd[c+3] + BNB;
        }
        ((float4*)As)[i] = v;
    }
    __syncthreads();

    int tc = tid & 15, tr = tid >> 4;
    int r0 = tr*4;
    int c0 = tc*4, c1 = 64 + tc*4;

    u64 accp[4][4];
    #pragma unroll
    for (int i = 0; i < 4; i++)
        #pragma unroll
        for (int j = 0; j < 4; j++) accp[i][j] = 0ull;

    for (int k = 0; k < 128; k += 4) {
        float4 a4[4];
        #pragma unroll
        for (int i = 0; i < 4; i++)
            a4[i] = *(const float4*)&As[(r0+i)*128 + k];
        #pragma unroll
        for (int kk = 0; kk < 4; kk++) {
            ulonglong2 w01 = *(const ulonglong2*)&Ws[(k+kk)*128 + c0];
            ulonglong2 w23 = *(const ulonglong2*)&Ws[(k+kk)*128 + c1];
            u64 wp0 = w01.x, wp1 = w01.y, wp2 = w23.x, wp3 = w23.y;
            #pragma unroll
            for (int i = 0; i < 4; i++) {
                float a = ((const float*)&a4[i])[kk];
                unsigned int ai = __float_as_uint(a);
                u64 ap;
                asm("mov.b64 %0, {%1, %1};" : "=l"(ap) : "r"(ai));
                asm("fma.rn.f32x2 %0, %1, %2, %0;" : "+l"(accp[i][0]) : "l"(ap), "l"(wp0));
                asm("fma.rn.f32x2 %0, %1, %2, %0;" : "+l"(accp[i][1]) : "l"(ap), "l"(wp1));
                asm("fma.rn.f32x2 %0, %1, %2, %0;" : "+l"(accp[i][2]) : "l"(ap), "l"(wp2));
                asm("fma.rn.f32x2 %0, %1, %2, %0;" : "+l"(accp[i][3]) : "l"(ap), "l"(wp3));
            }
        }
    }

    float t0[8], t1[8];
    #pragma unroll
    for (int j = 0; j < 8; j++) { t0[j] = 0.f; t1[j] = 0.f; }

    float4* O4 = (float4*)out;
    #pragma unroll
    for (int i = 0; i < 4; i++) {
        int gr = row0 + r0 + i;
        if (gr < n) {
            float o[8];
            #pragma unroll
            for (int j = 0; j < 4; j++) {
                unsigned int lo, hi;
                asm("mov.b64 {%0, %1}, %2;" : "=r"(lo), "=r"(hi) : "l"(accp[i][j]));
                o[2*j]   = __uint_as_float(lo);
                o[2*j+1] = __uint_as_float(hi);
            }
            if (act == 1) {
                #pragma unroll
                for (int j = 0; j < 8; j++) o[j] = fmaxf(o[j], 0.f);
            }
            if (sums) {
                #pragma unroll
                for (int j = 0; j < 8; j++) { t0[j] += o[j]; t1[j] += o[j]*o[j]; }
            }
            O4[gr*32 + tc]      = make_float4(o[0], o[1], o[2], o[3]);
            O4[gr*32 + 16 + tc] = make_float4(o[4], o[5], o[6], o[7]);
        }
    }

    if (sums) {
        __syncthreads();
        float* ss = sm;       // reuse 256 floats
        ss[tid] = 0.f;
        __syncthreads();
        #pragma unroll
        for (int j = 0; j < 4; j++) {
            atomicAdd(&ss[c0+j],     t0[j]);   atomicAdd(&ss[128+c0+j], t1[j]);
            atomicAdd(&ss[c1+j],     t0[4+j]); atomicAdd(&ss[128+c1+j], t1[4+j]);
        }
        __syncthreads();
        atomicAdd(&sums[tid], ss[tid]);
    }
}

// ---------------- CSR gather conv (grid-stride warp per node, optional stats) ----------------
__global__ __launch_bounds__(256) void gather128(
    const float* __restrict__ t,
    const int* __restrict__ rowptr, const int* __restrict__ eid,
    const int* __restrict__ esrc, const float* __restrict__ dis,
    const float* __restrict__ bias,
    float* __restrict__ out, float* __restrict__ sums, int n, int act)
{
    int lane = threadIdx.x & 31;
    int w0 = (blockIdx.x*blockDim.x + threadIdx.x) >> 5;
    int nw = (gridDim.x*blockDim.x) >> 5;
    float4 bb = bias ? ((const float4*)bias)[lane] : make_float4(0.f,0.f,0.f,0.f);
    float ls0[4] = {0.f,0.f,0.f,0.f}, ls1[4] = {0.f,0.f,0.f,0.f};

    for (int v = w0; v < n; v += nw) {
        float dv = dis[v];
        float4 acc = ((const float4*)t)[v*32 + lane];
        float d2 = dv*dv;
        acc.x *= d2; acc.y *= d2; acc.z *= d2; acc.w *= d2;
        int st = rowptr[v], en = rowptr[v+1];
        for (int p = st; p < en; p++) {
            int e = __ldg(&eid[p]);
            int s = __ldg(&esrc[e]);
            float w = __ldg(&dis[s]) * dv;
            float4 x = ((const float4*)t)[s*32 + lane];
            acc.x += w*x.x; acc.y += w*x.y; acc.z += w*x.z; acc.w += w*x.w;
        }
        acc.x += bb.x; acc.y += bb.y; acc.z += bb.z; acc.w += bb.w;
        if (act == 1) {
            acc.x = fmaxf(acc.x, 0.f); acc.y = fmaxf(acc.y, 0.f);
            acc.z = fmaxf(acc.z, 0.f); acc.w = fmaxf(acc.w, 0.f);
        }
        if (sums) {
            ls0[0]+=acc.x; ls1[0]+=acc.x*acc.x;
            ls0[1]+=acc.y; ls1[1]+=acc.y*acc.y;
            ls0[2]+=acc.z; ls1[2]+=acc.z*acc.z;
            ls0[3]+=acc.w; ls1[3]+=acc.w*acc.w;
        }
        ((float4*)out)[v*32 + lane] = acc;
    }

    if (sums) {
        __shared__ float ss[256];
        ss[threadIdx.x] = 0.f;
        __syncthreads();
        #pragma unroll
        for (int j = 0; j < 4; j++) {
            atomicAdd(&ss[lane*4+j],     ls0[j]);
            atomicAdd(&ss[128+lane*4+j], ls1[j]);
        }
        __syncthreads();
        atomicAdd(&sums[threadIdx.x], ss[threadIdx.x]);
    }
}

// fused XC+XO gather (edge-weighted, no bias/act)
__global__ __launch_bounds__(256) void gather2(
    const float* __restrict__ tc_, const float* __restrict__ to_,
    const int* __restrict__ rowptr, const int* __restrict__ eid,
    const int* __restrict__ esrc,
    const float* __restrict__ dis0, const float* __restrict__ dis1,
    const float* __restrict__ eatt,
    float* __restrict__ sc_, float* __restrict__ so_, int n)
{
    int lane = threadIdx.x & 31;
    int w0 = (blockIdx.x*blockDim.x + threadIdx.x) >> 5;
    int nw = (gridDim.x*blockDim.x) >> 5;
    for (int v = w0; v < n; v += nw) {
        float d0v = dis0[v], d1v = dis1[v];
        float4 ac = ((const float4*)tc_)[v*32 + lane];
        float4 ao = ((const float4*)to_)[v*32 + lane];
        float d02 = d0v*d0v, d12 = d1v*d1v;
        ac.x *= d02; ac.y *= d02; ac.z *= d02; ac.w *= d02;
        ao.x *= d12; ao.y *= d12; ao.z *= d12; ao.w *= d12;
        int st = rowptr[v], en = rowptr[v+1];
        for (int p = st; p < en; p++) {
            int e = __ldg(&eid[p]);
            int s = __ldg(&esrc[e]);
            float2 ea = __ldg((const float2*)&eatt[e*2]);
            float wc = __ldg(&dis0[s]) * d0v * ea.x;
            float wo = __ldg(&dis1[s]) * d1v * ea.y;
            float4 xc = ((const float4*)tc_)[s*32 + lane];
            float4 xo = ((const float4*)to_)[s*32 + lane];
            ac.x += wc*xc.x; ac.y += wc*xc.y; ac.z += wc*xc.z; ac.w += wc*xc.w;
            ao.x += wo*xo.x; ao.y += wo*xo.y; ao.z += wo*xo.z; ao.w += wo*xo.w;
        }
        ((float4*)sc_)[v*32 + lane] = ac;
        ((float4*)so_)[v*32 + lane] = ao;
    }
}

// ---------------- attention ----------------
__global__ void proj_kernel(const float* __restrict__ h, const float* __restrict__ eW,
                            const float* __restrict__ naW, float* __restrict__ epro,
                            float* __restrict__ t2, int n) {
    __shared__ float sEW[512];
    __shared__ float sNA[256];
    int tid = threadIdx.x;
    for (int i = tid; i < 512; i += blockDim.x) sEW[i] = eW[i];
    for (int i = tid; i < 256; i += blockDim.x) sNA[i] = naW[i];
    __syncthreads();
    int lane = tid & 31;
    int w0 = (blockIdx.x*blockDim.x + tid) >> 5;
    int nw = (gridDim.x*blockDim.x) >> 5;
    for (int v = w0; v < n; v += nw) {
        float4 hv = ((const float4*)h)[v*32 + lane];
        float hx[4] = {hv.x, hv.y, hv.z, hv.w};
        float p0=0,p1=0,q0=0,q1=0,u0=0,u1=0;
        #pragma unroll
        for (int i = 0; i < 4; i++) {
            int k = lane*4 + i; float x = hx[i];
            p0 += x*sEW[k*2+0];        p1 += x*sEW[k*2+1];
            q0 += x*sEW[(128+k)*2+0];  q1 += x*sEW[(128+k)*2+1];
            u0 += x*sNA[k*2+0];        u1 += x*sNA[k*2+1];
        }
        #pragma unroll
        for (int o = 16; o; o >>= 1) {
            p0 += __shfl_xor_sync(0xffffffffu, p0, o);
            p1 += __shfl_xor_sync(0xffffffffu, p1, o);
            q0 += __shfl_xor_sync(0xffffffffu, q0, o);
            q1 += __shfl_xor_sync(0xffffffffu, q1, o);
            u0 += __shfl_xor_sync(0xffffffffu, u0, o);
            u1 += __shfl_xor_sync(0xffffffffu, u1, o);
        }
        if (lane == 0) {
            epro[v*4+0]=p0; epro[v*4+1]=p1; epro[v*4+2]=q0; epro[v*4+3]=q1;
            t2[v*2+0]=u0; t2[v*2+1]=u1;
        }
    }
}

__global__ void edge_att_kernel(const int* __restrict__ src, const int* __restrict__ dst,
                                const float* __restrict__ epro, const float* __restrict__ eb,
                                float* __restrict__ eatt, float* deg0, float* deg1, int E) {
    int e = blockIdx.x*blockDim.x + threadIdx.x;
    if (e >= E) return;
    int s = src[e], d = dst[e];
    float l0 = epro[s*4+0] + epro[d*4+2] + eb[0];
    float l1 = epro[s*4+1] + epro[d*4+3] + eb[1];
    float m = fmaxf(l0, l1);
    float e0 = expf(l0 - m), e1 = expf(l1 - m);
    float inv = 1.f/(e0+e1);
    float a0 = e0*inv, a1 = e1*inv;
    eatt[e*2+0] = a0; eatt[e*2+1] = a1;
    atomicAdd(&deg0[s], a0);
    atomicAdd(&deg1[s], a1);
}

__global__ void natt_gather(const float* __restrict__ t2,
                            const int* __restrict__ rowptr, const int* __restrict__ eid,
                            const int* __restrict__ esrc, const float* __restrict__ disU,
                            const float* __restrict__ nab,
                            float* __restrict__ natt, int n) {
    int v = blockIdx.x*blockDim.x + threadIdx.x;
    if (v >= n) return;
    float dv = disU[v];
    float d2 = dv*dv;
    float a0 = t2[v*2+0]*d2, a1 = t2[v*2+1]*d2;
    int st = rowptr[v], en = rowptr[v+1];
    for (int p = st; p < en; p++) {
        int e = eid[p];
        int s = esrc[e];
        float w = disU[s]*dv;
        a0 += w*t2[s*2+0];
        a1 += w*t2[s*2+1];
    }
    a0 += nab[0]; a1 += nab[1];
    float m = fmaxf(a0, a1);
    float e0 = expf(a0 - m), e1 = expf(a1 - m);
    float inv = 1.f/(e0+e1);
    natt[v*2+0] = e0*inv; natt[v*2+1] = e1*inv;
}

// fused pooling of both branches: cat[g, 0:128]=xc pool, cat[g,128:256]=xo pool
__global__ void pool_both(const float* __restrict__ sc_, const float* __restrict__ so_,
                          const float* __restrict__ xcb, const float* __restrict__ xob,
                          const int* __restrict__ gstart, float* __restrict__ cat) {
    int g = blockIdx.x, c = threadIdx.x;
    int st = gstart[g], en = gstart[g+1];
    const float* s = (c < 128) ? sc_ : so_;
    int cc = c & 127;
    float bc = (c < 128) ? xcb[cc] : xob[cc];
    float acc = 0.f;
    for (int v = st; v < en; v++) {
        float z = s[v*128 + cc] + bc;
        acc += (z > 0.f) ? z : expm1f(z);
    }
    cat[g*256 + c] = acc;
}

// ---------------- fused heads ----------------
// layer 1: three GEMMs off cat (heads: 0=C relu, 1=O relu, 2=CO double-elu)
__global__ void head_gemm1(const float* __restrict__ cat,
                           const float* __restrict__ mean, const float* __restrict__ rstd,
                           const float* __restrict__ cW1, const float* __restrict__ cb1,
                           const float* __restrict__ oW1, const float* __restrict__ ob1,
                           const float* __restrict__ coW1, const float* __restrict__ cob1,
                           float* __restrict__ hd) {
    __shared__ float a[256];
    int r = blockIdx.x, head = blockIdx.y;
    for (int k = threadIdx.x; k < 256; k += 128)
        a[k] = (cat[r*256 + k] - mean[k]) * rstd[k] + BNB;
    __syncthreads();
    const float* W; const float* b; int K, koff, act;
    if (head == 0)      { W = cW1;  b = cb1;  K = 128; koff = 0;   act = 1; }
    else if (head == 1) { W = oW1;  b = ob1;  K = 128; koff = 128; act = 1; }
    else                { W = coW1; b = cob1; K = 256; koff = 0;   act = 2; }
    int c = threadIdx.x;
    float acc = b[c];
    for (int k = 0; k < K; k++) acc += a[koff + k] * W[k*128 + c];
    if (act == 1) acc = fmaxf(acc, 0.f);
    else {
        acc = (acc > 0.f) ? acc : expm1f(acc);
        acc = (acc > 0.f) ? acc : expm1f(acc);
    }
    hd[(head*Gg + r)*128 + c] = acc;
}

// layer 2 + log_softmax
__global__ void head_gemm2_lsm(const float* __restrict__ hd,
                               const float* __restrict__ mean, const float* __restrict__ rstd,
                               const float* __restrict__ cW2, const float* __restrict__ cb2,
                               const float* __restrict__ oW2, const float* __restrict__ ob2,
                               const float* __restrict__ coW2, const float* __restrict__ cob2,
                               float* __restrict__ out) {
    __shared__ float a[128];
    __shared__ float lg[COUT];
    int r = blockIdx.x, head = blockIdx.y;
    int k = threadIdx.x;
    a[k] = (hd[(head*Gg + r)*128 + k] - mean[head*128 + k]) * rstd[head*128 + k] + BNB;
    __syncthreads();
    const float* W = (head == 0) ? cW2 : (head == 1) ? oW2 : coW2;
    const float* b = (head == 0) ? cb2 : (head == 1) ? ob2 : cob2;
    if (k < COUT) {
        float acc = b[k];
        for (int kk = 0; kk < 128; kk++) acc += a[kk] * W[kk*COUT + k];
        lg[k] = acc;
    }
    __syncthreads();
    if (k < COUT) {
        float m = -1e30f;
        #pragma unroll
        for (int i = 0; i < COUT; i++) m = fmaxf(m, lg[i]);
        float s = 0.f;
        #pragma unroll
        for (int i = 0; i < COUT; i++) s += expf(lg[i] - m);
        out[head*Gg*COUT + r*COUT + k] = lg[k] - m - logf(s);
    }
}

// ---------------- host orchestration ----------------
extern "C" void kernel_launch(void* const* d_in, const int* in_sizes, int n_in,
                              void* d_out, int out_size) {
    const float* x      = (const float*)d_in[0];
    const float* W_feat = (const float*)d_in[1];
    const float* conv_Ws= (const float*)d_in[2];
    const float* conv_bs= (const float*)d_in[3];
    const float* eW     = (const float*)d_in[4];
    const float* eb     = (const float*)d_in[5];
    const float* naW    = (const float*)d_in[6];
    const float* nab    = (const float*)d_in[7];
    const float* xcW    = (const float*)d_in[8];
    const float* xcb    = (const float*)d_in[9];
    const float* xoW    = (const float*)d_in[10];
    const float* xob    = (const float*)d_in[11];
    const float* cW1    = (const float*)d_in[12];
    const float* cb1    = (const float*)d_in[13];
    const float* cW2    = (const float*)d_in[14];
    const float* cb2    = (const float*)d_in[15];
    const float* oW1    = (const float*)d_in[16];
    const float* ob1    = (const float*)d_in[17];
    const float* oW2    = (const float*)d_in[18];
    const float* ob2    = (const float*)d_in[19];
    const float* coW1   = (const float*)d_in[20];
    const float* cob1   = (const float*)d_in[21];
    const float* coW2   = (const float*)d_in[22];
    const float* cob2   = (const float*)d_in[23];
    const int* esrc     = (const int*)d_in[24];
    const int* edst     = (const int*)d_in[25];
    const int* batch    = (const int*)d_in[26];
    float* out = (float*)d_out;

    float *p_h,*p_t,*p_t2b,*p_s,*p_s2,*p_stats,*p_mean,*p_rstd,*p_disU,*p_dis0,*p_dis1;
    float *p_epro,*p_t2,*p_natt,*p_eatt,*p_cat,*p_hd;
    int *p_gstart,*p_cnt,*p_incl,*p_bsum,*p_rowptr,*p_cursor,*p_eid;
    cudaGetSymbolAddress((void**)&p_h, g_h);
    cudaGetSymbolAddress((void**)&p_t, g_t);
    cudaGetSymbolAddress((void**)&p_t2b, g_t2b);
    cudaGetSymbolAddress((void**)&p_s, g_s);
    cudaGetSymbolAddress((void**)&p_s2, g_s2);
    cudaGetSymbolAddress((void**)&p_stats, g_stats);
    cudaGetSymbolAddress((void**)&p_mean, g_mean);
    cudaGetSymbolAddress((void**)&p_rstd, g_rstd);
    cudaGetSymbolAddress((void**)&p_disU, g_disU);
    cudaGetSymbolAddress((void**)&p_dis0, g_dis0);
    cudaGetSymbolAddress((void**)&p_dis1, g_dis1);
    cudaGetSymbolAddress((void**)&p_epro, g_epro);
    cudaGetSymbolAddress((void**)&p_t2, g_t2);
    cudaGetSymbolAddress((void**)&p_natt, g_natt);
    cudaGetSymbolAddress((void**)&p_eatt, g_eatt);
    cudaGetSymbolAddress((void**)&p_cat, g_cat);
    cudaGetSymbolAddress((void**)&p_hd, g_hd);
    cudaGetSymbolAddress((void**)&p_gstart, g_gstart);
    cudaGetSymbolAddress((void**)&p_cnt, g_cnt);
    cudaGetSymbolAddress((void**)&p_incl, g_incl);
    cudaGetSymbolAddress((void**)&p_bsum, g_bsum);
    cudaGetSymbolAddress((void**)&p_rowptr, g_rowptr);
    cudaGetSymbolAddress((void**)&p_cursor, g_cursor);
    cudaGetSymbolAddress((void**)&p_eid, g_eid);

    cudaFuncSetAttribute(gemm128, cudaFuncAttributeMaxDynamicSharedMemorySize, GEMM_SMEM);

    const int N = Nn, E = Ee, G = Gg;
    const int NB = (N + 63) / 64;
    const int NT = (N + 255) / 256;
    const int ET = (E + 255) / 256;
    const int GB = 1024;               // gather grid (grid-stride)
    const int NSCAN = (N + 1023) / 1024;

    // ---- CSR build + degrees + group starts ----
    cudaMemsetAsync(p_cnt, 0, Nn*sizeof(int));
    fill3_f32<<<NT,256>>>(p_disU, p_dis0, p_dis1, 1.f, N);
    deg_hist<<<ET,256>>>(esrc, edst, p_disU, p_cnt, E);
    scan_block<<<NSCAN,1024>>>(p_cnt, p_incl, p_bsum, N);
    scan_tops<<<1,32>>>(p_bsum, NSCAN);
    make_rowptr<<<NT,256>>>(p_cnt, p_incl, p_bsum, p_rowptr, p_cursor, N, E);
    fill_csr<<<ET,256>>>(edst, p_cursor, p_eid, E);
    rsqrt_one<<<NT,256>>>(p_disU, N);
    gstart_kernel<<<NT,256>>>(batch, p_gstart, N, G);

    // ---- h = relu(BN(x) @ W_feat), h-stats fused into epilogue ----
    cudaMemsetAsync(p_stats, 0, 1024);
    colstats<<<512,256>>>(x, N, p_stats);
    finalize_stats<<<1,256>>>(p_stats, 128, 1.f/N, p_mean, p_rstd);
    cudaMemsetAsync(p_stats, 0, 1024);
    gemm128<<<NB,256,GEMM_SMEM>>>(x, nullptr,0,0, p_mean, p_rstd, W_feat,
                                  p_h, p_stats, N, 1);
    finalize_stats<<<1,256>>>(p_stats, 128, 1.f/N, p_mean, p_rstd);

    // ---- 3 GCN layers (stats for next layer fused into gather) ----
    for (int l = 0; l < 3; l++) {
        gemm128<<<NB,256,GEMM_SMEM>>>(p_h, nullptr,0,0, p_mean, p_rstd,
                                      conv_Ws + l*128*128, p_t, nullptr, N, 0);
        if (l < 2) {
            cudaMemsetAsync(p_stats, 0, 1024);
            gather128<<<GB,256>>>(p_t, p_rowptr, p_eid, esrc, p_disU,
                                  conv_bs + l*128, p_h, p_stats, N, 1);
            finalize_stats<<<1,256>>>(p_stats, 128, 1.f/N, p_mean, p_rstd);
        } else {
            gather128<<<GB,256>>>(p_t, p_rowptr, p_eid, esrc, p_disU,
                                  conv_bs + l*128, p_h, nullptr, N, 1);
        }
    }

    // ---- attention ----
    proj_kernel<<<512,256>>>(p_h, eW, naW, p_epro, p_t2, N);
    edge_att_kernel<<<ET,256>>>(esrc, edst, p_epro, eb, p_eatt, p_dis0, p_dis1, E);
    rsqrt_two<<<NT,256>>>(p_dis0, p_dis1, N);
    natt_gather<<<NT,256>>>(p_t2, p_rowptr, p_eid, esrc, p_disU, nab, p_natt, N);

    // ---- XC / XO stats (one fused pass over h) ----
    cudaMemsetAsync(p_stats, 0, 2048);
    colstats2<<<512,256>>>(p_h, p_natt, N, p_stats);
    finalize_stats<<<1,256>>>(p_stats,       128, 1.f/N, p_mean,       p_rstd);
    finalize_stats<<<1,256>>>(p_stats + 256, 128, 1.f/N, p_mean + 128, p_rstd + 128);

    // ---- XC / XO branches ----
    gemm128<<<NB,256,GEMM_SMEM>>>(p_h, p_natt, 2, 0, p_mean, p_rstd, xcW,
                                  p_t, nullptr, N, 0);
    gemm128<<<NB,256,GEMM_SMEM>>>(p_h, p_natt, 2, 1, p_mean + 128, p_rstd + 128,
                                  xoW, p_t2b, nullptr, N, 0);
    gather2<<<GB,256>>>(p_t, p_t2b, p_rowptr, p_eid, esrc, p_dis0, p_dis1,
                        p_eatt, p_s, p_s2, N);
    pool_both<<<G,256>>>(p_s, p_s2, xcb, xob, p_gstart, p_cat);

    // ---- heads (fused) ----
    // layer-1 stats: 256 cols of cat serve C (0:128), O (128:256), CO (0:256)
    head_stats<<<256,128>>>(p_cat, 256, G, p_mean, p_rstd);
    dim3 hg1(G, 3);
    head_gemm1<<<hg1,128>>>(p_cat, p_mean, p_rstd, cW1, cb1, oW1, ob1,
                            coW1, cob1, p_hd);
    head_stats3<<<384,128>>>(p_hd, G, p_mean, p_rstd);
    dim3 hg2(G, 3);
    head_gemm2_lsm<<<hg2,128>>>(p_hd, p_mean, p_rstd, cW2, cb2, oW2, ob2,
                                coW2, cob2, out);
}

// round 7
// speedup vs baseline: 1.5130x; 1.0148x over previous
#include <cuda_runtime.h>
#include <math.h>

#define Nn 50000
#define Ee 400000
#define Hh 128
#define Gg 512
#define COUT 10

typedef unsigned long long u64;

static constexpr float EPSBN = 1e-5f;
static constexpr float BNB   = 1e-4f;

// ---------------- scratch (static device allocations) ----------------
__device__ float g_h[Nn*Hh];
__device__ float g_t[Nn*Hh];
__device__ float g_t2b[Nn*Hh];
__device__ float g_s[Nn*Hh];
__device__ float g_s2[Nn*Hh];
__device__ float g_stats[512];
__device__ float g_mean[512];
__device__ float g_rstd[512];
__device__ float g_disU[Nn];
__device__ float2 g_deg01[Nn];
__device__ float g_epro[Nn*4];
__device__ float g_t2[Nn*2];
__device__ float g_natt[Nn*2];
__device__ float g_eperm[Ee*2];    // eatt in CSR-permuted order
__device__ int   g_gstart[Gg+1];
__device__ float g_cat[Gg*256];
__device__ float g_hd[3*Gg*128];
// CSR by destination
__device__ int g_cnt[Nn];
__device__ int g_incl[Nn];
__device__ int g_bsum[64];
__device__ int g_rowptr[Nn+1];
__device__ int g_cursor[Nn];
__device__ int g_csrc[Ee];         // src node id, permuted by dst
__device__ int g_pos[Ee];          // edge e -> CSR position p

// ---------------- small utility kernels ----------------
__global__ void init_kernel(float* disU, float2* deg01, int* cnt, int n) {
    int i = blockIdx.x*blockDim.x + threadIdx.x;
    if (i < n) { disU[i] = 1.f; deg01[i] = make_float2(1.f, 1.f); cnt[i] = 0; }
}

__global__ void deg_hist(const int* __restrict__ src, const int* __restrict__ dst,
                         float* degU, int* cnt, int E) {
    int i = blockIdx.x*blockDim.x + threadIdx.x;
    if (i < E) {
        atomicAdd(&degU[src[i]], 1.0f);
        atomicAdd(&cnt[dst[i]], 1);
    }
}

__global__ void rsqrt_arr(float* p, int n) {
    int i = blockIdx.x*blockDim.x + threadIdx.x;
    if (i < n) p[i] = rsqrtf(p[i]);
}

__global__ void gstart_kernel(const int* __restrict__ batch, int* gstart, int n, int G) {
    int i = blockIdx.x*blockDim.x + threadIdx.x;
    if (i >= n) return;
    int b  = batch[i];
    int pb = (i == 0) ? -1 : batch[i-1];
    for (int g = pb+1; g <= b; g++) gstart[g] = i;
    if (i == n-1) {
        for (int g = b+1; g <= G; g++) gstart[g] = n;
    }
}

// ---------------- CSR build ----------------
__global__ void scan_block(const int* __restrict__ cnt, int* incl, int* bsum, int n) {
    __shared__ int sm[1024];
    int i = blockIdx.x*1024 + threadIdx.x;
    sm[threadIdx.x] = (i < n) ? cnt[i] : 0;
    __syncthreads();
    for (int off = 1; off < 1024; off <<= 1) {
        int t = (threadIdx.x >= off) ? sm[threadIdx.x - off] : 0;
        __syncthreads();
        sm[threadIdx.x] += t;
        __syncthreads();
    }
    if (i < n) incl[i] = sm[threadIdx.x];
    if (threadIdx.x == 1023) bsum[blockIdx.x] = sm[1023];
}

__global__ void scan_tops(int* bsum, int nb) {
    if (threadIdx.x == 0 && blockIdx.x == 0) {
        int s = 0;
        for (int i = 0; i < nb; i++) { s += bsum[i]; bsum[i] = s; }
    }
}

// rowptr/cursor + fused rsqrt of unit degree
__global__ void make_rowptr(const int* __restrict__ cnt, const int* __restrict__ incl,
                            const int* __restrict__ bsum,
                            int* rowptr, int* cursor, float* disU, int n, int E) {
    int i = blockIdx.x*blockDim.x + threadIdx.x;
    if (i < n) {
        int b = i >> 10;
        int ex = incl[i] - cnt[i] + ((b > 0) ? bsum[b-1] : 0);
        rowptr[i] = ex;
        cursor[i] = ex;
        disU[i] = rsqrtf(disU[i]);
    }
    if (i == 0) rowptr[n] = E;
}

__global__ void fill_csr(const int* __restrict__ src, const int* __restrict__ dst,
                         int* cursor, int* csrc, int* pos, int E) {
    int e = blockIdx.x*blockDim.x + threadIdx.x;
    if (e < E) {
        int p = atomicAdd(&cursor[dst[e]], 1);
        csrc[p] = src[e];
        pos[e] = p;
    }
}

// ---------------- BatchNorm stats ----------------
__global__ void colstats(const float* __restrict__ A, int n, float* sums) {
    long total  = (long)n * 128;
    long stride = (long)gridDim.x * blockDim.x;
    long i0     = (long)blockIdx.x*blockDim.x + threadIdx.x;
    if (i0 >= total) return;
    int c = (int)(i0 % 128);
    float s0 = 0.f, s1 = 0.f;
    for (long i = i0; i < total; i += stride) {
        int r = (int)(i / 128);
        float v = A[(long)r*128 + c];
        s0 += v; s1 += v*v;
    }
    atomicAdd(&sums[c], s0);
    atomicAdd(&sums[128+c], s1);
}

__global__ void colstats2(const float* __restrict__ A, const float* __restrict__ natt,
                          int n, float* sums) {
    long total  = (long)n * 128;
    long stride = (long)gridDim.x * blockDim.x;
    long i0     = (long)blockIdx.x*blockDim.x + threadIdx.x;
    if (i0 >= total) return;
    int c = (int)(i0 % 128);
    float s00=0.f, s01=0.f, s10=0.f, s11=0.f;
    for (long i = i0; i < total; i += stride) {
        int r = (int)(i / 128);
        float v = A[(long)r*128 + c];
        float v0 = v * natt[r*2+0];
        float v1 = v * natt[r*2+1];
        s00 += v0; s01 += v0*v0;
        s10 += v1; s11 += v1*v1;
    }
    atomicAdd(&sums[c], s00);
    atomicAdd(&sums[128+c], s01);
    atomicAdd(&sums[256+c], s10);
    atomicAdd(&sums[384+c], s11);
}

__global__ void finalize_stats(const float* __restrict__ sums, int C, float inv_n,
                               float* mean, float* rstd) {
    int c = threadIdx.x + blockIdx.x*blockDim.x;
    if (c < C) {
        float m = sums[c]*inv_n;
        float var = sums[C+c]*inv_n - m*m;
        mean[c] = m;
        rstd[c] = rsqrtf(var + EPSBN);
    }
}

__global__ void head_stats(const float* __restrict__ A, int lda, int n,
                           float* mean, float* rstd) {
    __shared__ float s0s[4], s1s[4];
    int c = blockIdx.x;
    int lane = threadIdx.x & 31, warp = threadIdx.x >> 5;
    float s0 = 0.f, s1 = 0.f;
    for (int r = threadIdx.x; r < n; r += blockDim.x) {
        float v = A[r*lda + c];
        s0 += v; s1 += v*v;
    }
    #pragma unroll
    for (int o = 16; o; o >>= 1) {
        s0 += __shfl_xor_sync(0xffffffffu, s0, o);
        s1 += __shfl_xor_sync(0xffffffffu, s1, o);
    }
    if (lane == 0) { s0s[warp] = s0; s1s[warp] = s1; }
    __syncthreads();
    if (threadIdx.x == 0) {
        float t0 = 0.f, t1 = 0.f;
        for (int w = 0; w < 4; w++) { t0 += s0s[w]; t1 += s1s[w]; }
        float m = t0 / n;
        float var = t1 / n - m*m;
        mean[c] = m;
        rstd[c] = rsqrtf(var + EPSBN);
    }
}

__global__ void head_stats3(const float* __restrict__ hd, int n,
                            float* mean, float* rstd) {
    __shared__ float s0s[4], s1s[4];
    int cg = blockIdx.x;
    int head = cg >> 7, c = cg & 127;
    const float* A = hd + head*Gg*128;
    int lane = threadIdx.x & 31, warp = threadIdx.x >> 5;
    float s0 = 0.f, s1 = 0.f;
    for (int r = threadIdx.x; r < n; r += blockDim.x) {
        float v = A[r*128 + c];
        s0 += v; s1 += v*v;
    }
    #pragma unroll
    for (int o = 16; o; o >>= 1) {
        s0 += __shfl_xor_sync(0xffffffffu, s0, o);
        s1 += __shfl_xor_sync(0xffffffffu, s1, o);
    }
    if (lane == 0) { s0s[warp] = s0; s1s[warp] = s1; }
    __syncthreads();
    if (threadIdx.x == 0) {
        float t0 = 0.f, t1 = 0.f;
        for (int w = 0; w < 4; w++) { t0 += s0s[w]; t1 += s1s[w]; }
        float m = t0 / n;
        float var = t1 / n - m*m;
        mean[cg] = m;
        rstd[cg] = rsqrtf(var + EPSBN);
    }
}

// ---------------- big GEMM (packed f32x2 FMA, BM=64) ----------------
static constexpr int GEMM_SMEM = (64*128 + 128*128) * 4;

__global__ __launch_bounds__(256) void gemm128(
    const float* __restrict__ A,
    const float* __restrict__ rs, int rss, int rso,
    const float* __restrict__ mean, const float* __restrict__ rstd,
    const float* __restrict__ W,
    float* __restrict__ out,
    float* __restrict__ sums,
    int n, int act)
{
    extern __shared__ float sm[];
    float* As = sm;               // [64][128]
    float* Ws = sm + 64*128;      // [128][128]
    int tid  = threadIdx.x;
    int row0 = blockIdx.x * 64;

    const float4* Wg = (const float4*)W;
    float4* Ws4 = (float4*)Ws;
    #pragma unroll 4
    for (int i = tid; i < 128*32; i += 256) Ws4[i] = Wg[i];

    #pragma unroll 2
    for (int i = tid; i < 64*32; i += 256) {
        int r = i >> 5, cq = i & 31;
        int gr = row0 + r;
        float4 v = make_float4(0.f,0.f,0.f,0.f);
        if (gr < n) {
            v = ((const float4*)A)[gr*32 + cq];
            float sc = rs ? rs[gr*rss + rso] : 1.f;
            int c = cq*4;
            v.x = (v.x*sc - mean[c+0])*rstd[c+0] + BNB;
            v.y = (v.y*sc - mean[c+1])*rstd[c+1] + BNB;
            v.z = (v.z*sc - mean[c+2])*rstd[c+2] + BNB;
            v.w = (v.w*sc - mean[c+3])*rstd[c+3] + BNB;
        }
        ((float4*)As)[i] = v;
    }
    __syncthreads();

    int tc = tid & 15, tr = tid >> 4;
    int r0 = tr*4;
    int c0 = tc*4, c1 = 64 + tc*4;

    u64 accp[4][4];
    #pragma unroll
    for (int i = 0; i < 4; i++)
        #pragma unroll
        for (int j = 0; j < 4; j++) accp[i][j] = 0ull;

    for (int k = 0; k < 128; k += 4) {
        float4 a4[4];
        #pragma unroll
        for (int i = 0; i < 4; i++)
            a4[i] = *(const float4*)&As[(r0+i)*128 + k];
        #pragma unroll
        for (int kk = 0; kk < 4; kk++) {
            ulonglong2 w01 = *(const ulonglong2*)&Ws[(k+kk)*128 + c0];
            ulonglong2 w23 = *(const ulonglong2*)&Ws[(k+kk)*128 + c1];
            u64 wp0 = w01.x, wp1 = w01.y, wp2 = w23.x, wp3 = w23.y;
            #pragma unroll
            for (int i = 0; i < 4; i++) {
                float a = ((const float*)&a4[i])[kk];
                unsigned int ai = __float_as_uint(a);
                u64 ap;
                asm("mov.b64 %0, {%1, %1};" : "=l"(ap) : "r"(ai));
                asm("fma.rn.f32x2 %0, %1, %2, %0;" : "+l"(accp[i][0]) : "l"(ap), "l"(wp0));
                asm("fma.rn.f32x2 %0, %1, %2, %0;" : "+l"(accp[i][1]) : "l"(ap), "l"(wp1));
                asm("fma.rn.f32x2 %0, %1, %2, %0;" : "+l"(accp[i][2]) : "l"(ap), "l"(wp2));
                asm("fma.rn.f32x2 %0, %1, %2, %0;" : "+l"(accp[i][3]) : "l"(ap), "l"(wp3));
            }
        }
    }

    float t0[8], t1[8];
    #pragma unroll
    for (int j = 0; j < 8; j++) { t0[j] = 0.f; t1[j] = 0.f; }

    float4* O4 = (float4*)out;
    #pragma unroll
    for (int i = 0; i < 4; i++) {
        int gr = row0 + r0 + i;
        if (gr < n) {
            float o[8];
            #pragma unroll
            for (int j = 0; j < 4; j++) {
                unsigned int lo, hi;
                asm("mov.b64 {%0, %1}, %2;" : "=r"(lo), "=r"(hi) : "l"(accp[i][j]));
                o[2*j]   = __uint_as_float(lo);
                o[2*j+1] = __uint_as_float(hi);
            }
            if (act == 1) {
                #pragma unroll
                for (int j = 0; j < 8; j++) o[j] = fmaxf(o[j], 0.f);
            }
            if (sums) {
                #pragma unroll
                for (int j = 0; j < 8; j++) { t0[j] += o[j]; t1[j] += o[j]*o[j]; }
            }
            O4[gr*32 + tc]      = make_float4(o[0], o[1], o[2], o[3]);
            O4[gr*32 + 16 + tc] = make_float4(o[4], o[5], o[6], o[7]);
        }
    }

    if (sums) {
        __syncthreads();
        float* ss = sm;
        ss[tid] = 0.f;
        __syncthreads();
        #pragma unroll
        for (int j = 0; j < 4; j++) {
            atomicAdd(&ss[c0+j],     t0[j]);   atomicAdd(&ss[128+c0+j], t1[j]);
            atomicAdd(&ss[c1+j],     t0[4+j]); atomicAdd(&ss[128+c1+j], t1[4+j]);
        }
        __syncthreads();
        atomicAdd(&sums[tid], ss[tid]);
    }
}

// ---------------- CSR gather conv ----------------
// optional: column stats (sums) OR fused attention projections (eWg/naWg -> epro/t2)
__global__ __launch_bounds__(256) void gather128(
    const float* __restrict__ t,
    const int* __restrict__ rowptr, const int* __restrict__ csrc,
    const float* __restrict__ dis,
    const float* __restrict__ bias,
    float* __restrict__ out, float* __restrict__ sums,
    const float* __restrict__ eWg, const float* __restrict__ naWg,
    float* __restrict__ epro, float* __restrict__ t2,
    int n, int act)
{
    __shared__ float sEW[512];
    __shared__ float sNA[256];
    if (eWg) {
        for (int i = threadIdx.x; i < 512; i += 256) sEW[i] = eWg[i];
        for (int i = threadIdx.x; i < 256; i += 256) sNA[i] = naWg[i];
        __syncthreads();
    }
    int lane = threadIdx.x & 31;
    int w0 = (blockIdx.x*blockDim.x + threadIdx.x) >> 5;
    int nw = (gridDim.x*blockDim.x) >> 5;
    float4 bb = bias ? ((const float4*)bias)[lane] : make_float4(0.f,0.f,0.f,0.f);
    float ls0[4] = {0.f,0.f,0.f,0.f}, ls1[4] = {0.f,0.f,0.f,0.f};

    for (int v = w0; v < n; v += nw) {
        float dv = dis[v];
        float4 acc = ((const float4*)t)[v*32 + lane];
        float d2 = dv*dv;
        acc.x *= d2; acc.y *= d2; acc.z *= d2; acc.w *= d2;
        int st = rowptr[v], en = rowptr[v+1];
        for (int p = st; p < en; p++) {
            int s = __ldg(&csrc[p]);
            float w = __ldg(&dis[s]) * dv;
            float4 x = ((const float4*)t)[s*32 + lane];
            acc.x += w*x.x; acc.y += w*x.y; acc.z += w*x.z; acc.w += w*x.w;
        }
        acc.x += bb.x; acc.y += bb.y; acc.z += bb.z; acc.w += bb.w;
        if (act == 1) {
            acc.x = fmaxf(acc.x, 0.f); acc.y = fmaxf(acc.y, 0.f);
            acc.z = fmaxf(acc.z, 0.f); acc.w = fmaxf(acc.w, 0.f);
        }
        if (sums) {
            ls0[0]+=acc.x; ls1[0]+=acc.x*acc.x;
            ls0[1]+=acc.y; ls1[1]+=acc.y*acc.y;
            ls0[2]+=acc.z; ls1[2]+=acc.z*acc.z;
            ls0[3]+=acc.w; ls1[3]+=acc.w*acc.w;
        }
        ((float4*)out)[v*32 + lane] = acc;

        if (eWg) {
            // fused attention projections off the freshly computed h row
            float hx[4] = {acc.x, acc.y, acc.z, acc.w};
            float p0=0,p1=0,q0=0,q1=0,u0=0,u1=0;
            #pragma unroll
            for (int i = 0; i < 4; i++) {
                int k = lane*4 + i; float xv = hx[i];
                p0 += xv*sEW[k*2+0];        p1 += xv*sEW[k*2+1];
                q0 += xv*sEW[(128+k)*2+0];  q1 += xv*sEW[(128+k)*2+1];
                u0 += xv*sNA[k*2+0];        u1 += xv*sNA[k*2+1];
            }
            #pragma unroll
            for (int o = 16; o; o >>= 1) {
                p0 += __shfl_xor_sync(0xffffffffu, p0, o);
                p1 += __shfl_xor_sync(0xffffffffu, p1, o);
                q0 += __shfl_xor_sync(0xffffffffu, q0, o);
                q1 += __shfl_xor_sync(0xffffffffu, q1, o);
                u0 += __shfl_xor_sync(0xffffffffu, u0, o);
                u1 += __shfl_xor_sync(0xffffffffu, u1, o);
            }
            if (lane == 0) {
                epro[v*4+0]=p0; epro[v*4+1]=p1; epro[v*4+2]=q0; epro[v*4+3]=q1;
                t2[v*2+0]=u0; t2[v*2+1]=u1;
            }
        }
    }

    if (sums) {
        __shared__ float ss[256];
        ss[threadIdx.x] = 0.f;
        __syncthreads();
        #pragma unroll
        for (int j = 0; j < 4; j++) {
            atomicAdd(&ss[lane*4+j],     ls0[j]);
            atomicAdd(&ss[128+lane*4+j], ls1[j]);
        }
        __syncthreads();
        atomicAdd(&sums[threadIdx.x], ss[threadIdx.x]);
    }
}

// fused XC+XO gather (edge-weighted via permuted eatt)
__global__ __launch_bounds__(256) void gather2(
    const float* __restrict__ tc_, const float* __restrict__ to_,
    const int* __restrict__ rowptr, const int* __restrict__ csrc,
    const float2* __restrict__ dis01,
    const float* __restrict__ eperm,
    float* __restrict__ sc_, float* __restrict__ so_, int n)
{
    int lane = threadIdx.x & 31;
    int w0 = (blockIdx.x*blockDim.x + threadIdx.x) >> 5;
    int nw = (gridDim.x*blockDim.x) >> 5;
    for (int v = w0; v < n; v += nw) {
        float2 dv = dis01[v];
        float4 ac = ((const float4*)tc_)[v*32 + lane];
        float4 ao = ((const float4*)to_)[v*32 + lane];
        float d02 = dv.x*dv.x, d12 = dv.y*dv.y;
        ac.x *= d02; ac.y *= d02; ac.z *= d02; ac.w *= d02;
        ao.x *= d12; ao.y *= d12; ao.z *= d12; ao.w *= d12;
        int st = rowptr[v], en = rowptr[v+1];
        for (int p = st; p < en; p++) {
            int s = __ldg(&csrc[p]);
            float2 ea = __ldg((const float2*)&eperm[p*2]);
            float2 ds = __ldg(&dis01[s]);
            float wc = ds.x * dv.x * ea.x;
            float wo = ds.y * dv.y * ea.y;
            float4 xc = ((const float4*)tc_)[s*32 + lane];
            float4 xo = ((const float4*)to_)[s*32 + lane];
            ac.x += wc*xc.x; ac.y += wc*xc.y; ac.z += wc*xc.z; ac.w += wc*xc.w;
            ao.x += wo*xo.x; ao.y += wo*xo.y; ao.z += wo*xo.z; ao.w += wo*xo.w;
        }
        ((float4*)sc_)[v*32 + lane] = ac;
        ((float4*)so_)[v*32 + lane] = ao;
    }
}

// ---------------- attention ----------------
__global__ void edge_att_kernel(const int* __restrict__ src, const int* __restrict__ dst,
                                const int* __restrict__ pos,
                                const float* __restrict__ epro, const float* __restrict__ eb,
                                float* __restrict__ eperm, float2* __restrict__ deg01, int E) {
    int e = blockIdx.x*blockDim.x + threadIdx.x;
    if (e >= E) return;
    int s = src[e], d = dst[e];
    float2 ps = *(const float2*)&epro[s*4];
    float2 qd = *(const float2*)&epro[d*4+2];
    float l0 = ps.x + qd.x + eb[0];
    float l1 = ps.y + qd.y + eb[1];
    float m = fmaxf(l0, l1);
    float e0 = expf(l0 - m), e1 = expf(l1 - m);
    float inv = 1.f/(e0+e1);
    float a0 = e0*inv, a1 = e1*inv;
    int p = pos[e];
    *(float2*)&eperm[p*2] = make_float2(a0, a1);
    asm volatile("red.global.add.v2.f32 [%0], {%1, %2};"
                 :: "l"(&deg01[s]), "f"(a0), "f"(a1) : "memory");
}

__global__ void natt_gather(const float* __restrict__ t2,
                            const int* __restrict__ rowptr, const int* __restrict__ csrc,
                            const float* __restrict__ disU,
                            const float* __restrict__ nab,
                            float* __restrict__ natt, int n) {
    int v = blockIdx.x*blockDim.x + threadIdx.x;
    if (v >= n) return;
    float dv = disU[v];
    float d2 = dv*dv;
    float a0 = t2[v*2+0]*d2, a1 = t2[v*2+1]*d2;
    int st = rowptr[v], en = rowptr[v+1];
    for (int p = st; p < en; p++) {
        int s = __ldg(&csrc[p]);
        float w = __ldg(&disU[s])*dv;
        float2 ts = __ldg((const float2*)&t2[s*2]);
        a0 += w*ts.x;
        a1 += w*ts.y;
    }
    a0 += nab[0]; a1 += nab[1];
    float m = fmaxf(a0, a1);
    float e0 = expf(a0 - m), e1 = expf(a1 - m);
    float inv = 1.f/(e0+e1);
    natt[v*2+0] = e0*inv; natt[v*2+1] = e1*inv;
}

// fused pooling of both branches
__global__ void pool_both(const float* __restrict__ sc_, const float* __restrict__ so_,
                          const float* __restrict__ xcb, const float* __restrict__ xob,
                          const int* __restrict__ gstart, float* __restrict__ cat) {
    int g = blockIdx.x, c = threadIdx.x;
    int st = gstart[g], en = gstart[g+1];
    const float* s = (c < 128) ? sc_ : so_;
    int cc = c & 127;
    float bc = (c < 128) ? xcb[cc] : xob[cc];
    float acc = 0.f;
    for (int v = st; v < en; v++) {
        float z = s[v*128 + cc] + bc;
        acc += (z > 0.f) ? z : expm1f(z);
    }
    cat[g*256 + c] = acc;
}

// ---------------- fused heads ----------------
__global__ void head_gemm1(const float* __restrict__ cat,
                           const float* __restrict__ mean, const float* __restrict__ rstd,
                           const float* __restrict__ cW1, const float* __restrict__ cb1,
                           const float* __restrict__ oW1, const float* __restrict__ ob1,
                           const float* __restrict__ coW1, const float* __restrict__ cob1,
                           float* __restrict__ hd) {
    __shared__ float a[256];
    int r = blockIdx.x, head = blockIdx.y;
    for (int k = threadIdx.x; k < 256; k += 128)
        a[k] = (cat[r*256 + k] - mean[k]) * rstd[k] + BNB;
    __syncthreads();
    const float* W; const float* b; int K, koff, act;
    if (head == 0)      { W = cW1;  b = cb1;  K = 128; koff = 0;   act = 1; }
    else if (head == 1) { W = oW1;  b = ob1;  K = 128; koff = 128; act = 1; }
    else                { W = coW1; b = cob1; K = 256; koff = 0;   act = 2; }
    int c = threadIdx.x;
    float acc = b[c];
    for (int k = 0; k < K; k++) acc += a[koff + k] * W[k*128 + c];
    if (act == 1) acc = fmaxf(acc, 0.f);
    else {
        acc = (acc > 0.f) ? acc : expm1f(acc);
        acc = (acc > 0.f) ? acc : expm1f(acc);
    }
    hd[(head*Gg + r)*128 + c] = acc;
}

__global__ void head_gemm2_lsm(const float* __restrict__ hd,
                               const float* __restrict__ mean, const float* __restrict__ rstd,
                               const float* __restrict__ cW2, const float* __restrict__ cb2,
                               const float* __restrict__ oW2, const float* __restrict__ ob2,
                               const float* __restrict__ coW2, const float* __restrict__ cob2,
                               float* __restrict__ out) {
    __shared__ float a[128];
    __shared__ float lg[COUT];
    int r = blockIdx.x, head = blockIdx.y;
    int k = threadIdx.x;
    a[k] = (hd[(head*Gg + r)*128 + k] - mean[head*128 + k]) * rstd[head*128 + k] + BNB;
    __syncthreads();
    const float* W = (head == 0) ? cW2 : (head == 1) ? oW2 : coW2;
    const float* b = (head == 0) ? cb2 : (head == 1) ? ob2 : cob2;
    if (k < COUT) {
        float acc = b[k];
        for (int kk = 0; kk < 128; kk++) acc += a[kk] * W[kk*COUT + k];
        lg[k] = acc;
    }
    __syncthreads();
    if (k < COUT) {
        float m = -1e30f;
        #pragma unroll
        for (int i = 0; i < COUT; i++) m = fmaxf(m, lg[i]);
        float s = 0.f;
        #pragma unroll
        for (int i = 0; i < COUT; i++) s += expf(lg[i] - m);
        out[head*Gg*COUT + r*COUT + k] = lg[k] - m - logf(s);
    }
}

// ---------------- host orchestration ----------------
extern "C" void kernel_launch(void* const* d_in, const int* in_sizes, int n_in,
                              void* d_out, int out_size) {
    const float* x      = (const float*)d_in[0];
    const float* W_feat = (const float*)d_in[1];
    const float* conv_Ws= (const float*)d_in[2];
    const float* conv_bs= (const float*)d_in[3];
    const float* eW     = (const float*)d_in[4];
    const float* eb     = (const float*)d_in[5];
    const float* naW    = (const float*)d_in[6];
    const float* nab    = (const float*)d_in[7];
    const float* xcW    = (const float*)d_in[8];
    const float* xcb    = (const float*)d_in[9];
    const float* xoW    = (const float*)d_in[10];
    const float* xob    = (const float*)d_in[11];
    const float* cW1    = (const float*)d_in[12];
    const float* cb1    = (const float*)d_in[13];
    const float* cW2    = (const float*)d_in[14];
    const float* cb2    = (const float*)d_in[15];
    const float* oW1    = (const float*)d_in[16];
    const float* ob1    = (const float*)d_in[17];
    const float* oW2    = (const float*)d_in[18];
    const float* ob2    = (const float*)d_in[19];
    const float* coW1   = (const float*)d_in[20];
    const float* cob1   = (const float*)d_in[21];
    const float* coW2   = (const float*)d_in[22];
    const float* cob2   = (const float*)d_in[23];
    const int* esrc     = (const int*)d_in[24];
    const int* edst     = (const int*)d_in[25];
    const int* batch    = (const int*)d_in[26];
    float* out = (float*)d_out;

    float *p_h,*p_t,*p_t2b,*p_s,*p_s2,*p_stats,*p_mean,*p_rstd,*p_disU;
    float *p_epro,*p_t2,*p_natt,*p_eperm,*p_cat,*p_hd;
    float2* p_deg01;
    int *p_gstart,*p_cnt,*p_incl,*p_bsum,*p_rowptr,*p_cursor,*p_csrc,*p_pos;
    cudaGetSymbolAddress((void**)&p_h, g_h);
    cudaGetSymbolAddress((void**)&p_t, g_t);
    cudaGetSymbolAddress((void**)&p_t2b, g_t2b);
    cudaGetSymbolAddress((void**)&p_s, g_s);
    cudaGetSymbolAddress((void**)&p_s2, g_s2);
    cudaGetSymbolAddress((void**)&p_stats, g_stats);
    cudaGetSymbolAddress((void**)&p_mean, g_mean);
    cudaGetSymbolAddress((void**)&p_rstd, g_rstd);
    cudaGetSymbolAddress((void**)&p_disU, g_disU);
    cudaGetSymbolAddress((void**)&p_deg01, g_deg01);
    cudaGetSymbolAddress((void**)&p_epro, g_epro);
    cudaGetSymbolAddress((void**)&p_t2, g_t2);
    cudaGetSymbolAddress((void**)&p_natt, g_natt);
    cudaGetSymbolAddress((void**)&p_eperm, g_eperm);
    cudaGetSymbolAddress((void**)&p_cat, g_cat);
    cudaGetSymbolAddress((void**)&p_hd, g_hd);
    cudaGetSymbolAddress((void**)&p_gstart, g_gstart);
    cudaGetSymbolAddress((void**)&p_cnt, g_cnt);
    cudaGetSymbolAddress((void**)&p_incl, g_incl);
    cudaGetSymbolAddress((void**)&p_bsum, g_bsum);
    cudaGetSymbolAddress((void**)&p_rowptr, g_rowptr);
    cudaGetSymbolAddress((void**)&p_cursor, g_cursor);
    cudaGetSymbolAddress((void**)&p_csrc, g_csrc);
    cudaGetSymbolAddress((void**)&p_pos, g_pos);

    cudaFuncSetAttribute(gemm128, cudaFuncAttributeMaxDynamicSharedMemorySize, GEMM_SMEM);

    const int N = Nn, E = Ee, G = Gg;
    const int NB = (N + 63) / 64;
    const int NT = (N + 255) / 256;
    const int ET = (E + 255) / 256;
    const int GB = 1024;
    const int NSCAN = (N + 1023) / 1024;

    // ---- CSR build + degrees + group starts ----
    init_kernel<<<NT,256>>>(p_disU, p_deg01, p_cnt, N);
    deg_hist<<<ET,256>>>(esrc, edst, p_disU, p_cnt, E);
    scan_block<<<NSCAN,1024>>>(p_cnt, p_incl, p_bsum, N);
    scan_tops<<<1,32>>>(p_bsum, NSCAN);
    make_rowptr<<<NT,256>>>(p_cnt, p_incl, p_bsum, p_rowptr, p_cursor, p_disU, N, E);
    fill_csr<<<ET,256>>>(esrc, edst, p_cursor, p_csrc, p_pos, E);
    gstart_kernel<<<NT,256>>>(batch, p_gstart, N, G);

    // ---- h = relu(BN(x) @ W_feat), h-stats fused into epilogue ----
    cudaMemsetAsync(p_stats, 0, 1024);
    colstats<<<512,256>>>(x, N, p_stats);
    finalize_stats<<<1,256>>>(p_stats, 128, 1.f/N, p_mean, p_rstd);
    cudaMemsetAsync(p_stats, 0, 1024);
    gemm128<<<NB,256,GEMM_SMEM>>>(x, nullptr,0,0, p_mean, p_rstd, W_feat,
                                  p_h, p_stats, N, 1);
    finalize_stats<<<1,256>>>(p_stats, 128, 1.f/N, p_mean, p_rstd);

    // ---- 3 GCN layers ----
    for (int l = 0; l < 3; l++) {
        gemm128<<<NB,256,GEMM_SMEM>>>(p_h, nullptr,0,0, p_mean, p_rstd,
                                      conv_Ws + l*128*128, p_t, nullptr, N, 0);
        if (l < 2) {
            cudaMemsetAsync(p_stats, 0, 1024);
            gather128<<<GB,256>>>(p_t, p_rowptr, p_csrc, p_disU,
                                  conv_bs + l*128, p_h, p_stats,
                                  nullptr, nullptr, nullptr, nullptr, N, 1);
            finalize_stats<<<1,256>>>(p_stats, 128, 1.f/N, p_mean, p_rstd);
        } else {
            // last layer: fuse attention projections into the gather epilogue
            gather128<<<GB,256>>>(p_t, p_rowptr, p_csrc, p_disU,
                                  conv_bs + l*128, p_h, nullptr,
                                  eW, naW, p_epro, p_t2, N, 1);
        }
    }

    // ---- attention ----
    edge_att_kernel<<<ET,256>>>(esrc, edst, p_pos, p_epro, eb, p_eperm, p_deg01, E);
    rsqrt_arr<<<(2*N+255)/256,256>>>((float*)p_deg01, 2*N);
    natt_gather<<<NT,256>>>(p_t2, p_rowptr, p_csrc, p_disU, nab, p_natt, N);

    // ---- XC / XO stats (one fused pass over h) ----
    cudaMemsetAsync(p_stats, 0, 2048);
    colstats2<<<512,256>>>(p_h, p_natt, N, p_stats);
    finalize_stats<<<1,256>>>(p_stats,       128, 1.f/N, p_mean,       p_rstd);
    finalize_stats<<<1,256>>>(p_stats + 256, 128, 1.f/N, p_mean + 128, p_rstd + 128);

    // ---- XC / XO branches ----
    gemm128<<<NB,256,GEMM_SMEM>>>(p_h, p_natt, 2, 0, p_mean, p_rstd, xcW,
                                  p_t, nullptr, N, 0);
    gemm128<<<NB,256,GEMM_SMEM>>>(p_h, p_natt, 2, 1, p_mean + 128, p_rstd + 128,
                                  xoW, p_t2b, nullptr, N, 0);
    gather2<<<GB,256>>>(p_t, p_t2b, p_rowptr, p_csrc, p_deg01,
                        p_eperm, p_s, p_s2, N);
    pool_both<<<G,256>>>(p_s, p_s2, xcb, xob, p_gstart, p_cat);

    // ---- heads (fused) ----
    head_stats<<<256,128>>>(p_cat, 256, G, p_mean, p_rstd);
    dim3 hg1(G, 3);
    head_gemm1<<<hg1,128>>>(p_cat, p_mean, p_rstd, cW1, cb1, oW1, ob1,
                            coW1, cob1, p_hd);
    head_stats3<<<384,128>>>(p_hd, G, p_mean, p_rstd);
    dim3 hg2(G, 3);
    head_gemm2_lsm<<<hg2,128>>>(p_hd, p_mean, p_rstd, cW2, cb2, oW2, ob2,
                                coW2, cob2, out);
}

// round 8
// speedup vs baseline: 1.5246x; 1.0076x over previous
#include <cuda_runtime.h>
#include <math.h>

#define Nn 50000
#define Ee 400000
#define Hh 128
#define Gg 512
#define COUT 10

typedef unsigned long long u64;

static constexpr float EPSBN = 1e-5f;
static constexpr float BNB   = 1e-4f;

// ---------------- scratch (static device allocations) ----------------
__device__ float g_h[Nn*Hh];
__device__ float g_t[Nn*Hh];
__device__ float g_t2b[Nn*Hh];
__device__ float g_s[Nn*Hh];
__device__ float g_s2[Nn*Hh];
__device__ float g_stats[512];
__device__ float g_mean[512];
__device__ float g_rstd[512];
__device__ float g_disU[Nn];
__device__ float2 g_deg01[Nn];
__device__ float g_epro[Nn*4];
__device__ float g_t2[Nn*2];
__device__ float g_natt[Nn*2];
__device__ float g_eperm[Ee*2];
__device__ int   g_gstart[Gg+1];
__device__ float g_cat[Gg*256];
__device__ float g_hd[3*Gg*128];
// CSR by destination
__device__ int g_cnt[Nn];
__device__ int g_incl[Nn];
__device__ int g_bsum[64];
__device__ int g_rowptr[Nn+1];
__device__ int g_cursor[Nn];
__device__ int g_csrc[Ee];
__device__ int g_pos[Ee];

// ---------------- small utility kernels ----------------
__global__ void init_kernel(float* disU, float2* deg01, int* cnt, int n) {
    int i = blockIdx.x*blockDim.x + threadIdx.x;
    if (i < n) { disU[i] = 1.f; deg01[i] = make_float2(1.f, 1.f); cnt[i] = 0; }
}

__global__ void deg_hist(const int* __restrict__ src, const int* __restrict__ dst,
                         float* degU, int* cnt, int E) {
    int i = blockIdx.x*blockDim.x + threadIdx.x;
    if (i < E) {
        atomicAdd(&degU[src[i]], 1.0f);
        atomicAdd(&cnt[dst[i]], 1);
    }
}

__global__ void rsqrt_arr(float* p, int n) {
    int i = blockIdx.x*blockDim.x + threadIdx.x;
    if (i < n) p[i] = rsqrtf(p[i]);
}

__global__ void gstart_kernel(const int* __restrict__ batch, int* gstart, int n, int G) {
    int i = blockIdx.x*blockDim.x + threadIdx.x;
    if (i >= n) return;
    int b  = batch[i];
    int pb = (i == 0) ? -1 : batch[i-1];
    for (int g = pb+1; g <= b; g++) gstart[g] = i;
    if (i == n-1) {
        for (int g = b+1; g <= G; g++) gstart[g] = n;
    }
}

// ---------------- CSR build ----------------
__global__ void scan_block(const int* __restrict__ cnt, int* incl, int* bsum, int n) {
    __shared__ int sm[1024];
    int i = blockIdx.x*1024 + threadIdx.x;
    sm[threadIdx.x] = (i < n) ? cnt[i] : 0;
    __syncthreads();
    for (int off = 1; off < 1024; off <<= 1) {
        int t = (threadIdx.x >= off) ? sm[threadIdx.x - off] : 0;
        __syncthreads();
        sm[threadIdx.x] += t;
        __syncthreads();
    }
    if (i < n) incl[i] = sm[threadIdx.x];
    if (threadIdx.x == 1023) bsum[blockIdx.x] = sm[1023];
}

__global__ void scan_tops(int* bsum, int nb) {
    if (threadIdx.x == 0 && blockIdx.x == 0) {
        int s = 0;
        for (int i = 0; i < nb; i++) { s += bsum[i]; bsum[i] = s; }
    }
}

__global__ void make_rowptr(const int* __restrict__ cnt, const int* __restrict__ incl,
                            const int* __restrict__ bsum,
                            int* rowptr, int* cursor, float* disU, int n, int E) {
    int i = blockIdx.x*blockDim.x + threadIdx.x;
    if (i < n) {
        int b = i >> 10;
        int ex = incl[i] - cnt[i] + ((b > 0) ? bsum[b-1] : 0);
        rowptr[i] = ex;
        cursor[i] = ex;
        disU[i] = rsqrtf(disU[i]);
    }
    if (i == 0) rowptr[n] = E;
}

__global__ void fill_csr(const int* __restrict__ src, const int* __restrict__ dst,
                         int* cursor, int* csrc, int* pos, int E) {
    int e = blockIdx.x*blockDim.x + threadIdx.x;
    if (e < E) {
        int p = atomicAdd(&cursor[dst[e]], 1);
        csrc[p] = src[e];
        pos[e] = p;
    }
}

// ---------------- BatchNorm stats ----------------
__global__ void colstats(const float* __restrict__ A, int n, float* sums) {
    long total  = (long)n * 128;
    long stride = (long)gridDim.x * blockDim.x;
    long i0     = (long)blockIdx.x*blockDim.x + threadIdx.x;
    if (i0 >= total) return;
    int c = (int)(i0 % 128);
    float s0 = 0.f, s1 = 0.f;
    for (long i = i0; i < total; i += stride) {
        int r = (int)(i / 128);
        float v = A[(long)r*128 + c];
        s0 += v; s1 += v*v;
    }
    atomicAdd(&sums[c], s0);
    atomicAdd(&sums[128+c], s1);
}

__global__ void colstats2(const float* __restrict__ A, const float* __restrict__ natt,
                          int n, float* sums) {
    long total  = (long)n * 128;
    long stride = (long)gridDim.x * blockDim.x;
    long i0     = (long)blockIdx.x*blockDim.x + threadIdx.x;
    if (i0 >= total) return;
    int c = (int)(i0 % 128);
    float s00=0.f, s01=0.f, s10=0.f, s11=0.f;
    for (long i = i0; i < total; i += stride) {
        int r = (int)(i / 128);
        float v = A[(long)r*128 + c];
        float v0 = v * natt[r*2+0];
        float v1 = v * natt[r*2+1];
        s00 += v0; s01 += v0*v0;
        s10 += v1; s11 += v1*v1;
    }
    atomicAdd(&sums[c], s00);
    atomicAdd(&sums[128+c], s01);
    atomicAdd(&sums[256+c], s10);
    atomicAdd(&sums[384+c], s11);
}

__global__ void finalize_stats(const float* __restrict__ sums, int C, float inv_n,
                               float* mean, float* rstd) {
    int c = threadIdx.x + blockIdx.x*blockDim.x;
    if (c < C) {
        float m = sums[c]*inv_n;
        float var = sums[C+c]*inv_n - m*m;
        mean[c] = m;
        rstd[c] = rsqrtf(var + EPSBN);
    }
}

__global__ void head_stats(const float* __restrict__ A, int lda, int n,
                           float* mean, float* rstd) {
    __shared__ float s0s[4], s1s[4];
    int c = blockIdx.x;
    int lane = threadIdx.x & 31, warp = threadIdx.x >> 5;
    float s0 = 0.f, s1 = 0.f;
    for (int r = threadIdx.x; r < n; r += blockDim.x) {
        float v = A[r*lda + c];
        s0 += v; s1 += v*v;
    }
    #pragma unroll
    for (int o = 16; o; o >>= 1) {
        s0 += __shfl_xor_sync(0xffffffffu, s0, o);
        s1 += __shfl_xor_sync(0xffffffffu, s1, o);
    }
    if (lane == 0) { s0s[warp] = s0; s1s[warp] = s1; }
    __syncthreads();
    if (threadIdx.x == 0) {
        float t0 = 0.f, t1 = 0.f;
        for (int w = 0; w < 4; w++) { t0 += s0s[w]; t1 += s1s[w]; }
        float m = t0 / n;
        float var = t1 / n - m*m;
        mean[c] = m;
        rstd[c] = rsqrtf(var + EPSBN);
    }
}

__global__ void head_stats3(const float* __restrict__ hd, int n,
                            float* mean, float* rstd) {
    __shared__ float s0s[4], s1s[4];
    int cg = blockIdx.x;
    int head = cg >> 7, c = cg & 127;
    const float* A = hd + head*Gg*128;
    int lane = threadIdx.x & 31, warp = threadIdx.x >> 5;
    float s0 = 0.f, s1 = 0.f;
    for (int r = threadIdx.x; r < n; r += blockDim.x) {
        float v = A[r*128 + c];
        s0 += v; s1 += v*v;
    }
    #pragma unroll
    for (int o = 16; o; o >>= 1) {
        s0 += __shfl_xor_sync(0xffffffffu, s0, o);
        s1 += __shfl_xor_sync(0xffffffffu, s1, o);
    }
    if (lane == 0) { s0s[warp] = s0; s1s[warp] = s1; }
    __syncthreads();
    if (threadIdx.x == 0) {
        float t0 = 0.f, t1 = 0.f;
        for (int w = 0; w < 4; w++) { t0 += s0s[w]; t1 += s1s[w]; }
        float m = t0 / n;
        float var = t1 / n - m*m;
        mean[cg] = m;
        rstd[cg] = rsqrtf(var + EPSBN);
    }
}

// ---------------- big GEMM (packed f32x2 FMA, BM=64) ----------------
static constexpr int GEMM_SMEM = (64*128 + 128*128) * 4;

__global__ __launch_bounds__(256) void gemm128(
    const float* __restrict__ A,
    const float* __restrict__ rs, int rss, int rso,
    const float* __restrict__ mean, const float* __restrict__ rstd,
    const float* __restrict__ W,
    float* __restrict__ out,
    float* __restrict__ sums,
    int n, int act)
{
    extern __shared__ float sm[];
    float* As = sm;               // [64][128]
    float* Ws = sm + 64*128;      // [128][128]
    int tid  = threadIdx.x;
    int row0 = blockIdx.x * 64;

    const float4* Wg = (const float4*)W;
    float4* Ws4 = (float4*)Ws;
    #pragma unroll 4
    for (int i = tid; i < 128*32; i += 256) Ws4[i] = Wg[i];

    #pragma unroll 2
    for (int i = tid; i < 64*32; i += 256) {
        int r = i >> 5, cq = i & 31;
        int gr = row0 + r;
        float4 v = make_float4(0.f,0.f,0.f,0.f);
        if (gr < n) {
            v = ((const float4*)A)[gr*32 + cq];
            float sc = rs ? rs[gr*rss + rso] : 1.f;
            int c = cq*4;
            v.x = (v.x*sc - mean[c+0])*rstd[c+0] + BNB;
            v.y = (v.y*sc - mean[c+1])*rstd[c+1] + BNB;
            v.z = (v.z*sc - mean[c+2])*rstd[c+2] + BNB;
            v.w = (v.w*sc - mean[c+3])*rstd[c+3] + BNB;
        }
        ((float4*)As)[i] = v;
    }
    __syncthreads();

    int tc = tid & 15, tr = tid >> 4;
    int r0 = tr*4;
    int c0 = tc*4, c1 = 64 + tc*4;

    u64 accp[4][4];
    #pragma unroll
    for (int i = 0; i < 4; i++)
        #pragma unroll
        for (int j = 0; j < 4; j++) accp[i][j] = 0ull;

    for (int k = 0; k < 128; k += 4) {
        float4 a4[4];
        #pragma unroll
        for (int i = 0; i < 4; i++)
            a4[i] = *(const float4*)&As[(r0+i)*128 + k];
        #pragma unroll
        for (int kk = 0; kk < 4; kk++) {
            ulonglong2 w01 = *(const ulonglong2*)&Ws[(k+kk)*128 + c0];
            ulonglong2 w23 = *(const ulonglong2*)&Ws[(k+kk)*128 + c1];
            u64 wp0 = w01.x, wp1 = w01.y, wp2 = w23.x, wp3 = w23.y;
            #pragma unroll
            for (int i = 0; i < 4; i++) {
                float a = ((const float*)&a4[i])[kk];
                unsigned int ai = __float_as_uint(a);
                u64 ap;
                asm("mov.b64 %0, {%1, %1};" : "=l"(ap) : "r"(ai));
                asm("fma.rn.f32x2 %0, %1, %2, %0;" : "+l"(accp[i][0]) : "l"(ap), "l"(wp0));
                asm("fma.rn.f32x2 %0, %1, %2, %0;" : "+l"(accp[i][1]) : "l"(ap), "l"(wp1));
                asm("fma.rn.f32x2 %0, %1, %2, %0;" : "+l"(accp[i][2]) : "l"(ap), "l"(wp2));
                asm("fma.rn.f32x2 %0, %1, %2, %0;" : "+l"(accp[i][3]) : "l"(ap), "l"(wp3));
            }
        }
    }

    float t0[8], t1[8];
    #pragma unroll
    for (int j = 0; j < 8; j++) { t0[j] = 0.f; t1[j] = 0.f; }

    float4* O4 = (float4*)out;
    #pragma unroll
    for (int i = 0; i < 4; i++) {
        int gr = row0 + r0 + i;
        if (gr < n) {
            float o[8];
            #pragma unroll
            for (int j = 0; j < 4; j++) {
                unsigned int lo, hi;
                asm("mov.b64 {%0, %1}, %2;" : "=r"(lo), "=r"(hi) : "l"(accp[i][j]));
                o[2*j]   = __uint_as_float(lo);
                o[2*j+1] = __uint_as_float(hi);
            }
            if (act == 1) {
                #pragma unroll
                for (int j = 0; j < 8; j++) o[j] = fmaxf(o[j], 0.f);
            }
            if (sums) {
                #pragma unroll
                for (int j = 0; j < 8; j++) { t0[j] += o[j]; t1[j] += o[j]*o[j]; }
            }
            O4[gr*32 + tc]      = make_float4(o[0], o[1], o[2], o[3]);
            O4[gr*32 + 16 + tc] = make_float4(o[4], o[5], o[6], o[7]);
        }
    }

    if (sums) {
        __syncthreads();
        float* ss = sm;
        ss[tid] = 0.f;
        __syncthreads();
        #pragma unroll
        for (int j = 0; j < 4; j++) {
            atomicAdd(&ss[c0+j],     t0[j]);   atomicAdd(&ss[128+c0+j], t1[j]);
            atomicAdd(&ss[c1+j],     t0[4+j]); atomicAdd(&ss[128+c1+j], t1[4+j]);
        }
        __syncthreads();
        atomicAdd(&sums[tid], ss[tid]);
    }
}

// ---------------- CSR gather conv (MLP-4 unrolled) ----------------
__global__ __launch_bounds__(256) void gather128(
    const float* __restrict__ t,
    const int* __restrict__ rowptr, const int* __restrict__ csrc,
    const float* __restrict__ dis,
    const float* __restrict__ bias,
    float* __restrict__ out, float* __restrict__ sums,
    const float* __restrict__ eWg, const float* __restrict__ naWg,
    float* __restrict__ epro, float* __restrict__ t2,
    int n, int act)
{
    __shared__ float sEW[512];
    __shared__ float sNA[256];
    if (eWg) {
        for (int i = threadIdx.x; i < 512; i += 256) sEW[i] = eWg[i];
        for (int i = threadIdx.x; i < 256; i += 256) sNA[i] = naWg[i];
        __syncthreads();
    }
    int lane = threadIdx.x & 31;
    int w0 = (blockIdx.x*blockDim.x + threadIdx.x) >> 5;
    int nw = (gridDim.x*blockDim.x) >> 5;
    float4 bb = bias ? ((const float4*)bias)[lane] : make_float4(0.f,0.f,0.f,0.f);
    float ls0[4] = {0.f,0.f,0.f,0.f}, ls1[4] = {0.f,0.f,0.f,0.f};
    const float4* t4 = (const float4*)t;

    for (int v = w0; v < n; v += nw) {
        float dv = dis[v];
        float4 acc = t4[v*32 + lane];
        float d2 = dv*dv;
        acc.x *= d2; acc.y *= d2; acc.z *= d2; acc.w *= d2;
        int p = rowptr[v], en = rowptr[v+1];
        // MLP-4 main loop
        for (; p + 4 <= en; p += 4) {
            int s0 = __ldg(&csrc[p+0]);
            int s1 = __ldg(&csrc[p+1]);
            int s2 = __ldg(&csrc[p+2]);
            int s3 = __ldg(&csrc[p+3]);
            float w0_ = __ldg(&dis[s0]);
            float w1_ = __ldg(&dis[s1]);
            float w2_ = __ldg(&dis[s2]);
            float w3_ = __ldg(&dis[s3]);
            float4 x0 = t4[s0*32 + lane];
            float4 x1 = t4[s1*32 + lane];
            float4 x2 = t4[s2*32 + lane];
            float4 x3 = t4[s3*32 + lane];
            w0_ *= dv; w1_ *= dv; w2_ *= dv; w3_ *= dv;
            acc.x += w0_*x0.x + w1_*x1.x + w2_*x2.x + w3_*x3.x;
            acc.y += w0_*x0.y + w1_*x1.y + w2_*x2.y + w3_*x3.y;
            acc.z += w0_*x0.z + w1_*x1.z + w2_*x2.z + w3_*x3.z;
            acc.w += w0_*x0.w + w1_*x1.w + w2_*x2.w + w3_*x3.w;
        }
        for (; p < en; p++) {
            int s = __ldg(&csrc[p]);
            float w = __ldg(&dis[s]) * dv;
            float4 x = t4[s*32 + lane];
            acc.x += w*x.x; acc.y += w*x.y; acc.z += w*x.z; acc.w += w*x.w;
        }
        acc.x += bb.x; acc.y += bb.y; acc.z += bb.z; acc.w += bb.w;
        if (act == 1) {
            acc.x = fmaxf(acc.x, 0.f); acc.y = fmaxf(acc.y, 0.f);
            acc.z = fmaxf(acc.z, 0.f); acc.w = fmaxf(acc.w, 0.f);
        }
        if (sums) {
            ls0[0]+=acc.x; ls1[0]+=acc.x*acc.x;
            ls0[1]+=acc.y; ls1[1]+=acc.y*acc.y;
            ls0[2]+=acc.z; ls1[2]+=acc.z*acc.z;
            ls0[3]+=acc.w; ls1[3]+=acc.w*acc.w;
        }
        ((float4*)out)[v*32 + lane] = acc;

        if (eWg) {
            float hx[4] = {acc.x, acc.y, acc.z, acc.w};
            float p0=0,p1=0,q0=0,q1=0,u0=0,u1=0;
            #pragma unroll
            for (int i = 0; i < 4; i++) {
                int k = lane*4 + i; float xv = hx[i];
                p0 += xv*sEW[k*2+0];        p1 += xv*sEW[k*2+1];
                q0 += xv*sEW[(128+k)*2+0];  q1 += xv*sEW[(128+k)*2+1];
                u0 += xv*sNA[k*2+0];        u1 += xv*sNA[k*2+1];
            }
            #pragma unroll
            for (int o = 16; o; o >>= 1) {
                p0 += __shfl_xor_sync(0xffffffffu, p0, o);
                p1 += __shfl_xor_sync(0xffffffffu, p1, o);
                q0 += __shfl_xor_sync(0xffffffffu, q0, o);
                q1 += __shfl_xor_sync(0xffffffffu, q1, o);
                u0 += __shfl_xor_sync(0xffffffffu, u0, o);
                u1 += __shfl_xor_sync(0xffffffffu, u1, o);
            }
            if (lane == 0) {
                epro[v*4+0]=p0; epro[v*4+1]=p1; epro[v*4+2]=q0; epro[v*4+3]=q1;
                t2[v*2+0]=u0; t2[v*2+1]=u1;
            }
        }
    }

    if (sums) {
        __shared__ float ss[256];
        ss[threadIdx.x] = 0.f;
        __syncthreads();
        #pragma unroll
        for (int j = 0; j < 4; j++) {
            atomicAdd(&ss[lane*4+j],     ls0[j]);
            atomicAdd(&ss[128+lane*4+j], ls1[j]);
        }
        __syncthreads();
        atomicAdd(&sums[threadIdx.x], ss[threadIdx.x]);
    }
}

// fused XC+XO gather (MLP-2 unrolled)
__global__ __launch_bounds__(256) void gather2(
    const float* __restrict__ tc_, const float* __restrict__ to_,
    const int* __restrict__ rowptr, const int* __restrict__ csrc,
    const float2* __restrict__ dis01,
    const float* __restrict__ eperm,
    float* __restrict__ sc_, float* __restrict__ so_, int n)
{
    int lane = threadIdx.x & 31;
    int w0 = (blockIdx.x*blockDim.x + threadIdx.x) >> 5;
    int nw = (gridDim.x*blockDim.x) >> 5;
    const float4* tc4 = (const float4*)tc_;
    const float4* to4 = (const float4*)to_;
    for (int v = w0; v < n; v += nw) {
        float2 dv = dis01[v];
        float4 ac = tc4[v*32 + lane];
        float4 ao = to4[v*32 + lane];
        float d02 = dv.x*dv.x, d12 = dv.y*dv.y;
        ac.x *= d02; ac.y *= d02; ac.z *= d02; ac.w *= d02;
        ao.x *= d12; ao.y *= d12; ao.z *= d12; ao.w *= d12;
        int p = rowptr[v], en = rowptr[v+1];
        for (; p + 2 <= en; p += 2) {
            int s0 = __ldg(&csrc[p+0]);
            int s1 = __ldg(&csrc[p+1]);
            float2 ea0 = __ldg((const float2*)&eperm[(p+0)*2]);
            float2 ea1 = __ldg((const float2*)&eperm[(p+1)*2]);
            float2 ds0 = __ldg(&dis01[s0]);
            float2 ds1 = __ldg(&dis01[s1]);
            float4 xc0 = tc4[s0*32 + lane];
            float4 xo0 = to4[s0*32 + lane];
            float4 xc1 = tc4[s1*32 + lane];
            float4 xo1 = to4[s1*32 + lane];
            float wc0 = ds0.x * dv.x * ea0.x, wo0 = ds0.y * dv.y * ea0.y;
            float wc1 = ds1.x * dv.x * ea1.x, wo1 = ds1.y * dv.y * ea1.y;
            ac.x += wc0*xc0.x + wc1*xc1.x; ac.y += wc0*xc0.y + wc1*xc1.y;
            ac.z += wc0*xc0.z + wc1*xc1.z; ac.w += wc0*xc0.w + wc1*xc1.w;
            ao.x += wo0*xo0.x + wo1*xo1.x; ao.y += wo0*xo0.y + wo1*xo1.y;
            ao.z += wo0*xo0.z + wo1*xo1.z; ao.w += wo0*xo0.w + wo1*xo1.w;
        }
        for (; p < en; p++) {
            int s = __ldg(&csrc[p]);
            float2 ea = __ldg((const float2*)&eperm[p*2]);
            float2 ds = __ldg(&dis01[s]);
            float wc = ds.x * dv.x * ea.x;
            float wo = ds.y * dv.y * ea.y;
            float4 xc = tc4[s*32 + lane];
            float4 xo = to4[s*32 + lane];
            ac.x += wc*xc.x; ac.y += wc*xc.y; ac.z += wc*xc.z; ac.w += wc*xc.w;
            ao.x += wo*xo.x; ao.y += wo*xo.y; ao.z += wo*xo.z; ao.w += wo*xo.w;
        }
        ((float4*)sc_)[v*32 + lane] = ac;
        ((float4*)so_)[v*32 + lane] = ao;
    }
}

// ---------------- attention ----------------
__global__ void edge_att_kernel(const int* __restrict__ src, const int* __restrict__ dst,
                                const int* __restrict__ pos,
                                const float* __restrict__ epro, const float* __restrict__ eb,
                                float* __restrict__ eperm, float2* __restrict__ deg01, int E) {
    int e = blockIdx.x*blockDim.x + threadIdx.x;
    if (e >= E) return;
    int s = src[e], d = dst[e];
    float2 ps = *(const float2*)&epro[s*4];
    float2 qd = *(const float2*)&epro[d*4+2];
    float l0 = ps.x + qd.x + eb[0];
    float l1 = ps.y + qd.y + eb[1];
    float m = fmaxf(l0, l1);
    float e0 = expf(l0 - m), e1 = expf(l1 - m);
    float inv = 1.f/(e0+e1);
    float a0 = e0*inv, a1 = e1*inv;
    int p = pos[e];
    *(float2*)&eperm[p*2] = make_float2(a0, a1);
    asm volatile("red.global.add.v2.f32 [%0], {%1, %2};"
                 :: "l"(&deg01[s]), "f"(a0), "f"(a1) : "memory");
}

__global__ void natt_gather(const float* __restrict__ t2,
                            const int* __restrict__ rowptr, const int* __restrict__ csrc,
                            const float* __restrict__ disU,
                            const float* __restrict__ nab,
                            float* __restrict__ natt, int n) {
    int v = blockIdx.x*blockDim.x + threadIdx.x;
    if (v >= n) return;
    float dv = disU[v];
    float d2 = dv*dv;
    float a0 = t2[v*2+0]*d2, a1 = t2[v*2+1]*d2;
    int p = rowptr[v], en = rowptr[v+1];
    for (; p + 4 <= en; p += 4) {
        int s0 = __ldg(&csrc[p+0]);
        int s1 = __ldg(&csrc[p+1]);
        int s2 = __ldg(&csrc[p+2]);
        int s3 = __ldg(&csrc[p+3]);
        float w0 = __ldg(&disU[s0]);
        float w1 = __ldg(&disU[s1]);
        float w2 = __ldg(&disU[s2]);
        float w3 = __ldg(&disU[s3]);
        float2 x0 = __ldg((const float2*)&t2[s0*2]);
        float2 x1 = __ldg((const float2*)&t2[s1*2]);
        float2 x2 = __ldg((const float2*)&t2[s2*2]);
        float2 x3 = __ldg((const float2*)&t2[s3*2]);
        w0 *= dv; w1 *= dv; w2 *= dv; w3 *= dv;
        a0 += w0*x0.x + w1*x1.x + w2*x2.x + w3*x3.x;
        a1 += w0*x0.y + w1*x1.y + w2*x2.y + w3*x3.y;
    }
    for (; p < en; p++) {
        int s = __ldg(&csrc[p]);
        float w = __ldg(&disU[s])*dv;
        float2 ts = __ldg((const float2*)&t2[s*2]);
        a0 += w*ts.x;
        a1 += w*ts.y;
    }
    a0 += nab[0]; a1 += nab[1];
    float m = fmaxf(a0, a1);
    float e0 = expf(a0 - m), e1 = expf(a1 - m);
    float inv = 1.f/(e0+e1);
    natt[v*2+0] = e0*inv; natt[v*2+1] = e1*inv;
}

// fused pooling of both branches
__global__ void pool_both(const float* __restrict__ sc_, const float* __restrict__ so_,
                          const float* __restrict__ xcb, const float* __restrict__ xob,
                          const int* __restrict__ gstart, float* __restrict__ cat) {
    int g = blockIdx.x, c = threadIdx.x;
    int st = gstart[g], en = gstart[g+1];
    const float* s = (c < 128) ? sc_ : so_;
    int cc = c & 127;
    float bc = (c < 128) ? xcb[cc] : xob[cc];
    float acc = 0.f;
    for (int v = st; v < en; v++) {
        float z = s[v*128 + cc] + bc;
        acc += (z > 0.f) ? z : expm1f(z);
    }
    cat[g*256 + c] = acc;
}

// ---------------- fused heads ----------------
__global__ void head_gemm1(const float* __restrict__ cat,
                           const float* __restrict__ mean, const float* __restrict__ rstd,
                           const float* __restrict__ cW1, const float* __restrict__ cb1,
                           const float* __restrict__ oW1, const float* __restrict__ ob1,
                           const float* __restrict__ coW1, const float* __restrict__ cob1,
                           float* __restrict__ hd) {
    __shared__ float a[256];
    int r = blockIdx.x, head = blockIdx.y;
    for (int k = threadIdx.x; k < 256; k += 128)
        a[k] = (cat[r*256 + k] - mean[k]) * rstd[k] + BNB;
    __syncthreads();
    const float* W; const float* b; int K, koff, act;
    if (head == 0)      { W = cW1;  b = cb1;  K = 128; koff = 0;   act = 1; }
    else if (head == 1) { W = oW1;  b = ob1;  K = 128; koff = 128; act = 1; }
    else                { W = coW1; b = cob1; K = 256; koff = 0;   act = 2; }
    int c = threadIdx.x;
    float acc = b[c];
    for (int k = 0; k < K; k++) acc += a[koff + k] * W[k*128 + c];
    if (act == 1) acc = fmaxf(acc, 0.f);
    else {
        acc = (acc > 0.f) ? acc : expm1f(acc);
        acc = (acc > 0.f) ? acc : expm1f(acc);
    }
    hd[(head*Gg + r)*128 + c] = acc;
}

__global__ void head_gemm2_lsm(const float* __restrict__ hd,
                               const float* __restrict__ mean, const float* __restrict__ rstd,
                               const float* __restrict__ cW2, const float* __restrict__ cb2,
                               const float* __restrict__ oW2, const float* __restrict__ ob2,
                               const float* __restrict__ coW2, const float* __restrict__ cob2,
                               float* __restrict__ out) {
    __shared__ float a[128];
    __shared__ float lg[COUT];
    int r = blockIdx.x, head = blockIdx.y;
    int k = threadIdx.x;
    a[k] = (hd[(head*Gg + r)*128 + k] - mean[head*128 + k]) * rstd[head*128 + k] + BNB;
    __syncthreads();
    const float* W = (head == 0) ? cW2 : (head == 1) ? oW2 : coW2;
    const float* b = (head == 0) ? cb2 : (head == 1) ? ob2 : cob2;
    if (k < COUT) {
        float acc = b[k];
        for (int kk = 0; kk < 128; kk++) acc += a[kk] * W[kk*COUT + k];
        lg[k] = acc;
    }
    __syncthreads();
    if (k < COUT) {
        float m = -1e30f;
        #pragma unroll
        for (int i = 0; i < COUT; i++) m = fmaxf(m, lg[i]);
        float s = 0.f;
        #pragma unroll
        for (int i = 0; i < COUT; i++) s += expf(lg[i] - m);
        out[head*Gg*COUT + r*COUT + k] = lg[k] - m - logf(s);
    }
}

// ---------------- host orchestration ----------------
extern "C" void kernel_launch(void* const* d_in, const int* in_sizes, int n_in,
                              void* d_out, int out_size) {
    const float* x      = (const float*)d_in[0];
    const float* W_feat = (const float*)d_in[1];
    const float* conv_Ws= (const float*)d_in[2];
    const float* conv_bs= (const float*)d_in[3];
    const float* eW     = (const float*)d_in[4];
    const float* eb     = (const float*)d_in[5];
    const float* naW    = (const float*)d_in[6];
    const float* nab    = (const float*)d_in[7];
    const float* xcW    = (const float*)d_in[8];
    const float* xcb    = (const float*)d_in[9];
    const float* xoW    = (const float*)d_in[10];
    const float* xob    = (const float*)d_in[11];
    const float* cW1    = (const float*)d_in[12];
    const float* cb1    = (const float*)d_in[13];
    const float* cW2    = (const float*)d_in[14];
    const float* cb2    = (const float*)d_in[15];
    const float* oW1    = (const float*)d_in[16];
    const float* ob1    = (const float*)d_in[17];
    const float* oW2    = (const float*)d_in[18];
    const float* ob2    = (const float*)d_in[19];
    const float* coW1   = (const float*)d_in[20];
    const float* cob1   = (const float*)d_in[21];
    const float* coW2   = (const float*)d_in[22];
    const float* cob2   = (const float*)d_in[23];
    const int* esrc     = (const int*)d_in[24];
    const int* edst     = (const int*)d_in[25];
    const int* batch    = (const int*)d_in[26];
    float* out = (float*)d_out;

    float *p_h,*p_t,*p_t2b,*p_s,*p_s2,*p_stats,*p_mean,*p_rstd,*p_disU;
    float *p_epro,*p_t2,*p_natt,*p_eperm,*p_cat,*p_hd;
    float2* p_deg01;
    int *p_gstart,*p_cnt,*p_incl,*p_bsum,*p_rowptr,*p_cursor,*p_csrc,*p_pos;
    cudaGetSymbolAddress((void**)&p_h, g_h);
    cudaGetSymbolAddress((void**)&p_t, g_t);
    cudaGetSymbolAddress((void**)&p_t2b, g_t2b);
    cudaGetSymbolAddress((void**)&p_s, g_s);
    cudaGetSymbolAddress((void**)&p_s2, g_s2);
    cudaGetSymbolAddress((void**)&p_stats, g_stats);
    cudaGetSymbolAddress((void**)&p_mean, g_mean);
    cudaGetSymbolAddress((void**)&p_rstd, g_rstd);
    cudaGetSymbolAddress((void**)&p_disU, g_disU);
    cudaGetSymbolAddress((void**)&p_deg01, g_deg01);
    cudaGetSymbolAddress((void**)&p_epro, g_epro);
    cudaGetSymbolAddress((void**)&p_t2, g_t2);
    cudaGetSymbolAddress((void**)&p_natt, g_natt);
    cudaGetSymbolAddress((void**)&p_eperm, g_eperm);
    cudaGetSymbolAddress((void**)&p_cat, g_cat);
    cudaGetSymbolAddress((void**)&p_hd, g_hd);
    cudaGetSymbolAddress((void**)&p_gstart, g_gstart);
    cudaGetSymbolAddress((void**)&p_cnt, g_cnt);
    cudaGetSymbolAddress((void**)&p_incl, g_incl);
    cudaGetSymbolAddress((void**)&p_bsum, g_bsum);
    cudaGetSymbolAddress((void**)&p_rowptr, g_rowptr);
    cudaGetSymbolAddress((void**)&p_cursor, g_cursor);
    cudaGetSymbolAddress((void**)&p_csrc, g_csrc);
    cudaGetSymbolAddress((void**)&p_pos, g_pos);

    cudaFuncSetAttribute(gemm128, cudaFuncAttributeMaxDynamicSharedMemorySize, GEMM_SMEM);

    const int N = Nn, E = Ee, G = Gg;
    const int NB = (N + 63) / 64;
    const int NT = (N + 255) / 256;
    const int ET = (E + 255) / 256;
    const int GB = 1024;
    const int NSCAN = (N + 1023) / 1024;

    // ---- CSR build + degrees + group starts ----
    init_kernel<<<NT,256>>>(p_disU, p_deg01, p_cnt, N);
    deg_hist<<<ET,256>>>(esrc, edst, p_disU, p_cnt, E);
    scan_block<<<NSCAN,1024>>>(p_cnt, p_incl, p_bsum, N);
    scan_tops<<<1,32>>>(p_bsum, NSCAN);
    make_rowptr<<<NT,256>>>(p_cnt, p_incl, p_bsum, p_rowptr, p_cursor, p_disU, N, E);
    fill_csr<<<ET,256>>>(esrc, edst, p_cursor, p_csrc, p_pos, E);
    gstart_kernel<<<NT,256>>>(batch, p_gstart, N, G);

    // ---- h = relu(BN(x) @ W_feat), h-stats fused into epilogue ----
    cudaMemsetAsync(p_stats, 0, 1024);
    colstats<<<512,256>>>(x, N, p_stats);
    finalize_stats<<<1,256>>>(p_stats, 128, 1.f/N, p_mean, p_rstd);
    cudaMemsetAsync(p_stats, 0, 1024);
    gemm128<<<NB,256,GEMM_SMEM>>>(x, nullptr,0,0, p_mean, p_rstd, W_feat,
                                  p_h, p_stats, N, 1);
    finalize_stats<<<1,256>>>(p_stats, 128, 1.f/N, p_mean, p_rstd);

    // ---- 3 GCN layers ----
    for (int l = 0; l < 3; l++) {
        gemm128<<<NB,256,GEMM_SMEM>>>(p_h, nullptr,0,0, p_mean, p_rstd,
                                      conv_Ws + l*128*128, p_t, nullptr, N, 0);
        if (l < 2) {
            cudaMemsetAsync(p_stats, 0, 1024);
            gather128<<<GB,256>>>(p_t, p_rowptr, p_csrc, p_disU,
                                  conv_bs + l*128, p_h, p_stats,
                                  nullptr, nullptr, nullptr, nullptr, N, 1);
            finalize_stats<<<1,256>>>(p_stats, 128, 1.f/N, p_mean, p_rstd);
        } else {
            gather128<<<GB,256>>>(p_t, p_rowptr, p_csrc, p_disU,
                                  conv_bs + l*128, p_h, nullptr,
                                  eW, naW, p_epro, p_t2, N, 1);
        }
    }

    // ---- attention ----
    edge_att_kernel<<<ET,256>>>(esrc, edst, p_pos, p_epro, eb, p_eperm, p_deg01, E);
    rsqrt_arr<<<(2*N+255)/256,256>>>((float*)p_deg01, 2*N);
    natt_gather<<<NT,256>>>(p_t2, p_rowptr, p_csrc, p_disU, nab, p_natt, N);

    // ---- XC / XO stats (one fused pass over h) ----
    cudaMemsetAsync(p_stats, 0, 2048);
    colstats2<<<512,256>>>(p_h, p_natt, N, p_stats);
    finalize_stats<<<1,256>>>(p_stats,       128, 1.f/N, p_mean,       p_rstd);
    finalize_stats<<<1,256>>>(p_stats + 256, 128, 1.f/N, p_mean + 128, p_rstd + 128);

    // ---- XC / XO branches ----
    gemm128<<<NB,256,GEMM_SMEM>>>(p_h, p_natt, 2, 0, p_mean, p_rstd, xcW,
                                  p_t, nullptr, N, 0);
    gemm128<<<NB,256,GEMM_SMEM>>>(p_h, p_natt, 2, 1, p_mean + 128, p_rstd + 128,
                                  xoW, p_t2b, nullptr, N, 0);
    gather2<<<GB,256>>>(p_t, p_t2b, p_rowptr, p_csrc, p_deg01,
                        p_eperm, p_s, p_s2, N);
    pool_both<<<G,256>>>(p_s, p_s2, xcb, xob, p_gstart, p_cat);

    // ---- heads (fused) ----
    head_stats<<<256,128>>>(p_cat, 256, G, p_mean, p_rstd);
    dim3 hg1(G, 3);
    head_gemm1<<<hg1,128>>>(p_cat, p_mean, p_rstd, cW1, cb1, oW1, ob1,
                            coW1, cob1, p_hd);
    head_stats3<<<384,128>>>(p_hd, G, p_mean, p_rstd);
    dim3 hg2(G, 3);
    head_gemm2_lsm<<<hg2,128>>>(p_hd, p_mean, p_rstd, cW2, cb2, oW2, ob2,
                                coW2, cob2, out);
}

// round 9
// speedup vs baseline: 1.6476x; 1.0807x over previous
#include <cuda_runtime.h>
#include <math.h>

#define Nn 50000
#define Ee 400000
#define Hh 128
#define Gg 512
#define COUT 10

typedef unsigned long long u64;

static constexpr float EPSBN = 1e-5f;
static constexpr float BNB   = 1e-4f;

// ---------------- scratch (static device allocations) ----------------
__device__ float g_h[Nn*Hh];
__device__ float g_t[Nn*Hh];
__device__ float g_t2b[Nn*Hh];
__device__ float g_stats[512];      // zero-init; every consumer re-zeroes
__device__ float g_mean[512];
__device__ float g_rstd[512];
__device__ float g_disU[Nn];
__device__ float2 g_deg01[Nn];
__device__ float g_epro[Nn*4];
__device__ float g_t2[Nn*2];
__device__ float g_natt[Nn*2];
__device__ float g_eperm[Ee*2];
__device__ float g_bias2[256];
__device__ int   g_gstart[Gg+1];
__device__ float g_cat[Gg*256];
__device__ float g_hd[3*Gg*128];
// CSR by destination
__device__ int g_cnt[Nn];
__device__ int g_incl[Nn];
__device__ int g_bsum[64];
__device__ int g_rowptr[Nn+1];
__device__ int g_cursor[Nn];
__device__ int g_csrc[Ee];
__device__ int g_pos[Ee];

// ---------------- small utility kernels ----------------
__global__ void init_kernel(float* disU, float2* deg01, int* cnt, int n) {
    int i = blockIdx.x*blockDim.x + threadIdx.x;
    if (i < n) { disU[i] = 1.f; deg01[i] = make_float2(1.f, 1.f); cnt[i] = 0; }
}

__global__ void deg_hist(const int* __restrict__ src, const int* __restrict__ dst,
                         float* degU, int* cnt, int E) {
    int i = blockIdx.x*blockDim.x + threadIdx.x;
    if (i < E) {
        atomicAdd(&degU[src[i]], 1.0f);
        atomicAdd(&cnt[dst[i]], 1);
    }
}

__global__ void rsqrt_arr(float* p, int n) {
    int i = blockIdx.x*blockDim.x + threadIdx.x;
    if (i < n) p[i] = rsqrtf(p[i]);
}

__global__ void gstart_kernel(const int* __restrict__ batch, int* gstart, int n, int G) {
    int i = blockIdx.x*blockDim.x + threadIdx.x;
    if (i >= n) return;
    int b  = batch[i];
    int pb = (i == 0) ? -1 : batch[i-1];
    for (int g = pb+1; g <= b; g++) gstart[g] = i;
    if (i == n-1) {
        for (int g = b+1; g <= G; g++) gstart[g] = n;
    }
}

// ---------------- CSR build ----------------
__global__ void scan_block(const int* __restrict__ cnt, int* incl, int* bsum, int n) {
    __shared__ int sm[1024];
    int i = blockIdx.x*1024 + threadIdx.x;
    sm[threadIdx.x] = (i < n) ? cnt[i] : 0;
    __syncthreads();
    for (int off = 1; off < 1024; off <<= 1) {
        int t = (threadIdx.x >= off) ? sm[threadIdx.x - off] : 0;
        __syncthreads();
        sm[threadIdx.x] += t;
        __syncthreads();
    }
    if (i < n) incl[i] = sm[threadIdx.x];
    if (threadIdx.x == 1023) bsum[blockIdx.x] = sm[1023];
}

// warp-parallel scan over <=64 block sums
__global__ void scan_tops(int* bsum, int nb) {
    int lane = threadIdx.x;
    int v0 = (lane < nb) ? bsum[lane] : 0;
    int v1 = (32 + lane < nb) ? bsum[32 + lane] : 0;
    #pragma unroll
    for (int o = 1; o < 32; o <<= 1) {
        int t = __shfl_up_sync(0xffffffffu, v0, o);
        if (lane >= o) v0 += t;
    }
    int tot0 = __shfl_sync(0xffffffffu, v0, 31);
    #pragma unroll
    for (int o = 1; o < 32; o <<= 1) {
        int t = __shfl_up_sync(0xffffffffu, v1, o);
        if (lane >= o) v1 += t;
    }
    v1 += tot0;
    if (lane < nb) bsum[lane] = v0;
    if (32 + lane < nb) bsum[32 + lane] = v1;
}

__global__ void make_rowptr(const int* __restrict__ cnt, const int* __restrict__ incl,
                            const int* __restrict__ bsum,
                            int* rowptr, int* cursor, float* disU, int n, int E) {
    int i = blockIdx.x*blockDim.x + threadIdx.x;
    if (i < n) {
        int b = i >> 10;
        int ex = incl[i] - cnt[i] + ((b > 0) ? bsum[b-1] : 0);
        rowptr[i] = ex;
        cursor[i] = ex;
        disU[i] = rsqrtf(disU[i]);
    }
    if (i == 0) rowptr[n] = E;
}

__global__ void fill_csr(const int* __restrict__ src, const int* __restrict__ dst,
                         int* cursor, int* csrc, int* pos, int E) {
    int e = blockIdx.x*blockDim.x + threadIdx.x;
    if (e < E) {
        int p = atomicAdd(&cursor[dst[e]], 1);
        csrc[p] = src[e];
        pos[e] = p;
    }
}

// ---------------- BatchNorm stats ----------------
__global__ void colstats(const float* __restrict__ A, int n, float* sums) {
    long total  = (long)n * 128;
    long stride = (long)gridDim.x * blockDim.x;
    long i0     = (long)blockIdx.x*blockDim.x + threadIdx.x;
    if (i0 >= total) return;
    int c = (int)(i0 % 128);
    float s0 = 0.f, s1 = 0.f;
    for (long i = i0; i < total; i += stride) {
        int r = (int)(i / 128);
        float v = A[(long)r*128 + c];
        s0 += v; s1 += v*v;
    }
    atomicAdd(&sums[c], s0);
    atomicAdd(&sums[128+c], s1);
}

__global__ void colstats2(const float* __restrict__ A, const float* __restrict__ natt,
                          int n, float* sums) {
    long total  = (long)n * 128;
    long stride = (long)gridDim.x * blockDim.x;
    long i0     = (long)blockIdx.x*blockDim.x + threadIdx.x;
    if (i0 >= total) return;
    int c = (int)(i0 % 128);
    float s00=0.f, s01=0.f, s10=0.f, s11=0.f;
    for (long i = i0; i < total; i += stride) {
        int r = (int)(i / 128);
        float v = A[(long)r*128 + c];
        float v0 = v * natt[r*2+0];
        float v1 = v * natt[r*2+1];
        s00 += v0; s01 += v0*v0;
        s10 += v1; s11 += v1*v1;
    }
    atomicAdd(&sums[c], s00);
    atomicAdd(&sums[128+c], s01);
    atomicAdd(&sums[256+c], s10);
    atomicAdd(&sums[384+c], s11);
}

// finalize + RE-ZERO the accumulator (keeps zero invariant across graph replays)
__global__ void finalize_stats(float* sums, int C, float inv_n,
                               float* mean, float* rstd) {
    int c = threadIdx.x + blockIdx.x*blockDim.x;
    if (c < C) {
        float s0 = sums[c], s1 = sums[C+c];
        sums[c] = 0.f; sums[C+c] = 0.f;
        float m = s0*inv_n;
        float var = s1*inv_n - m*m;
        mean[c] = m;
        rstd[c] = rsqrtf(var + EPSBN);
    }
}

// finalize both natt channels (layout: [s0_0|s1_0|s0_1|s1_1] x128) + zero
__global__ void finalize2(float* sums, float inv_n, float* mean, float* rstd) {
    int c = threadIdx.x;               // 0..255
    int ch = c >> 7, cc = c & 127;
    float s0 = sums[ch*256 + cc], s1 = sums[ch*256 + 128 + cc];
    sums[ch*256 + cc] = 0.f; sums[ch*256 + 128 + cc] = 0.f;
    float m = s0*inv_n;
    float var = s1*inv_n - m*m;
    mean[c] = m;
    rstd[c] = rsqrtf(var + EPSBN);
}

__global__ void head_stats(const float* __restrict__ A, int lda, int n,
                           float* mean, float* rstd) {
    __shared__ float s0s[4], s1s[4];
    int c = blockIdx.x;
    int lane = threadIdx.x & 31, warp = threadIdx.x >> 5;
    float s0 = 0.f, s1 = 0.f;
    for (int r = threadIdx.x; r < n; r += blockDim.x) {
        float v = A[r*lda + c];
        s0 += v; s1 += v*v;
    }
    #pragma unroll
    for (int o = 16; o; o >>= 1) {
        s0 += __shfl_xor_sync(0xffffffffu, s0, o);
        s1 += __shfl_xor_sync(0xffffffffu, s1, o);
    }
    if (lane == 0) { s0s[warp] = s0; s1s[warp] = s1; }
    __syncthreads();
    if (threadIdx.x == 0) {
        float t0 = 0.f, t1 = 0.f;
        for (int w = 0; w < 4; w++) { t0 += s0s[w]; t1 += s1s[w]; }
        float m = t0 / n;
        float var = t1 / n - m*m;
        mean[c] = m;
        rstd[c] = rsqrtf(var + EPSBN);
    }
}

__global__ void head_stats3(const float* __restrict__ hd, int n,
                            float* mean, float* rstd) {
    __shared__ float s0s[4], s1s[4];
    int cg = blockIdx.x;
    int head = cg >> 7, c = cg & 127;
    const float* A = hd + head*Gg*128;
    int lane = threadIdx.x & 31, warp = threadIdx.x >> 5;
    float s0 = 0.f, s1 = 0.f;
    for (int r = threadIdx.x; r < n; r += blockDim.x) {
        float v = A[r*128 + c];
        s0 += v; s1 += v*v;
    }
    #pragma unroll
    for (int o = 16; o; o >>= 1) {
        s0 += __shfl_xor_sync(0xffffffffu, s0, o);
        s1 += __shfl_xor_sync(0xffffffffu, s1, o);
    }
    if (lane == 0) { s0s[warp] = s0; s1s[warp] = s1; }
    __syncthreads();
    if (threadIdx.x == 0) {
        float t0 = 0.f, t1 = 0.f;
        for (int w = 0; w < 4; w++) { t0 += s0s[w]; t1 += s1s[w]; }
        float m = t0 / n;
        float var = t1 / n - m*m;
        mean[cg] = m;
        rstd[cg] = rsqrtf(var + EPSBN);
    }
}

// BN-fold bias rows: bias2[hh*128+j] = sum_k (BNB - mean_k*rstd_k) * W_hh[k,j]
__global__ void bias_kernel(const float* __restrict__ mean, const float* __restrict__ rstd,
                            const float* __restrict__ xcW, const float* __restrict__ xoW,
                            float* __restrict__ bias2) {
    __shared__ float coef[128];
    int hh = blockIdx.x;
    int j = threadIdx.x;
    const float* W = hh ? xoW : xcW;
    coef[j] = BNB - mean[hh*128+j]*rstd[hh*128+j];
    __syncthreads();
    float acc = 0.f;
    for (int k = 0; k < 128; k++) acc += coef[k]*W[k*128+j];
    bias2[hh*128+j] = acc;
}

// ---------------- big GEMM (packed f32x2 FMA, BM=64) ----------------
static constexpr int GEMM_SMEM = (64*128 + 128*128) * 4;

__global__ __launch_bounds__(256) void gemm128(
    const float* __restrict__ A,
    const float* __restrict__ mean, const float* __restrict__ rstd,
    const float* __restrict__ W,
    float* __restrict__ out,
    float* __restrict__ sums,
    int n, int act)
{
    extern __shared__ float sm[];
    float* As = sm;               // [64][128]
    float* Ws = sm + 64*128;      // [128][128]
    int tid  = threadIdx.x;
    int row0 = blockIdx.x * 64;

    const float4* Wg = (const float4*)W;
    float4* Ws4 = (float4*)Ws;
    #pragma unroll 4
    for (int i = tid; i < 128*32; i += 256) Ws4[i] = Wg[i];

    #pragma unroll 2
    for (int i = tid; i < 64*32; i += 256) {
        int r = i >> 5, cq = i & 31;
        int gr = row0 + r;
        float4 v = make_float4(0.f,0.f,0.f,0.f);
        if (gr < n) {
            v = ((const float4*)A)[gr*32 + cq];
            int c = cq*4;
            v.x = (v.x - mean[c+0])*rstd[c+0] + BNB;
            v.y = (v.y - mean[c+1])*rstd[c+1] + BNB;
            v.z = (v.z - mean[c+2])*rstd[c+2] + BNB;
            v.w = (v.w - mean[c+3])*rstd[c+3] + BNB;
        }
        ((float4*)As)[i] = v;
    }
    __syncthreads();

    int tc = tid & 15, tr = tid >> 4;
    int r0 = tr*4;
    int c0 = tc*4, c1 = 64 + tc*4;

    u64 accp[4][4];
    #pragma unroll
    for (int i = 0; i < 4; i++)
        #pragma unroll
        for (int j = 0; j < 4; j++) accp[i][j] = 0ull;

    for (int k = 0; k < 128; k += 4) {
        float4 a4[4];
        #pragma unroll
        for (int i = 0; i < 4; i++)
            a4[i] = *(const float4*)&As[(r0+i)*128 + k];
        #pragma unroll
        for (int kk = 0; kk < 4; kk++) {
            ulonglong2 w01 = *(const ulonglong2*)&Ws[(k+kk)*128 + c0];
            ulonglong2 w23 = *(const ulonglong2*)&Ws[(k+kk)*128 + c1];
            u64 wp0 = w01.x, wp1 = w01.y, wp2 = w23.x, wp3 = w23.y;
            #pragma unroll
            for (int i = 0; i < 4; i++) {
                float a = ((const float*)&a4[i])[kk];
                unsigned int ai = __float_as_uint(a);
                u64 ap;
                asm("mov.b64 %0, {%1, %1};" : "=l"(ap) : "r"(ai));
                asm("fma.rn.f32x2 %0, %1, %2, %0;" : "+l"(accp[i][0]) : "l"(ap), "l"(wp0));
                asm("fma.rn.f32x2 %0, %1, %2, %0;" : "+l"(accp[i][1]) : "l"(ap), "l"(wp1));
                asm("fma.rn.f32x2 %0, %1, %2, %0;" : "+l"(accp[i][2]) : "l"(ap), "l"(wp2));
                asm("fma.rn.f32x2 %0, %1, %2, %0;" : "+l"(accp[i][3]) : "l"(ap), "l"(wp3));
            }
        }
    }

    float t0[8], t1[8];
    #pragma unroll
    for (int j = 0; j < 8; j++) { t0[j] = 0.f; t1[j] = 0.f; }

    float4* O4 = (float4*)out;
    #pragma unroll
    for (int i = 0; i < 4; i++) {
        int gr = row0 + r0 + i;
        if (gr < n) {
            float o[8];
            #pragma unroll
            for (int j = 0; j < 4; j++) {
                unsigned int lo, hi;
                asm("mov.b64 {%0, %1}, %2;" : "=r"(lo), "=r"(hi) : "l"(accp[i][j]));
                o[2*j]   = __uint_as_float(lo);
                o[2*j+1] = __uint_as_float(hi);
            }
            if (act == 1) {
                #pragma unroll
                for (int j = 0; j < 8; j++) o[j] = fmaxf(o[j], 0.f);
            }
            if (sums) {
                #pragma unroll
                for (int j = 0; j < 8; j++) { t0[j] += o[j]; t1[j] += o[j]*o[j]; }
            }
            O4[gr*32 + tc]      = make_float4(o[0], o[1], o[2], o[3]);
            O4[gr*32 + 16 + tc] = make_float4(o[4], o[5], o[6], o[7]);
        }
    }

    if (sums) {
        __syncthreads();
        float* ss = sm;
        ss[tid] = 0.f;
        __syncthreads();
        #pragma unroll
        for (int j = 0; j < 4; j++) {
            atomicAdd(&ss[c0+j],     t0[j]);   atomicAdd(&ss[128+c0+j], t1[j]);
            atomicAdd(&ss[c1+j],     t0[4+j]); atomicAdd(&ss[128+c1+j], t1[4+j]);
        }
        __syncthreads();
        atomicAdd(&sums[tid], ss[tid]);
    }
}

// ---------------- merged XC/XO GEMM ----------------
// Pc = natt0 ⊙ (h @ diag(rstd0)·xcW) + bias2_c ; Po analog with channel 1.
__global__ __launch_bounds__(256) void gemm256(
    const float* __restrict__ h,
    const float* __restrict__ natt,
    const float* __restrict__ rstd2,     // [256]
    const float* __restrict__ xcW, const float* __restrict__ xoW,
    const float* __restrict__ bias2,     // [256]
    float* __restrict__ outc, float* __restrict__ outo, int n)
{
    extern __shared__ float sm[];
    float* As = sm;               // [64][128] (un-normalized h)
    float* Ws = sm + 64*128;      // [128][128]
    int tid  = threadIdx.x;
    int row0 = blockIdx.x * 64;

    #pragma unroll 2
    for (int i = tid; i < 64*32; i += 256) {
        int r = i >> 5, cq = i & 31;
        int gr = row0 + r;
        float4 v = (gr < n) ? ((const float4*)h)[gr*32 + cq]
                            : make_float4(0.f,0.f,0.f,0.f);
        ((float4*)As)[i] = v;
    }

    int tc = tid & 15, tr = tid >> 4;
    int r0 = tr*4;
    int c0 = tc*4, c1 = 64 + tc*4;

    #pragma unroll
    for (int half = 0; half < 2; half++) {
        const float* W  = half ? xoW : xcW;
        const float* rs = rstd2 + half*128;
        const float* bs = bias2 + half*128;
        float* out = half ? outo : outc;

        __syncthreads();
        for (int i = tid; i < 128*32; i += 256) {
            int k = i >> 5;
            float4 w = ((const float4*)W)[i];
            float sc = rs[k];
            w.x *= sc; w.y *= sc; w.z *= sc; w.w *= sc;
            ((float4*)Ws)[i] = w;
        }
        __syncthreads();

        // per-row natt scale for this channel
        float nv[4];
        #pragma unroll
        for (int i = 0; i < 4; i++) {
            int gr = row0 + r0 + i;
            nv[i] = (gr < n) ? natt[gr*2 + half] : 0.f;
        }

        u64 accp[4][4];
        #pragma unroll
        for (int i = 0; i < 4; i++)
            #pragma unroll
            for (int j = 0; j < 4; j++) accp[i][j] = 0ull;

        for (int k = 0; k < 128; k += 4) {
            float4 a4[4];
            #pragma unroll
            for (int i = 0; i < 4; i++)
                a4[i] = *(const float4*)&As[(r0+i)*128 + k];
            #pragma unroll
            for (int kk = 0; kk < 4; kk++) {
                ulonglong2 w01 = *(const ulonglong2*)&Ws[(k+kk)*128 + c0];
                ulonglong2 w23 = *(const ulonglong2*)&Ws[(k+kk)*128 + c1];
                u64 wp0 = w01.x, wp1 = w01.y, wp2 = w23.x, wp3 = w23.y;
                #pragma unroll
                for (int i = 0; i < 4; i++) {
                    float a = ((const float*)&a4[i])[kk] * nv[i];
                    unsigned int ai = __float_as_uint(a);
                    u64 ap;
                    asm("mov.b64 %0, {%1, %1};" : "=l"(ap) : "r"(ai));
                    asm("fma.rn.f32x2 %0, %1, %2, %0;" : "+l"(accp[i][0]) : "l"(ap), "l"(wp0));
                    asm("fma.rn.f32x2 %0, %1, %2, %0;" : "+l"(accp[i][1]) : "l"(ap), "l"(wp1));
                    asm("fma.rn.f32x2 %0, %1, %2, %0;" : "+l"(accp[i][2]) : "l"(ap), "l"(wp2));
                    asm("fma.rn.f32x2 %0, %1, %2, %0;" : "+l"(accp[i][3]) : "l"(ap), "l"(wp3));
                }
            }
        }

        float4 b0 = *(const float4*)&bs[c0];
        float4 b1 = *(const float4*)&bs[c1];
        float4* O4 = (float4*)out;
        #pragma unroll
        for (int i = 0; i < 4; i++) {
            int gr = row0 + r0 + i;
            if (gr < n) {
                float o[8];
                #pragma unroll
                for (int j = 0; j < 4; j++) {
                    unsigned int lo, hi;
                    asm("mov.b64 {%0, %1}, %2;" : "=r"(lo), "=r"(hi) : "l"(accp[i][j]));
                    o[2*j]   = __uint_as_float(lo);
                    o[2*j+1] = __uint_as_float(hi);
                }
                O4[gr*32 + tc]      = make_float4(o[0]+b0.x, o[1]+b0.y, o[2]+b0.z, o[3]+b0.w);
                O4[gr*32 + 16 + tc] = make_float4(o[4]+b1.x, o[5]+b1.y, o[6]+b1.z, o[7]+b1.w);
            }
        }
    }
}

// ---------------- CSR gather conv (MLP-4) ----------------
__global__ __launch_bounds__(256) void gather128(
    const float* __restrict__ t,
    const int* __restrict__ rowptr, const int* __restrict__ csrc,
    const float* __restrict__ dis,
    const float* __restrict__ bias,
    float* __restrict__ out, float* __restrict__ sums,
    const float* __restrict__ eWg, const float* __restrict__ naWg,
    float* __restrict__ epro, float* __restrict__ t2,
    int n, int act)
{
    __shared__ float sEW[512];
    __shared__ float sNA[256];
    if (eWg) {
        for (int i = threadIdx.x; i < 512; i += 256) sEW[i] = eWg[i];
        for (int i = threadIdx.x; i < 256; i += 256) sNA[i] = naWg[i];
        __syncthreads();
    }
    int lane = threadIdx.x & 31;
    int w0 = (blockIdx.x*blockDim.x + threadIdx.x) >> 5;
    int nw = (gridDim.x*blockDim.x) >> 5;
    float4 bb = bias ? ((const float4*)bias)[lane] : make_float4(0.f,0.f,0.f,0.f);
    float ls0[4] = {0.f,0.f,0.f,0.f}, ls1[4] = {0.f,0.f,0.f,0.f};
    const float4* t4 = (const float4*)t;

    for (int v = w0; v < n; v += nw) {
        float dv = dis[v];
        float4 acc = t4[v*32 + lane];
        float d2 = dv*dv;
        acc.x *= d2; acc.y *= d2; acc.z *= d2; acc.w *= d2;
        int p = rowptr[v], en = rowptr[v+1];
        for (; p + 4 <= en; p += 4) {
            int s0 = __ldg(&csrc[p+0]);
            int s1 = __ldg(&csrc[p+1]);
            int s2 = __ldg(&csrc[p+2]);
            int s3 = __ldg(&csrc[p+3]);
            float w0_ = __ldg(&dis[s0]);
            float w1_ = __ldg(&dis[s1]);
            float w2_ = __ldg(&dis[s2]);
            float w3_ = __ldg(&dis[s3]);
            float4 x0 = t4[s0*32 + lane];
            float4 x1 = t4[s1*32 + lane];
            float4 x2 = t4[s2*32 + lane];
            float4 x3 = t4[s3*32 + lane];
            w0_ *= dv; w1_ *= dv; w2_ *= dv; w3_ *= dv;
            acc.x += w0_*x0.x + w1_*x1.x + w2_*x2.x + w3_*x3.x;
            acc.y += w0_*x0.y + w1_*x1.y + w2_*x2.y + w3_*x3.y;
            acc.z += w0_*x0.z + w1_*x1.z + w2_*x2.z + w3_*x3.z;
            acc.w += w0_*x0.w + w1_*x1.w + w2_*x2.w + w3_*x3.w;
        }
        for (; p < en; p++) {
            int s = __ldg(&csrc[p]);
            float w = __ldg(&dis[s]) * dv;
            float4 x = t4[s*32 + lane];
            acc.x += w*x.x; acc.y += w*x.y; acc.z += w*x.z; acc.w += w*x.w;
        }
        acc.x += bb.x; acc.y += bb.y; acc.z += bb.z; acc.w += bb.w;
        if (act == 1) {
            acc.x = fmaxf(acc.x, 0.f); acc.y = fmaxf(acc.y, 0.f);
            acc.z = fmaxf(acc.z, 0.f); acc.w = fmaxf(acc.w, 0.f);
        }
        if (sums) {
            ls0[0]+=acc.x; ls1[0]+=acc.x*acc.x;
            ls0[1]+=acc.y; ls1[1]+=acc.y*acc.y;
            ls0[2]+=acc.z; ls1[2]+=acc.z*acc.z;
            ls0[3]+=acc.w; ls1[3]+=acc.w*acc.w;
        }
        ((float4*)out)[v*32 + lane] = acc;

        if (eWg) {
            float hx[4] = {acc.x, acc.y, acc.z, acc.w};
            float p0=0,p1=0,q0=0,q1=0,u0=0,u1=0;
            #pragma unroll
            for (int i = 0; i < 4; i++) {
                int k = lane*4 + i; float xv = hx[i];
                p0 += xv*sEW[k*2+0];        p1 += xv*sEW[k*2+1];
                q0 += xv*sEW[(128+k)*2+0];  q1 += xv*sEW[(128+k)*2+1];
                u0 += xv*sNA[k*2+0];        u1 += xv*sNA[k*2+1];
            }
            #pragma unroll
            for (int o = 16; o; o >>= 1) {
                p0 += __shfl_xor_sync(0xffffffffu, p0, o);
                p1 += __shfl_xor_sync(0xffffffffu, p1, o);
                q0 += __shfl_xor_sync(0xffffffffu, q0, o);
                q1 += __shfl_xor_sync(0xffffffffu, q1, o);
                u0 += __shfl_xor_sync(0xffffffffu, u0, o);
                u1 += __shfl_xor_sync(0xffffffffu, u1, o);
            }
            if (lane == 0) {
                epro[v*4+0]=p0; epro[v*4+1]=p1; epro[v*4+2]=q0; epro[v*4+3]=q1;
                t2[v*2+0]=u0; t2[v*2+1]=u1;
            }
        }
    }

    if (sums) {
        __shared__ float ss[256];
        ss[threadIdx.x] = 0.f;
        __syncthreads();
        #pragma unroll
        for (int j = 0; j < 4; j++) {
            atomicAdd(&ss[lane*4+j],     ls0[j]);
            atomicAdd(&ss[128+lane*4+j], ls1[j]);
        }
        __syncthreads();
        atomicAdd(&sums[threadIdx.x], ss[threadIdx.x]);
    }
}

// fused XC+XO gather + conv-bias + ELU + global_add_pool (atomic into cat)
__global__ __launch_bounds__(256) void gather2(
    const float* __restrict__ tc_, const float* __restrict__ to_,
    const int* __restrict__ rowptr, const int* __restrict__ csrc,
    const float2* __restrict__ dis01,
    const float* __restrict__ eperm,
    const float* __restrict__ xcb, const float* __restrict__ xob,
    const int* __restrict__ batch,
    float* __restrict__ cat, int n)
{
    int lane = threadIdx.x & 31;
    int w0 = (blockIdx.x*blockDim.x + threadIdx.x) >> 5;
    int nw = (gridDim.x*blockDim.x) >> 5;
    const float4* tc4 = (const float4*)tc_;
    const float4* to4 = (const float4*)to_;
    float4 bc = ((const float4*)xcb)[lane];
    float4 bo = ((const float4*)xob)[lane];

    for (int v = w0; v < n; v += nw) {
        float2 dv = dis01[v];
        float4 ac = tc4[v*32 + lane];
        float4 ao = to4[v*32 + lane];
        float d02 = dv.x*dv.x, d12 = dv.y*dv.y;
        ac.x *= d02; ac.y *= d02; ac.z *= d02; ac.w *= d02;
        ao.x *= d12; ao.y *= d12; ao.z *= d12; ao.w *= d12;
        int p = rowptr[v], en = rowptr[v+1];
        for (; p + 2 <= en; p += 2) {
            int s0 = __ldg(&csrc[p+0]);
            int s1 = __ldg(&csrc[p+1]);
            float2 ea0 = __ldg((const float2*)&eperm[(p+0)*2]);
            float2 ea1 = __ldg((const float2*)&eperm[(p+1)*2]);
            float2 ds0 = __ldg(&dis01[s0]);
            float2 ds1 = __ldg(&dis01[s1]);
            float4 xc0 = tc4[s0*32 + lane];
            float4 xo0 = to4[s0*32 + lane];
            float4 xc1 = tc4[s1*32 + lane];
            float4 xo1 = to4[s1*32 + lane];
            float wc0 = ds0.x * dv.x * ea0.x, wo0 = ds0.y * dv.y * ea0.y;
            float wc1 = ds1.x * dv.x * ea1.x, wo1 = ds1.y * dv.y * ea1.y;
            ac.x += wc0*xc0.x + wc1*xc1.x; ac.y += wc0*xc0.y + wc1*xc1.y;
            ac.z += wc0*xc0.z + wc1*xc1.z; ac.w += wc0*xc0.w + wc1*xc1.w;
            ao.x += wo0*xo0.x + wo1*xo1.x; ao.y += wo0*xo0.y + wo1*xo1.y;
            ao.z += wo0*xo0.z + wo1*xo1.z; ao.w += wo0*xo0.w + wo1*xo1.w;
        }
        for (; p < en; p++) {
            int s = __ldg(&csrc[p]);
            float2 ea = __ldg((const float2*)&eperm[p*2]);
            float2 ds = __ldg(&dis01[s]);
            float wc = ds.x * dv.x * ea.x;
            float wo = ds.y * dv.y * ea.y;
            float4 xc = tc4[s*32 + lane];
            float4 xo = to4[s*32 + lane];
            ac.x += wc*xc.x; ac.y += wc*xc.y; ac.z += wc*xc.z; ac.w += wc*xc.w;
            ao.x += wo*xo.x; ao.y += wo*xo.y; ao.z += wo*xo.z; ao.w += wo*xo.w;
        }
        // conv bias + ELU + pool
        float zc[4] = {ac.x+bc.x, ac.y+bc.y, ac.z+bc.z, ac.w+bc.w};
        float zo[4] = {ao.x+bo.x, ao.y+bo.y, ao.z+bo.z, ao.w+bo.w};
        #pragma unroll
        for (int j = 0; j < 4; j++) {
            zc[j] = (zc[j] > 0.f) ? zc[j] : expm1f(zc[j]);
            zo[j] = (zo[j] > 0.f) ? zo[j] : expm1f(zo[j]);
        }
        int g = __ldg(&batch[v]);
        float* pc = cat + g*256 + lane*4;
        float* po = pc + 128;
        asm volatile("red.global.add.v4.f32 [%0], {%1, %2, %3, %4};"
                     :: "l"(pc), "f"(zc[0]), "f"(zc[1]), "f"(zc[2]), "f"(zc[3]) : "memory");
        asm volatile("red.global.add.v4.f32 [%0], {%1, %2, %3, %4};"
                     :: "l"(po), "f"(zo[0]), "f"(zo[1]), "f"(zo[2]), "f"(zo[3]) : "memory");
    }
}

// ---------------- attention ----------------
__global__ void edge_att_kernel(const int* __restrict__ src, const int* __restrict__ dst,
                                const int* __restrict__ pos,
                                const float* __restrict__ epro, const float* __restrict__ eb,
                                float* __restrict__ eperm, float2* __restrict__ deg01, int E) {
    int e = blockIdx.x*blockDim.x + threadIdx.x;
    if (e >= E) return;
    int s = src[e], d = dst[e];
    float2 ps = *(const float2*)&epro[s*4];
    float2 qd = *(const float2*)&epro[d*4+2];
    float l0 = ps.x + qd.x + eb[0];
    float l1 = ps.y + qd.y + eb[1];
    float m = fmaxf(l0, l1);
    float e0 = expf(l0 - m), e1 = expf(l1 - m);
    float inv = 1.f/(e0+e1);
    float a0 = e0*inv, a1 = e1*inv;
    int p = pos[e];
    *(float2*)&eperm[p*2] = make_float2(a0, a1);
    asm volatile("red.global.add.v2.f32 [%0], {%1, %2};"
                 :: "l"(&deg01[s]), "f"(a0), "f"(a1) : "memory");
}

__global__ void natt_gather(const float* __restrict__ t2,
                            const int* __restrict__ rowptr, const int* __restrict__ csrc,
                            const float* __restrict__ disU,
                            const float* __restrict__ nab,
                            float* __restrict__ natt, int n) {
    int v = blockIdx.x*blockDim.x + threadIdx.x;
    if (v >= n) return;
    float dv = disU[v];
    float d2 = dv*dv;
    float a0 = t2[v*2+0]*d2, a1 = t2[v*2+1]*d2;
    int p = rowptr[v], en = rowptr[v+1];
    for (; p + 4 <= en; p += 4) {
        int s0 = __ldg(&csrc[p+0]);
        int s1 = __ldg(&csrc[p+1]);
        int s2 = __ldg(&csrc[p+2]);
        int s3 = __ldg(&csrc[p+3]);
        float w0 = __ldg(&disU[s0]);
        float w1 = __ldg(&disU[s1]);
        float w2 = __ldg(&disU[s2]);
        float w3 = __ldg(&disU[s3]);
        float2 x0 = __ldg((const float2*)&t2[s0*2]);
        float2 x1 = __ldg((const float2*)&t2[s1*2]);
        float2 x2 = __ldg((const float2*)&t2[s2*2]);
        float2 x3 = __ldg((const float2*)&t2[s3*2]);
        w0 *= dv; w1 *= dv; w2 *= dv; w3 *= dv;
        a0 += w0*x0.x + w1*x1.x + w2*x2.x + w3*x3.x;
        a1 += w0*x0.y + w1*x1.y + w2*x2.y + w3*x3.y;
    }
    for (; p < en; p++) {
        int s = __ldg(&csrc[p]);
        float w = __ldg(&disU[s])*dv;
        float2 ts = __ldg((const float2*)&t2[s*2]);
        a0 += w*ts.x;
        a1 += w*ts.y;
    }
    a0 += nab[0]; a1 += nab[1];
    float m = fmaxf(a0, a1);
    float e0 = expf(a0 - m), e1 = expf(a1 - m);
    float inv = 1.f/(e0+e1);
    natt[v*2+0] = e0*inv; natt[v*2+1] = e1*inv;
}

// ---------------- fused heads ----------------
__global__ void head_gemm1(const float* __restrict__ cat,
                           const float* __restrict__ mean, const float* __restrict__ rstd,
                           const float* __restrict__ cW1, const float* __restrict__ cb1,
                           const float* __restrict__ oW1, const float* __restrict__ ob1,
                           const float* __restrict__ coW1, const float* __restrict__ cob1,
                           float* __restrict__ hd) {
    __shared__ float a[256];
    int r = blockIdx.x, head = blockIdx.y;
    for (int k = threadIdx.x; k < 256; k += 128)
        a[k] = (cat[r*256 + k] - mean[k]) * rstd[k] + BNB;
    __syncthreads();
    const float* W; const float* b; int K, koff, act;
    if (head == 0)      { W = cW1;  b = cb1;  K = 128; koff = 0;   act = 1; }
    else if (head == 1) { W = oW1;  b = ob1;  K = 128; koff = 128; act = 1; }
    else                { W = coW1; b = cob1; K = 256; koff = 0;   act = 2; }
    int c = threadIdx.x;
    float acc = b[c];
    for (int k = 0; k < K; k++) acc += a[koff + k] * W[k*128 + c];
    if (act == 1) acc = fmaxf(acc, 0.f);
    else {
        acc = (acc > 0.f) ? acc : expm1f(acc);
        acc = (acc > 0.f) ? acc : expm1f(acc);
    }
    hd[(head*Gg + r)*128 + c] = acc;
}

__global__ void head_gemm2_lsm(const float* __restrict__ hd,
                               const float* __restrict__ mean, const float* __restrict__ rstd,
                               const float* __restrict__ cW2, const float* __restrict__ cb2,
                               const float* __restrict__ oW2, const float* __restrict__ ob2,
                               const float* __restrict__ coW2, const float* __restrict__ cob2,
                               float* __restrict__ out) {
    __shared__ float a[128];
    __shared__ float lg[COUT];
    int r = blockIdx.x, head = blockIdx.y;
    int k = threadIdx.x;
    a[k] = (hd[(head*Gg + r)*128 + k] - mean[head*128 + k]) * rstd[head*128 + k] + BNB;
    __syncthreads();
    const float* W = (head == 0) ? cW2 : (head == 1) ? oW2 : coW2;
    const float* b = (head == 0) ? cb2 : (head == 1) ? ob2 : cob2;
    if (k < COUT) {
        float acc = b[k];
        for (int kk = 0; kk < 128; kk++) acc += a[kk] * W[kk*COUT + k];
        lg[k] = acc;
    }
    __syncthreads();
    if (k < COUT) {
        float m = -1e30f;
        #pragma unroll
        for (int i = 0; i < COUT; i++) m = fmaxf(m, lg[i]);
        float s = 0.f;
        #pragma unroll
        for (int i = 0; i < COUT; i++) s += expf(lg[i] - m);
        out[head*Gg*COUT + r*COUT + k] = lg[k] - m - logf(s);
    }
}

// ---------------- host orchestration ----------------
extern "C" void kernel_launch(void* const* d_in, const int* in_sizes, int n_in,
                              void* d_out, int out_size) {
    const float* x      = (const float*)d_in[0];
    const float* W_feat = (const float*)d_in[1];
    const float* conv_Ws= (const float*)d_in[2];
    const float* conv_bs= (const float*)d_in[3];
    const float* eW     = (const float*)d_in[4];
    const float* eb     = (const float*)d_in[5];
    const float* naW    = (const float*)d_in[6];
    const float* nab    = (const float*)d_in[7];
    const float* xcW    = (const float*)d_in[8];
    const float* xcb    = (const float*)d_in[9];
    const float* xoW    = (const float*)d_in[10];
    const float* xob    = (const float*)d_in[11];
    const float* cW1    = (const float*)d_in[12];
    const float* cb1    = (const float*)d_in[13];
    const float* cW2    = (const float*)d_in[14];
    const float* cb2    = (const float*)d_in[15];
    const float* oW1    = (const float*)d_in[16];
    const float* ob1    = (const float*)d_in[17];
    const float* oW2    = (const float*)d_in[18];
    const float* ob2    = (const float*)d_in[19];
    const float* coW1   = (const float*)d_in[20];
    const float* cob1   = (const float*)d_in[21];
    const float* coW2   = (const float*)d_in[22];
    const float* cob2   = (const float*)d_in[23];
    const int* esrc     = (const int*)d_in[24];
    const int* edst     = (const int*)d_in[25];
    const int* batch    = (const int*)d_in[26];
    float* out = (float*)d_out;

    float *p_h,*p_t,*p_t2b,*p_stats,*p_mean,*p_rstd,*p_disU;
    float *p_epro,*p_t2,*p_natt,*p_eperm,*p_bias2,*p_cat,*p_hd;
    float2* p_deg01;
    int *p_gstart,*p_cnt,*p_incl,*p_bsum,*p_rowptr,*p_cursor,*p_csrc,*p_pos;
    cudaGetSymbolAddress((void**)&p_h, g_h);
    cudaGetSymbolAddress((void**)&p_t, g_t);
    cudaGetSymbolAddress((void**)&p_t2b, g_t2b);
    cudaGetSymbolAddress((void**)&p_stats, g_stats);
    cudaGetSymbolAddress((void**)&p_mean, g_mean);
    cudaGetSymbolAddress((void**)&p_rstd, g_rstd);
    cudaGetSymbolAddress((void**)&p_disU, g_disU);
    cudaGetSymbolAddress((void**)&p_deg01, g_deg01);
    cudaGetSymbolAddress((void**)&p_epro, g_epro);
    cudaGetSymbolAddress((void**)&p_t2, g_t2);
    cudaGetSymbolAddress((void**)&p_natt, g_natt);
    cudaGetSymbolAddress((void**)&p_eperm, g_eperm);
    cudaGetSymbolAddress((void**)&p_bias2, g_bias2);
    cudaGetSymbolAddress((void**)&p_cat, g_cat);
    cudaGetSymbolAddress((void**)&p_hd, g_hd);
    cudaGetSymbolAddress((void**)&p_gstart, g_gstart);
    cudaGetSymbolAddress((void**)&p_cnt, g_cnt);
    cudaGetSymbolAddress((void**)&p_incl, g_incl);
    cudaGetSymbolAddress((void**)&p_bsum, g_bsum);
    cudaGetSymbolAddress((void**)&p_rowptr, g_rowptr);
    cudaGetSymbolAddress((void**)&p_cursor, g_cursor);
    cudaGetSymbolAddress((void**)&p_csrc, g_csrc);
    cudaGetSymbolAddress((void**)&p_pos, g_pos);

    cudaFuncSetAttribute(gemm128, cudaFuncAttributeMaxDynamicSharedMemorySize, GEMM_SMEM);
    cudaFuncSetAttribute(gemm256, cudaFuncAttributeMaxDynamicSharedMemorySize, GEMM_SMEM);

    const int N = Nn, E = Ee, G = Gg;
    const int NB = (N + 63) / 64;
    const int NT = (N + 255) / 256;
    const int ET = (E + 255) / 256;
    const int GB = 1024;
    const int NSCAN = (N + 1023) / 1024;

    // ---- CSR build + degrees + group starts ----
    init_kernel<<<NT,256>>>(p_disU, p_deg01, p_cnt, N);
    deg_hist<<<ET,256>>>(esrc, edst, p_disU, p_cnt, E);
    scan_block<<<NSCAN,1024>>>(p_cnt, p_incl, p_bsum, N);
    scan_tops<<<1,32>>>(p_bsum, NSCAN);
    make_rowptr<<<NT,256>>>(p_cnt, p_incl, p_bsum, p_rowptr, p_cursor, p_disU, N, E);
    fill_csr<<<ET,256>>>(esrc, edst, p_cursor, p_csrc, p_pos, E);
    gstart_kernel<<<NT,256>>>(batch, p_gstart, N, G);

    // ---- h = relu(BN(x) @ W_feat), h-stats fused ----
    colstats<<<512,256>>>(x, N, p_stats);
    finalize_stats<<<1,256>>>(p_stats, 128, 1.f/N, p_mean, p_rstd);
    gemm128<<<NB,256,GEMM_SMEM>>>(x, p_mean, p_rstd, W_feat, p_h, p_stats, N, 1);
    finalize_stats<<<1,256>>>(p_stats, 128, 1.f/N, p_mean, p_rstd);

    // ---- 3 GCN layers ----
    for (int l = 0; l < 3; l++) {
        gemm128<<<NB,256,GEMM_SMEM>>>(p_h, p_mean, p_rstd,
                                      conv_Ws + l*128*128, p_t, nullptr, N, 0);
        if (l < 2) {
            gather128<<<GB,256>>>(p_t, p_rowptr, p_csrc, p_disU,
                                  conv_bs + l*128, p_h, p_stats,
                                  nullptr, nullptr, nullptr, nullptr, N, 1);
            finalize_stats<<<1,256>>>(p_stats, 128, 1.f/N, p_mean, p_rstd);
        } else {
            gather128<<<GB,256>>>(p_t, p_rowptr, p_csrc, p_disU,
                                  conv_bs + l*128, p_h, nullptr,
                                  eW, naW, p_epro, p_t2, N, 1);
        }
    }

    // ---- attention ----
    edge_att_kernel<<<ET,256>>>(esrc, edst, p_pos, p_epro, eb, p_eperm, p_deg01, E);
    rsqrt_arr<<<(2*N+255)/256,256>>>((float*)p_deg01, 2*N);
    natt_gather<<<NT,256>>>(p_t2, p_rowptr, p_csrc, p_disU, nab, p_natt, N);

    // ---- XC / XO stats (one fused pass over h) ----
    colstats2<<<512,256>>>(p_h, p_natt, N, p_stats);
    finalize2<<<1,256>>>(p_stats, 1.f/N, p_mean, p_rstd);

    // ---- merged XC/XO GEMM + fused gather/pool ----
    bias_kernel<<<2,128>>>(p_mean, p_rstd, xcW, xoW, p_bias2);
    gemm256<<<NB,256,GEMM_SMEM>>>(p_h, p_natt, p_rstd, xcW, xoW, p_bias2,
                                  p_t, p_t2b, N);
    cudaMemsetAsync(p_cat, 0, Gg*256*sizeof(float));
    gather2<<<GB,256>>>(p_t, p_t2b, p_rowptr, p_csrc, p_deg01, p_eperm,
                        xcb, xob, batch, p_cat, N);

    // ---- heads (fused) ----
    head_stats<<<256,128>>>(p_cat, 256, G, p_mean, p_rstd);
    dim3 hg1(G, 3);
    head_gemm1<<<hg1,128>>>(p_cat, p_mean, p_rstd, cW1, cb1, oW1, ob1,
                            coW1, cob1, p_hd);
    head_stats3<<<384,128>>>(p_hd, G, p_mean, p_rstd);
    dim3 hg2(G, 3);
    head_gemm2_lsm<<<hg2,128>>>(p_hd, p_mean, p_rstd, cW2, cb2, oW2, ob2,
                                coW2, cob2, out);
}

// round 10
// speedup vs baseline: 1.7012x; 1.0325x over previous
#include <cuda_runtime.h>
#include <math.h>

#define Nn 50000
#define Ee 400000
#define Hh 128
#define Gg 512
#define COUT 10

typedef unsigned long long u64;

static constexpr float EPSBN = 1e-5f;
static constexpr float BNB   = 1e-4f;

// ---------------- scratch (static device allocations) ----------------
__device__ float g_h[Nn*Hh];
__device__ float g_t[Nn*Hh];
__device__ float g_t2b[Nn*Hh];
__device__ float g_stats[512];      // zero-init; every consumer re-zeroes
__device__ float g_mean[512];
__device__ float g_rstd[512];
__device__ float g_disU[Nn];
__device__ float2 g_deg01[Nn];
__device__ float g_epro[Nn*4];
__device__ float g_t2[Nn*2];
__device__ float g_natt[Nn*2];
__device__ float g_eperm[Ee*2];
__device__ float g_bias2[256];
__device__ float g_cat[Gg*256];
__device__ float g_hd[3*Gg*128];
// CSR by destination
__device__ int g_cnt[Nn];
__device__ int g_incl[Nn];
__device__ int g_bsum[64];
__device__ int g_rowptr[Nn+1];
__device__ int g_cursor[Nn];
__device__ int g_csrc[Ee];
__device__ int g_pos[Ee];

// ---------------- small utility kernels ----------------
__global__ void init_kernel(float* disU, float2* deg01, int* cnt, int n) {
    int i = blockIdx.x*blockDim.x + threadIdx.x;
    if (i < n) { disU[i] = 1.f; deg01[i] = make_float2(1.f, 1.f); cnt[i] = 0; }
}

__global__ void deg_hist(const int* __restrict__ src, const int* __restrict__ dst,
                         float* degU, int* cnt, int E) {
    int i = blockIdx.x*blockDim.x + threadIdx.x;
    if (i < E) {
        atomicAdd(&degU[src[i]], 1.0f);
        atomicAdd(&cnt[dst[i]], 1);
    }
}

__global__ void rsqrt_arr(float* p, int n) {
    int i = blockIdx.x*blockDim.x + threadIdx.x;
    if (i < n) p[i] = rsqrtf(p[i]);
}

// ---------------- CSR build ----------------
__global__ void scan_block(const int* __restrict__ cnt, int* incl, int* bsum, int n) {
    __shared__ int sm[1024];
    int i = blockIdx.x*1024 + threadIdx.x;
    sm[threadIdx.x] = (i < n) ? cnt[i] : 0;
    __syncthreads();
    for (int off = 1; off < 1024; off <<= 1) {
        int t = (threadIdx.x >= off) ? sm[threadIdx.x - off] : 0;
        __syncthreads();
        sm[threadIdx.x] += t;
        __syncthreads();
    }
    if (i < n) incl[i] = sm[threadIdx.x];
    if (threadIdx.x == 1023) bsum[blockIdx.x] = sm[1023];
}

__global__ void scan_tops(int* bsum, int nb) {
    int lane = threadIdx.x;
    int v0 = (lane < nb) ? bsum[lane] : 0;
    int v1 = (32 + lane < nb) ? bsum[32 + lane] : 0;
    #pragma unroll
    for (int o = 1; o < 32; o <<= 1) {
        int t = __shfl_up_sync(0xffffffffu, v0, o);
        if (lane >= o) v0 += t;
    }
    int tot0 = __shfl_sync(0xffffffffu, v0, 31);
    #pragma unroll
    for (int o = 1; o < 32; o <<= 1) {
        int t = __shfl_up_sync(0xffffffffu, v1, o);
        if (lane >= o) v1 += t;
    }
    v1 += tot0;
    if (lane < nb) bsum[lane] = v0;
    if (32 + lane < nb) bsum[32 + lane] = v1;
}

__global__ void make_rowptr(const int* __restrict__ cnt, const int* __restrict__ incl,
                            const int* __restrict__ bsum,
                            int* rowptr, int* cursor, float* disU, int n, int E) {
    int i = blockIdx.x*blockDim.x + threadIdx.x;
    if (i < n) {
        int b = i >> 10;
        int ex = incl[i] - cnt[i] + ((b > 0) ? bsum[b-1] : 0);
        rowptr[i] = ex;
        cursor[i] = ex;
        disU[i] = rsqrtf(disU[i]);
    }
    if (i == 0) rowptr[n] = E;
}

__global__ void fill_csr(const int* __restrict__ src, const int* __restrict__ dst,
                         int* cursor, int* csrc, int* pos, int E) {
    int e = blockIdx.x*blockDim.x + threadIdx.x;
    if (e < E) {
        int p = atomicAdd(&cursor[dst[e]], 1);
        csrc[p] = src[e];
        pos[e] = p;
    }
}

// ---------------- BatchNorm stats ----------------
__global__ void colstats(const float* __restrict__ A, int n, float* sums) {
    long total  = (long)n * 128;
    long stride = (long)gridDim.x * blockDim.x;
    long i0     = (long)blockIdx.x*blockDim.x + threadIdx.x;
    if (i0 >= total) return;
    int c = (int)(i0 % 128);
    float s0 = 0.f, s1 = 0.f;
    for (long i = i0; i < total; i += stride) {
        int r = (int)(i / 128);
        float v = A[(long)r*128 + c];
        s0 += v; s1 += v*v;
    }
    atomicAdd(&sums[c], s0);
    atomicAdd(&sums[128+c], s1);
}

__global__ void colstats2(const float* __restrict__ A, const float* __restrict__ natt,
                          int n, float* sums) {
    long total  = (long)n * 128;
    long stride = (long)gridDim.x * blockDim.x;
    long i0     = (long)blockIdx.x*blockDim.x + threadIdx.x;
    if (i0 >= total) return;
    int c = (int)(i0 % 128);
    float s00=0.f, s01=0.f, s10=0.f, s11=0.f;
    for (long i = i0; i < total; i += stride) {
        int r = (int)(i / 128);
        float v = A[(long)r*128 + c];
        float v0 = v * natt[r*2+0];
        float v1 = v * natt[r*2+1];
        s00 += v0; s01 += v0*v0;
        s10 += v1; s11 += v1*v1;
    }
    atomicAdd(&sums[c], s00);
    atomicAdd(&sums[128+c], s01);
    atomicAdd(&sums[256+c], s10);
    atomicAdd(&sums[384+c], s11);
}

__global__ void finalize_stats(float* sums, int C, float inv_n,
                               float* mean, float* rstd) {
    int c = threadIdx.x + blockIdx.x*blockDim.x;
    if (c < C) {
        float s0 = sums[c], s1 = sums[C+c];
        sums[c] = 0.f; sums[C+c] = 0.f;
        float m = s0*inv_n;
        float var = s1*inv_n - m*m;
        mean[c] = m;
        rstd[c] = rsqrtf(var + EPSBN);
    }
}

__global__ void finalize2(float* sums, float inv_n, float* mean, float* rstd) {
    int c = threadIdx.x;               // 0..255
    int ch = c >> 7, cc = c & 127;
    float s0 = sums[ch*256 + cc], s1 = sums[ch*256 + 128 + cc];
    sums[ch*256 + cc] = 0.f; sums[ch*256 + 128 + cc] = 0.f;
    float m = s0*inv_n;
    float var = s1*inv_n - m*m;
    mean[c] = m;
    rstd[c] = rsqrtf(var + EPSBN);
}

__global__ void head_stats(const float* __restrict__ A, int lda, int n,
                           float* mean, float* rstd) {
    __shared__ float s0s[4], s1s[4];
    int c = blockIdx.x;
    int lane = threadIdx.x & 31, warp = threadIdx.x >> 5;
    float s0 = 0.f, s1 = 0.f;
    for (int r = threadIdx.x; r < n; r += blockDim.x) {
        float v = A[r*lda + c];
        s0 += v; s1 += v*v;
    }
    #pragma unroll
    for (int o = 16; o; o >>= 1) {
        s0 += __shfl_xor_sync(0xffffffffu, s0, o);
        s1 += __shfl_xor_sync(0xffffffffu, s1, o);
    }
    if (lane == 0) { s0s[warp] = s0; s1s[warp] = s1; }
    __syncthreads();
    if (threadIdx.x == 0) {
        float t0 = 0.f, t1 = 0.f;
        for (int w = 0; w < 4; w++) { t0 += s0s[w]; t1 += s1s[w]; }
        float m = t0 / n;
        float var = t1 / n - m*m;
        mean[c] = m;
        rstd[c] = rsqrtf(var + EPSBN);
    }
}

__global__ void head_stats3(const float* __restrict__ hd, int n,
                            float* mean, float* rstd) {
    __shared__ float s0s[4], s1s[4];
    int cg = blockIdx.x;
    int head = cg >> 7, c = cg & 127;
    const float* A = hd + head*Gg*128;
    int lane = threadIdx.x & 31, warp = threadIdx.x >> 5;
    float s0 = 0.f, s1 = 0.f;
    for (int r = threadIdx.x; r < n; r += blockDim.x) {
        float v = A[r*128 + c];
        s0 += v; s1 += v*v;
    }
    #pragma unroll
    for (int o = 16; o; o >>= 1) {
        s0 += __shfl_xor_sync(0xffffffffu, s0, o);
        s1 += __shfl_xor_sync(0xffffffffu, s1, o);
    }
    if (lane == 0) { s0s[warp] = s0; s1s[warp] = s1; }
    __syncthreads();
    if (threadIdx.x == 0) {
        float t0 = 0.f, t1 = 0.f;
        for (int w = 0; w < 4; w++) { t0 += s0s[w]; t1 += s1s[w]; }
        float m = t0 / n;
        float var = t1 / n - m*m;
        mean[cg] = m;
        rstd[cg] = rsqrtf(var + EPSBN);
    }
}

__global__ void bias_kernel(const float* __restrict__ mean, const float* __restrict__ rstd,
                            const float* __restrict__ xcW, const float* __restrict__ xoW,
                            float* __restrict__ bias2) {
    __shared__ float coef[128];
    int hh = blockIdx.x;
    int j = threadIdx.x;
    const float* W = hh ? xoW : xcW;
    coef[j] = BNB - mean[hh*128+j]*rstd[hh*128+j];
    __syncthreads();
    float acc = 0.f;
    for (int k = 0; k < 128; k++) acc += coef[k]*W[k*128+j];
    bias2[hh*128+j] = acc;
}

// ---------------- big GEMM (packed f32x2 FMA, BM=64) ----------------
static constexpr int GEMM_SMEM = (64*128 + 128*128) * 4;

__global__ __launch_bounds__(256) void gemm128(
    const float* __restrict__ A,
    const float* __restrict__ mean, const float* __restrict__ rstd,
    const float* __restrict__ W,
    float* __restrict__ out,
    float* __restrict__ sums,
    int n, int act)
{
    extern __shared__ float sm[];
    float* As = sm;               // [64][128]
    float* Ws = sm + 64*128;      // [128][128]
    int tid  = threadIdx.x;
    int row0 = blockIdx.x * 64;

    const float4* Wg = (const float4*)W;
    float4* Ws4 = (float4*)Ws;
    #pragma unroll 4
    for (int i = tid; i < 128*32; i += 256) Ws4[i] = Wg[i];

    #pragma unroll 2
    for (int i = tid; i < 64*32; i += 256) {
        int r = i >> 5, cq = i & 31;
        int gr = row0 + r;
        float4 v = make_float4(0.f,0.f,0.f,0.f);
        if (gr < n) {
            v = ((const float4*)A)[gr*32 + cq];
            int c = cq*4;
            v.x = (v.x - mean[c+0])*rstd[c+0] + BNB;
            v.y = (v.y - mean[c+1])*rstd[c+1] + BNB;
            v.z = (v.z - mean[c+2])*rstd[c+2] + BNB;
            v.w = (v.w - mean[c+3])*rstd[c+3] + BNB;
        }
        ((float4*)As)[i] = v;
    }
    __syncthreads();

    int tc = tid & 15, tr = tid >> 4;
    int r0 = tr*4;
    int c0 = tc*4, c1 = 64 + tc*4;

    u64 accp[4][4];
    #pragma unroll
    for (int i = 0; i < 4; i++)
        #pragma unroll
        for (int j = 0; j < 4; j++) accp[i][j] = 0ull;

    for (int k = 0; k < 128; k += 4) {
        float4 a4[4];
        #pragma unroll
        for (int i = 0; i < 4; i++)
            a4[i] = *(const float4*)&As[(r0+i)*128 + k];
        #pragma unroll
        for (int kk = 0; kk < 4; kk++) {
            ulonglong2 w01 = *(const ulonglong2*)&Ws[(k+kk)*128 + c0];
            ulonglong2 w23 = *(const ulonglong2*)&Ws[(k+kk)*128 + c1];
            u64 wp0 = w01.x, wp1 = w01.y, wp2 = w23.x, wp3 = w23.y;
            #pragma unroll
            for (int i = 0; i < 4; i++) {
                float a = ((const float*)&a4[i])[kk];
                unsigned int ai = __float_as_uint(a);
                u64 ap;
                asm("mov.b64 %0, {%1, %1};" : "=l"(ap) : "r"(ai));
                asm("fma.rn.f32x2 %0, %1, %2, %0;" : "+l"(accp[i][0]) : "l"(ap), "l"(wp0));
                asm("fma.rn.f32x2 %0, %1, %2, %0;" : "+l"(accp[i][1]) : "l"(ap), "l"(wp1));
                asm("fma.rn.f32x2 %0, %1, %2, %0;" : "+l"(accp[i][2]) : "l"(ap), "l"(wp2));
                asm("fma.rn.f32x2 %0, %1, %2, %0;" : "+l"(accp[i][3]) : "l"(ap), "l"(wp3));
            }
        }
    }

    float t0[8], t1[8];
    #pragma unroll
    for (int j = 0; j < 8; j++) { t0[j] = 0.f; t1[j] = 0.f; }

    float4* O4 = (float4*)out;
    #pragma unroll
    for (int i = 0; i < 4; i++) {
        int gr = row0 + r0 + i;
        if (gr < n) {
            float o[8];
            #pragma unroll
            for (int j = 0; j < 4; j++) {
                unsigned int lo, hi;
                asm("mov.b64 {%0, %1}, %2;" : "=r"(lo), "=r"(hi) : "l"(accp[i][j]));
                o[2*j]   = __uint_as_float(lo);
                o[2*j+1] = __uint_as_float(hi);
            }
            if (act == 1) {
                #pragma unroll
                for (int j = 0; j < 8; j++) o[j] = fmaxf(o[j], 0.f);
            }
            if (sums) {
                #pragma unroll
                for (int j = 0; j < 8; j++) { t0[j] += o[j]; t1[j] += o[j]*o[j]; }
            }
            O4[gr*32 + tc]      = make_float4(o[0], o[1], o[2], o[3]);
            O4[gr*32 + 16 + tc] = make_float4(o[4], o[5], o[6], o[7]);
        }
    }

    if (sums) {
        __syncthreads();
        float* ss = sm;
        ss[tid] = 0.f;
        __syncthreads();
        #pragma unroll
        for (int j = 0; j < 4; j++) {
            atomicAdd(&ss[c0+j],     t0[j]);   atomicAdd(&ss[128+c0+j], t1[j]);
            atomicAdd(&ss[c1+j],     t0[4+j]); atomicAdd(&ss[128+c1+j], t1[4+j]);
        }
        __syncthreads();
        atomicAdd(&sums[tid], ss[tid]);
    }
}

// ---------------- merged XC/XO GEMM ----------------
__global__ __launch_bounds__(256) void gemm256(
    const float* __restrict__ h,
    const float* __restrict__ natt,
    const float* __restrict__ rstd2,
    const float* __restrict__ xcW, const float* __restrict__ xoW,
    const float* __restrict__ bias2,
    float* __restrict__ outc, float* __restrict__ outo, int n)
{
    extern __shared__ float sm[];
    float* As = sm;               // [64][128]
    float* Ws = sm + 64*128;      // [128][128]
    int tid  = threadIdx.x;
    int row0 = blockIdx.x * 64;

    #pragma unroll 2
    for (int i = tid; i < 64*32; i += 256) {
        int r = i >> 5, cq = i & 31;
        int gr = row0 + r;
        float4 v = (gr < n) ? ((const float4*)h)[gr*32 + cq]
                            : make_float4(0.f,0.f,0.f,0.f);
        ((float4*)As)[i] = v;
    }

    int tc = tid & 15, tr = tid >> 4;
    int r0 = tr*4;
    int c0 = tc*4, c1 = 64 + tc*4;

    #pragma unroll
    for (int half = 0; half < 2; half++) {
        const float* W  = half ? xoW : xcW;
        const float* rs = rstd2 + half*128;
        const float* bs = bias2 + half*128;
        float* out = half ? outo : outc;

        __syncthreads();
        for (int i = tid; i < 128*32; i += 256) {
            int k = i >> 5;
            float4 w = ((const float4*)W)[i];
            float sc = rs[k];
            w.x *= sc; w.y *= sc; w.z *= sc; w.w *= sc;
            ((float4*)Ws)[i] = w;
        }
        __syncthreads();

        float nv[4];
        #pragma unroll
        for (int i = 0; i < 4; i++) {
            int gr = row0 + r0 + i;
            nv[i] = (gr < n) ? natt[gr*2 + half] : 0.f;
        }

        u64 accp[4][4];
        #pragma unroll
        for (int i = 0; i < 4; i++)
            #pragma unroll
            for (int j = 0; j < 4; j++) accp[i][j] = 0ull;

        for (int k = 0; k < 128; k += 4) {
            float4 a4[4];
            #pragma unroll
            for (int i = 0; i < 4; i++)
                a4[i] = *(const float4*)&As[(r0+i)*128 + k];
            #pragma unroll
            for (int kk = 0; kk < 4; kk++) {
                ulonglong2 w01 = *(const ulonglong2*)&Ws[(k+kk)*128 + c0];
                ulonglong2 w23 = *(const ulonglong2*)&Ws[(k+kk)*128 + c1];
                u64 wp0 = w01.x, wp1 = w01.y, wp2 = w23.x, wp3 = w23.y;
                #pragma unroll
                for (int i = 0; i < 4; i++) {
                    float a = ((const float*)&a4[i])[kk] * nv[i];
                    unsigned int ai = __float_as_uint(a);
                    u64 ap;
                    asm("mov.b64 %0, {%1, %1};" : "=l"(ap) : "r"(ai));
                    asm("fma.rn.f32x2 %0, %1, %2, %0;" : "+l"(accp[i][0]) : "l"(ap), "l"(wp0));
                    asm("fma.rn.f32x2 %0, %1, %2, %0;" : "+l"(accp[i][1]) : "l"(ap), "l"(wp1));
                    asm("fma.rn.f32x2 %0, %1, %2, %0;" : "+l"(accp[i][2]) : "l"(ap), "l"(wp2));
                    asm("fma.rn.f32x2 %0, %1, %2, %0;" : "+l"(accp[i][3]) : "l"(ap), "l"(wp3));
                }
            }
        }

        float4 b0 = *(const float4*)&bs[c0];
        float4 b1 = *(const float4*)&bs[c1];
        float4* O4 = (float4*)out;
        #pragma unroll
        for (int i = 0; i < 4; i++) {
            int gr = row0 + r0 + i;
            if (gr < n) {
                float o[8];
                #pragma unroll
                for (int j = 0; j < 4; j++) {
                    unsigned int lo, hi;
                    asm("mov.b64 {%0, %1}, %2;" : "=r"(lo), "=r"(hi) : "l"(accp[i][j]));
                    o[2*j]   = __uint_as_float(lo);
                    o[2*j+1] = __uint_as_float(hi);
                }
                O4[gr*32 + tc]      = make_float4(o[0]+b0.x, o[1]+b0.y, o[2]+b0.z, o[3]+b0.w);
                O4[gr*32 + 16 + tc] = make_float4(o[4]+b1.x, o[5]+b1.y, o[6]+b1.z, o[7]+b1.w);
            }
        }
    }
}

// ---------------- CSR gather conv (MLP-4) ----------------
__global__ __launch_bounds__(256) void gather128(
    const float* __restrict__ t,
    const int* __restrict__ rowptr, const int* __restrict__ csrc,
    const float* __restrict__ dis,
    const float* __restrict__ bias,
    float* __restrict__ out, float* __restrict__ sums,
    const float* __restrict__ eWg, const float* __restrict__ naWg,
    float* __restrict__ epro, float* __restrict__ t2,
    int n, int act)
{
    __shared__ float sEW[512];
    __shared__ float sNA[256];
    if (eWg) {
        for (int i = threadIdx.x; i < 512; i += 256) sEW[i] = eWg[i];
        for (int i = threadIdx.x; i < 256; i += 256) sNA[i] = naWg[i];
        __syncthreads();
    }
    int lane = threadIdx.x & 31;
    int w0 = (blockIdx.x*blockDim.x + threadIdx.x) >> 5;
    int nw = (gridDim.x*blockDim.x) >> 5;
    float4 bb = bias ? ((const float4*)bias)[lane] : make_float4(0.f,0.f,0.f,0.f);
    float ls0[4] = {0.f,0.f,0.f,0.f}, ls1[4] = {0.f,0.f,0.f,0.f};
    const float4* t4 = (const float4*)t;

    for (int v = w0; v < n; v += nw) {
        float dv = dis[v];
        float4 acc = t4[v*32 + lane];
        float d2 = dv*dv;
        acc.x *= d2; acc.y *= d2; acc.z *= d2; acc.w *= d2;
        int p = rowptr[v], en = rowptr[v+1];
        for (; p + 4 <= en; p += 4) {
            int s0 = __ldg(&csrc[p+0]);
            int s1 = __ldg(&csrc[p+1]);
            int s2 = __ldg(&csrc[p+2]);
            int s3 = __ldg(&csrc[p+3]);
            float w0_ = __ldg(&dis[s0]);
            float w1_ = __ldg(&dis[s1]);
            float w2_ = __ldg(&dis[s2]);
            float w3_ = __ldg(&dis[s3]);
            float4 x0 = t4[s0*32 + lane];
            float4 x1 = t4[s1*32 + lane];
            float4 x2 = t4[s2*32 + lane];
            float4 x3 = t4[s3*32 + lane];
            w0_ *= dv; w1_ *= dv; w2_ *= dv; w3_ *= dv;
            acc.x += w0_*x0.x + w1_*x1.x + w2_*x2.x + w3_*x3.x;
            acc.y += w0_*x0.y + w1_*x1.y + w2_*x2.y + w3_*x3.y;
            acc.z += w0_*x0.z + w1_*x1.z + w2_*x2.z + w3_*x3.z;
            acc.w += w0_*x0.w + w1_*x1.w + w2_*x2.w + w3_*x3.w;
        }
        for (; p < en; p++) {
            int s = __ldg(&csrc[p]);
            float w = __ldg(&dis[s]) * dv;
            float4 x = t4[s*32 + lane];
            acc.x += w*x.x; acc.y += w*x.y; acc.z += w*x.z; acc.w += w*x.w;
        }
        acc.x += bb.x; acc.y += bb.y; acc.z += bb.z; acc.w += bb.w;
        if (act == 1) {
            acc.x = fmaxf(acc.x, 0.f); acc.y = fmaxf(acc.y, 0.f);
            acc.z = fmaxf(acc.z, 0.f); acc.w = fmaxf(acc.w, 0.f);
        }
        if (sums) {
            ls0[0]+=acc.x; ls1[0]+=acc.x*acc.x;
            ls0[1]+=acc.y; ls1[1]+=acc.y*acc.y;
            ls0[2]+=acc.z; ls1[2]+=acc.z*acc.z;
            ls0[3]+=acc.w; ls1[3]+=acc.w*acc.w;
        }
        ((float4*)out)[v*32 + lane] = acc;

        if (eWg) {
            float hx[4] = {acc.x, acc.y, acc.z, acc.w};
            float p0=0,p1=0,q0=0,q1=0,u0=0,u1=0;
            #pragma unroll
            for (int i = 0; i < 4; i++) {
                int k = lane*4 + i; float xv = hx[i];
                p0 += xv*sEW[k*2+0];        p1 += xv*sEW[k*2+1];
                q0 += xv*sEW[(128+k)*2+0];  q1 += xv*sEW[(128+k)*2+1];
                u0 += xv*sNA[k*2+0];        u1 += xv*sNA[k*2+1];
            }
            #pragma unroll
            for (int o = 16; o; o >>= 1) {
                p0 += __shfl_xor_sync(0xffffffffu, p0, o);
                p1 += __shfl_xor_sync(0xffffffffu, p1, o);
                q0 += __shfl_xor_sync(0xffffffffu, q0, o);
                q1 += __shfl_xor_sync(0xffffffffu, q1, o);
                u0 += __shfl_xor_sync(0xffffffffu, u0, o);
                u1 += __shfl_xor_sync(0xffffffffu, u1, o);
            }
            if (lane == 0) {
                epro[v*4+0]=p0; epro[v*4+1]=p1; epro[v*4+2]=q0; epro[v*4+3]=q1;
                t2[v*2+0]=u0; t2[v*2+1]=u1;
            }
        }
    }

    if (sums) {
        __shared__ float ss[256];
        ss[threadIdx.x] = 0.f;
        __syncthreads();
        #pragma unroll
        for (int j = 0; j < 4; j++) {
            atomicAdd(&ss[lane*4+j],     ls0[j]);
            atomicAdd(&ss[128+lane*4+j], ls1[j]);
        }
        __syncthreads();
        atomicAdd(&sums[threadIdx.x], ss[threadIdx.x]);
    }
}

// fused XC+XO gather + conv-bias + ELU + global_add_pool
__global__ __launch_bounds__(256) void gather2(
    const float* __restrict__ tc_, const float* __restrict__ to_,
    const int* __restrict__ rowptr, const int* __restrict__ csrc,
    const float2* __restrict__ dis01,
    const float* __restrict__ eperm,
    const float* __restrict__ xcb, const float* __restrict__ xob,
    const int* __restrict__ batch,
    float* __restrict__ cat, int n)
{
    int lane = threadIdx.x & 31;
    int w0 = (blockIdx.x*blockDim.x + threadIdx.x) >> 5;
    int nw = (gridDim.x*blockDim.x) >> 5;
    const float4* tc4 = (const float4*)tc_;
    const float4* to4 = (const float4*)to_;
    float4 bc = ((const float4*)xcb)[lane];
    float4 bo = ((const float4*)xob)[lane];

    for (int v = w0; v < n; v += nw) {
        float2 dv = dis01[v];
        float4 ac = tc4[v*32 + lane];
        float4 ao = to4[v*32 + lane];
        float d02 = dv.x*dv.x, d12 = dv.y*dv.y;
        ac.x *= d02; ac.y *= d02; ac.z *= d02; ac.w *= d02;
        ao.x *= d12; ao.y *= d12; ao.z *= d12; ao.w *= d12;
        int p = rowptr[v], en = rowptr[v+1];
        for (; p + 2 <= en; p += 2) {
            int s0 = __ldg(&csrc[p+0]);
            int s1 = __ldg(&csrc[p+1]);
            float2 ea0 = __ldg((const float2*)&eperm[(p+0)*2]);
            float2 ea1 = __ldg((const float2*)&eperm[(p+1)*2]);
            float2 ds0 = __ldg(&dis01[s0]);
            float2 ds1 = __ldg(&dis01[s1]);
            float4 xc0 = tc4[s0*32 + lane];
            float4 xo0 = to4[s0*32 + lane];
            float4 xc1 = tc4[s1*32 + lane];
            float4 xo1 = to4[s1*32 + lane];
            float wc0 = ds0.x * dv.x * ea0.x, wo0 = ds0.y * dv.y * ea0.y;
            float wc1 = ds1.x * dv.x * ea1.x, wo1 = ds1.y * dv.y * ea1.y;
            ac.x += wc0*xc0.x + wc1*xc1.x; ac.y += wc0*xc0.y + wc1*xc1.y;
            ac.z += wc0*xc0.z + wc1*xc1.z; ac.w += wc0*xc0.w + wc1*xc1.w;
            ao.x += wo0*xo0.x + wo1*xo1.x; ao.y += wo0*xo0.y + wo1*xo1.y;
            ao.z += wo0*xo0.z + wo1*xo1.z; ao.w += wo0*xo0.w + wo1*xo1.w;
        }
        for (; p < en; p++) {
            int s = __ldg(&csrc[p]);
            float2 ea = __ldg((const float2*)&eperm[p*2]);
            float2 ds = __ldg(&dis01[s]);
            float wc = ds.x * dv.x * ea.x;
            float wo = ds.y * dv.y * ea.y;
            float4 xc = tc4[s*32 + lane];
            float4 xo = to4[s*32 + lane];
            ac.x += wc*xc.x; ac.y += wc*xc.y; ac.z += wc*xc.z; ac.w += wc*xc.w;
            ao.x += wo*xo.x; ao.y += wo*xo.y; ao.z += wo*xo.z; ao.w += wo*xo.w;
        }
        float zc[4] = {ac.x+bc.x, ac.y+bc.y, ac.z+bc.z, ac.w+bc.w};
        float zo[4] = {ao.x+bo.x, ao.y+bo.y, ao.z+bo.z, ao.w+bo.w};
        #pragma unroll
        for (int j = 0; j < 4; j++) {
            zc[j] = (zc[j] > 0.f) ? zc[j] : expm1f(zc[j]);
            zo[j] = (zo[j] > 0.f) ? zo[j] : expm1f(zo[j]);
        }
        int g = __ldg(&batch[v]);
        float* pc = cat + g*256 + lane*4;
        float* po = pc + 128;
        asm volatile("red.global.add.v4.f32 [%0], {%1, %2, %3, %4};"
                     :: "l"(pc), "f"(zc[0]), "f"(zc[1]), "f"(zc[2]), "f"(zc[3]) : "memory");
        asm volatile("red.global.add.v4.f32 [%0], {%1, %2, %3, %4};"
                     :: "l"(po), "f"(zo[0]), "f"(zo[1]), "f"(zo[2]), "f"(zo[3]) : "memory");
    }
}

// ---------------- attention ----------------
__global__ void edge_att_kernel(const int* __restrict__ src, const int* __restrict__ dst,
                                const int* __restrict__ pos,
                                const float* __restrict__ epro, const float* __restrict__ eb,
                                float* __restrict__ eperm, float2* __restrict__ deg01, int E) {
    int e = blockIdx.x*blockDim.x + threadIdx.x;
    if (e >= E) return;
    int s = src[e], d = dst[e];
    float2 ps = *(const float2*)&epro[s*4];
    float2 qd = *(const float2*)&epro[d*4+2];
    float l0 = ps.x + qd.x + eb[0];
    float l1 = ps.y + qd.y + eb[1];
    float m = fmaxf(l0, l1);
    float e0 = expf(l0 - m), e1 = expf(l1 - m);
    float inv = 1.f/(e0+e1);
    float a0 = e0*inv, a1 = e1*inv;
    int p = pos[e];
    *(float2*)&eperm[p*2] = make_float2(a0, a1);
    asm volatile("red.global.add.v2.f32 [%0], {%1, %2};"
                 :: "l"(&deg01[s]), "f"(a0), "f"(a1) : "memory");
}

__global__ void natt_gather(const float* __restrict__ t2,
                            const int* __restrict__ rowptr, const int* __restrict__ csrc,
                            const float* __restrict__ disU,
                            const float* __restrict__ nab,
                            float* __restrict__ natt, int n) {
    int v = blockIdx.x*blockDim.x + threadIdx.x;
    if (v >= n) return;
    float dv = disU[v];
    float d2 = dv*dv;
    float a0 = t2[v*2+0]*d2, a1 = t2[v*2+1]*d2;
    int p = rowptr[v], en = rowptr[v+1];
    for (; p + 4 <= en; p += 4) {
        int s0 = __ldg(&csrc[p+0]);
        int s1 = __ldg(&csrc[p+1]);
        int s2 = __ldg(&csrc[p+2]);
        int s3 = __ldg(&csrc[p+3]);
        float w0 = __ldg(&disU[s0]);
        float w1 = __ldg(&disU[s1]);
        float w2 = __ldg(&disU[s2]);
        float w3 = __ldg(&disU[s3]);
        float2 x0 = __ldg((const float2*)&t2[s0*2]);
        float2 x1 = __ldg((const float2*)&t2[s1*2]);
        float2 x2 = __ldg((const float2*)&t2[s2*2]);
        float2 x3 = __ldg((const float2*)&t2[s3*2]);
        w0 *= dv; w1 *= dv; w2 *= dv; w3 *= dv;
        a0 += w0*x0.x + w1*x1.x + w2*x2.x + w3*x3.x;
        a1 += w0*x0.y + w1*x1.y + w2*x2.y + w3*x3.y;
    }
    for (; p < en; p++) {
        int s = __ldg(&csrc[p]);
        float w = __ldg(&disU[s])*dv;
        float2 ts = __ldg((const float2*)&t2[s*2]);
        a0 += w*ts.x;
        a1 += w*ts.y;
    }
    a0 += nab[0]; a1 += nab[1];
    float m = fmaxf(a0, a1);
    float e0 = expf(a0 - m), e1 = expf(a1 - m);
    float inv = 1.f/(e0+e1);
    natt[v*2+0] = e0*inv; natt[v*2+1] = e1*inv;
}

// ---------------- fused heads ----------------
__global__ void head_gemm1(const float* __restrict__ cat,
                           const float* __restrict__ mean, const float* __restrict__ rstd,
                           const float* __restrict__ cW1, const float* __restrict__ cb1,
                           const float* __restrict__ oW1, const float* __restrict__ ob1,
                           const float* __restrict__ coW1, const float* __restrict__ cob1,
                           float* __restrict__ hd) {
    __shared__ float a[256];
    int r = blockIdx.x, head = blockIdx.y;
    for (int k = threadIdx.x; k < 256; k += 128)
        a[k] = (cat[r*256 + k] - mean[k]) * rstd[k] + BNB;
    __syncthreads();
    const float* W; const float* b; int K, koff, act;
    if (head == 0)      { W = cW1;  b = cb1;  K = 128; koff = 0;   act = 1; }
    else if (head == 1) { W = oW1;  b = ob1;  K = 128; koff = 128; act = 1; }
    else                { W = coW1; b = cob1; K = 256; koff = 0;   act = 2; }
    int c = threadIdx.x;
    float acc = b[c];
    for (int k = 0; k < K; k++) acc += a[koff + k] * W[k*128 + c];
    if (act == 1) acc = fmaxf(acc, 0.f);
    else {
        acc = (acc > 0.f) ? acc : expm1f(acc);
        acc = (acc > 0.f) ? acc : expm1f(acc);
    }
    hd[(head*Gg + r)*128 + c] = acc;
}

__global__ void head_gemm2_lsm(const float* __restrict__ hd,
                               const float* __restrict__ mean, const float* __restrict__ rstd,
                               const float* __restrict__ cW2, const float* __restrict__ cb2,
                               const float* __restrict__ oW2, const float* __restrict__ ob2,
                               const float* __restrict__ coW2, const float* __restrict__ cob2,
                               float* __restrict__ out) {
    __shared__ float a[128];
    __shared__ float lg[COUT];
    int r = blockIdx.x, head = blockIdx.y;
    int k = threadIdx.x;
    a[k] = (hd[(head*Gg + r)*128 + k] - mean[head*128 + k]) * rstd[head*128 + k] + BNB;
    __syncthreads();
    const float* W = (head == 0) ? cW2 : (head == 1) ? oW2 : coW2;
    const float* b = (head == 0) ? cb2 : (head == 1) ? ob2 : cob2;
    if (k < COUT) {
        float acc = b[k];
        for (int kk = 0; kk < 128; kk++) acc += a[kk] * W[kk*COUT + k];
        lg[k] = acc;
    }
    __syncthreads();
    if (k < COUT) {
        float m = -1e30f;
        #pragma unroll
        for (int i = 0; i < COUT; i++) m = fmaxf(m, lg[i]);
        float s = 0.f;
        #pragma unroll
        for (int i = 0; i < COUT; i++) s += expf(lg[i] - m);
        out[head*Gg*COUT + r*COUT + k] = lg[k] - m - logf(s);
    }
}

// ---------------- host orchestration ----------------
extern "C" void kernel_launch(void* const* d_in, const int* in_sizes, int n_in,
                              void* d_out, int out_size) {
    const float* x      = (const float*)d_in[0];
    const float* W_feat = (const float*)d_in[1];
    const float* conv_Ws= (const float*)d_in[2];
    const float* conv_bs= (const float*)d_in[3];
    const float* eW     = (const float*)d_in[4];
    const float* eb     = (const float*)d_in[5];
    const float* naW    = (const float*)d_in[6];
    const float* nab    = (const float*)d_in[7];
    const float* xcW    = (const float*)d_in[8];
    const float* xcb    = (const float*)d_in[9];
    const float* xoW    = (const float*)d_in[10];
    const float* xob    = (const float*)d_in[11];
    const float* cW1    = (const float*)d_in[12];
    const float* cb1    = (const float*)d_in[13];
    const float* cW2    = (const float*)d_in[14];
    const float* cb2    = (const float*)d_in[15];
    const float* oW1    = (const float*)d_in[16];
    const float* ob1    = (const float*)d_in[17];
    const float* oW2    = (const float*)d_in[18];
    const float* ob2    = (const float*)d_in[19];
    const float* coW1   = (const float*)d_in[20];
    const float* cob1   = (const float*)d_in[21];
    const float* coW2   = (const float*)d_in[22];
    const float* cob2   = (const float*)d_in[23];
    const int* esrc     = (const int*)d_in[24];
    const int* edst     = (const int*)d_in[25];
    const int* batch    = (const int*)d_in[26];
    float* out = (float*)d_out;

    float *p_h,*p_t,*p_t2b,*p_stats,*p_mean,*p_rstd,*p_disU;
    float *p_epro,*p_t2,*p_natt,*p_eperm,*p_bias2,*p_cat,*p_hd;
    float2* p_deg01;
    int *p_cnt,*p_incl,*p_bsum,*p_rowptr,*p_cursor,*p_csrc,*p_pos;
    cudaGetSymbolAddress((void**)&p_h, g_h);
    cudaGetSymbolAddress((void**)&p_t, g_t);
    cudaGetSymbolAddress((void**)&p_t2b, g_t2b);
    cudaGetSymbolAddress((void**)&p_stats, g_stats);
    cudaGetSymbolAddress((void**)&p_mean, g_mean);
    cudaGetSymbolAddress((void**)&p_rstd, g_rstd);
    cudaGetSymbolAddress((void**)&p_disU, g_disU);
    cudaGetSymbolAddress((void**)&p_deg01, g_deg01);
    cudaGetSymbolAddress((void**)&p_epro, g_epro);
    cudaGetSymbolAddress((void**)&p_t2, g_t2);
    cudaGetSymbolAddress((void**)&p_natt, g_natt);
    cudaGetSymbolAddress((void**)&p_eperm, g_eperm);
    cudaGetSymbolAddress((void**)&p_bias2, g_bias2);
    cudaGetSymbolAddress((void**)&p_cat, g_cat);
    cudaGetSymbolAddress((void**)&p_hd, g_hd);
    cudaGetSymbolAddress((void**)&p_cnt, g_cnt);
    cudaGetSymbolAddress((void**)&p_incl, g_incl);
    cudaGetSymbolAddress((void**)&p_bsum, g_bsum);
    cudaGetSymbolAddress((void**)&p_rowptr, g_rowptr);
    cudaGetSymbolAddress((void**)&p_cursor, g_cursor);
    cudaGetSymbolAddress((void**)&p_csrc, g_csrc);
    cudaGetSymbolAddress((void**)&p_pos, g_pos);

    cudaFuncSetAttribute(gemm128, cudaFuncAttributeMaxDynamicSharedMemorySize, GEMM_SMEM);
    cudaFuncSetAttribute(gemm256, cudaFuncAttributeMaxDynamicSharedMemorySize, GEMM_SMEM);

    const int N = Nn, E = Ee, G = Gg;
    const int NB = (N + 63) / 64;
    const int NT = (N + 255) / 256;
    const int ET = (E + 255) / 256;
    const int GB = 1024;
    const int NSCAN = (N + 1023) / 1024;

    // side stream + events for graph-internal parallelism (fork/join on capture)
    cudaStream_t sA;
    cudaStreamCreateWithFlags(&sA, cudaStreamNonBlocking);
    cudaEvent_t evF1, evJ1, evF2, evJ2;
    cudaEventCreateWithFlags(&evF1, cudaEventDisableTiming);
    cudaEventCreateWithFlags(&evJ1, cudaEventDisableTiming);
    cudaEventCreateWithFlags(&evF2, cudaEventDisableTiming);
    cudaEventCreateWithFlags(&evJ2, cudaEventDisableTiming);

    // ==== FORK 1: CSR build on sA, concurrent with stats+gemm0 on main ====
    cudaEventRecord(evF1, 0);
    cudaStreamWaitEvent(sA, evF1, 0);
    init_kernel<<<NT,256,0,sA>>>(p_disU, p_deg01, p_cnt, N);
    deg_hist<<<ET,256,0,sA>>>(esrc, edst, p_disU, p_cnt, E);
    scan_block<<<NSCAN,1024,0,sA>>>(p_cnt, p_incl, p_bsum, N);
    scan_tops<<<1,32,0,sA>>>(p_bsum, NSCAN);
    make_rowptr<<<NT,256,0,sA>>>(p_cnt, p_incl, p_bsum, p_rowptr, p_cursor, p_disU, N, E);
    fill_csr<<<ET,256,0,sA>>>(esrc, edst, p_cursor, p_csrc, p_pos, E);
    cudaEventRecord(evJ1, sA);

    // main chain: h = relu(BN(x) @ W_feat), stats fused; layer-0 GEMM
    colstats<<<512,256>>>(x, N, p_stats);
    finalize_stats<<<1,256>>>(p_stats, 128, 1.f/N, p_mean, p_rstd);
    gemm128<<<NB,256,GEMM_SMEM>>>(x, p_mean, p_rstd, W_feat, p_h, p_stats, N, 1);
    finalize_stats<<<1,256>>>(p_stats, 128, 1.f/N, p_mean, p_rstd);
    gemm128<<<NB,256,GEMM_SMEM>>>(p_h, p_mean, p_rstd, conv_Ws, p_t, nullptr, N, 0);

    // JOIN 1 (gather needs CSR + disU)
    cudaStreamWaitEvent(0, evJ1, 0);

    // ---- GCN layers ----
    gather128<<<GB,256>>>(p_t, p_rowptr, p_csrc, p_disU, conv_bs, p_h, p_stats,
                          nullptr, nullptr, nullptr, nullptr, N, 1);
    finalize_stats<<<1,256>>>(p_stats, 128, 1.f/N, p_mean, p_rstd);
    for (int l = 1; l < 3; l++) {
        gemm128<<<NB,256,GEMM_SMEM>>>(p_h, p_mean, p_rstd,
                                      conv_Ws + l*128*128, p_t, nullptr, N, 0);
        if (l < 2) {
            gather128<<<GB,256>>>(p_t, p_rowptr, p_csrc, p_disU,
                                  conv_bs + l*128, p_h, p_stats,
                                  nullptr, nullptr, nullptr, nullptr, N, 1);
            finalize_stats<<<1,256>>>(p_stats, 128, 1.f/N, p_mean, p_rstd);
        } else {
            gather128<<<GB,256>>>(p_t, p_rowptr, p_csrc, p_disU,
                                  conv_bs + l*128, p_h, nullptr,
                                  eW, naW, p_epro, p_t2, N, 1);
        }
    }

    // ==== FORK 2: edge attention on sA, concurrent with natt+gemm256 chain ====
    cudaEventRecord(evF2, 0);
    cudaStreamWaitEvent(sA, evF2, 0);
    edge_att_kernel<<<ET,256,0,sA>>>(esrc, edst, p_pos, p_epro, eb, p_eperm, p_deg01, E);
    rsqrt_arr<<<(2*N+255)/256,256,0,sA>>>((float*)p_deg01, 2*N);
    cudaMemsetAsync(p_cat, 0, Gg*256*sizeof(float), sA);
    cudaEventRecord(evJ2, sA);

    // main: node attention + XC/XO stats + merged GEMM
    natt_gather<<<NT,256>>>(p_t2, p_rowptr, p_csrc, p_disU, nab, p_natt, N);
    colstats2<<<512,256>>>(p_h, p_natt, N, p_stats);
    finalize2<<<1,256>>>(p_stats, 1.f/N, p_mean, p_rstd);
    bias_kernel<<<2,128>>>(p_mean, p_rstd, xcW, xoW, p_bias2);
    gemm256<<<NB,256,GEMM_SMEM>>>(p_h, p_natt, p_rstd, xcW, xoW, p_bias2,
                                  p_t, p_t2b, N);

    // JOIN 2 (gather2 needs eperm + deg01 + zeroed cat)
    cudaStreamWaitEvent(0, evJ2, 0);
    gather2<<<GB,256>>>(p_t, p_t2b, p_rowptr, p_csrc, p_deg01, p_eperm,
                        xcb, xob, batch, p_cat, N);

    // ---- heads ----
    head_stats<<<256,128>>>(p_cat, 256, G, p_mean, p_rstd);
    dim3 hg1(G, 3);
    head_gemm1<<<hg1,128>>>(p_cat, p_mean, p_rstd, cW1, cb1, oW1, ob1,
                            coW1, cob1, p_hd);
    head_stats3<<<384,128>>>(p_hd, G, p_mean, p_rstd);
    dim3 hg2(G, 3);
    head_gemm2_lsm<<<hg2,128>>>(p_hd, p_mean, p_rstd, cW2, cb2, oW2, ob2,
                                coW2, cob2, out);

    cudaEventDestroy(evF1);
    cudaEventDestroy(evJ1);
    cudaEventDestroy(evF2);
    cudaEventDestroy(evJ2);
    cudaStreamDestroy(sA);
}